// round 11
// baseline (speedup 1.0000x reference)
#include <cuda_runtime.h>
#include <cuda_fp16.h>
#include <cuda_bf16.h>
#include <stdint.h>

// Problem constants
#define AN   32
#define OBS  128
#define EDIM 64
#define DDIM 64
#define HHEADS 4
#define RDIM 256
#define NACT 16
#define ZDIM 192
#define MAXROWS (4096*32)

// Scratch buffers
__device__ float g_buf64[MAXROWS * 64];    // XE -> ATT (per-batch CTA-exclusive swap)
__device__ float g_bufP [MAXROWS * RDIM];  // P = XE @ Qfold
__device__ float g_Qfold[256 * 64];
__device__ float g_Ufold[8 * 64];
__device__ __align__(16) __half g_xrh  [MAXROWS * RDIM];
__device__ __align__(16) __half g_hinh [MAXROWS * RDIM];
__device__ __align__(16) __half g_Wih16[3 * RDIM * RDIM];
__device__ __align__(16) __half g_Whh16[3 * RDIM * RDIM];

__device__ __forceinline__ float sigf(float x) { return 1.0f / (1.0f + __expf(-x)); }

__device__ __forceinline__ uint32_t f2tf(float x) {
    uint32_t r;
    asm("cvt.rna.tf32.f32 %0, %1;" : "=r"(r) : "f"(x));
    return r;
}

#define MMA_TF32(d, a, b)                                                     \
    asm volatile(                                                             \
        "mma.sync.aligned.m16n8k8.row.col.f32.tf32.tf32.f32 "                 \
        "{%0,%1,%2,%3},{%4,%5,%6,%7},{%8,%9},{%0,%1,%2,%3};"                  \
        : "+f"(d[0]), "+f"(d[1]), "+f"(d[2]), "+f"(d[3])                      \
        : "r"(a[0]), "r"(a[1]), "r"(a[2]), "r"(a[3]), "r"(b[0]), "r"(b[1]))

#define MMA_F16(d, a, b)                                                      \
    asm volatile(                                                             \
        "mma.sync.aligned.m16n8k16.row.col.f32.f16.f16.f32 "                  \
        "{%0,%1,%2,%3},{%4,%5,%6,%7},{%8,%9},{%0,%1,%2,%3};"                  \
        : "+f"(d[0]), "+f"(d[1]), "+f"(d[2]), "+f"(d[3])                      \
        : "r"(a[0]), "r"(a[1]), "r"(a[2]), "r"(a[3]), "r"(b[0]), "r"(b[1]))

#define LDSM_X4(r, addr)                                                      \
    asm volatile(                                                             \
        "ldmatrix.sync.aligned.m8n8.x4.shared.b16 {%0,%1,%2,%3}, [%4];"       \
        : "=r"((r)[0]), "=r"((r)[1]), "=r"((r)[2]), "=r"((r)[3])              \
        : "r"(addr))

__device__ __forceinline__ void cpa16(uint32_t dst, const void* src) {
    asm volatile("cp.async.cg.shared.global [%0], [%1], 16;"
                 :: "r"(dst), "l"(src));
}
#define CPA_COMMIT()  asm volatile("cp.async.commit_group;" ::: "memory")
#define CPA_WAIT(N)   asm volatile("cp.async.wait_group %0;" :: "n"(N) : "memory")

// ---------------------------------------------------------------------------
// k0: GAT weight folding + GRU weight fp16 conversion
// ---------------------------------------------------------------------------
__global__ void k0_prep(const float* __restrict__ Wh, const float* __restrict__ Wo,
                        const float* __restrict__ asrc, const float* __restrict__ adst,
                        const float* __restrict__ Wih, const float* __restrict__ Whh,
                        float* __restrict__ Qfold, float* __restrict__ Ufold,
                        __half* __restrict__ Wih16, __half* __restrict__ Whh16)
{
    int tid = blockIdx.x * blockDim.x + threadIdx.x;
    int stride = gridDim.x * blockDim.x;
    // Qfold[n=hd*64+e][e'] = sum_d Wh[hd][e'][d] * Wo[hd*64+d][e]
    for (int i = tid; i < 256 * 64; i += stride) {
        int n = i >> 6, ep = i & 63;
        int hd = n >> 6, e = n & 63;
        float s = 0.f;
        #pragma unroll 8
        for (int d = 0; d < 64; ++d)
            s = fmaf(Wh[(hd * 64 + ep) * 64 + d], Wo[(hd * 64 + d) * 64 + e], s);
        Qfold[i] = s;
    }
    // Ufold[r][e']: r<4 -> src head r; r>=4 -> dst head r-4
    for (int i = tid; i < 8 * 64; i += stride) {
        int r = i >> 6, ep = i & 63;
        int hd = r & 3;
        const float* av = (r < 4) ? (asrc + hd * 64) : (adst + hd * 64);
        float s = 0.f;
        #pragma unroll 8
        for (int d = 0; d < 64; ++d)
            s = fmaf(Wh[(hd * 64 + ep) * 64 + d], av[d], s);
        Ufold[i] = s;
    }
    for (int i = tid; i < 3 * 256 * 256; i += stride) {
        Wih16[i] = __float2half(Wih[i]);
        Whh16[i] = __float2half(Whh[i]);
    }
}

// ---------------------------------------------------------------------------
// kH: fp32 -> fp16 conversion (hidden state)
// ---------------------------------------------------------------------------
__global__ void kH_f2h(const float* __restrict__ in, __half2* __restrict__ out, int n4)
{
    int i = blockIdx.x * blockDim.x + threadIdx.x;
    int stride = gridDim.x * blockDim.x;
    for (; i < n4; i += stride) {
        float4 v = ((const float4*)in)[i];
        out[2 * i]     = __floats2half2_rn(v.x, v.y);
        out[2 * i + 1] = __floats2half2_rn(v.z, v.w);
    }
}

// ---------------------------------------------------------------------------
// Generic tf32 GEMM (proven R4). OUTH=1: fp16 output.
// ---------------------------------------------------------------------------
#define GEMM_SMEM ((2*16*136 + 2*16*72) * 4)

template<int K1, int K2, int EPI, int OUTH>
__global__ void __launch_bounds__(256) gemm_tn(
    const float* __restrict__ A1, const float* __restrict__ A2,
    const float* __restrict__ W,  const float* __restrict__ bias,
    void* __restrict__ Cout)
{
    constexpr int KT = K1 + K2;
    constexpr int NS = KT / 16;
    extern __shared__ uint32_t sg[];
    uint32_t* As = sg;
    uint32_t* Bs = sg + 2 * 16 * 136;

    const int tid  = threadIdx.x;
    const int lane = tid & 31;
    const int warp = tid >> 5;
    const int wm = (warp & 3) * 32;
    const int wn = (warp >> 2) * 32;
    const int g  = lane >> 2;
    const int tg = lane & 3;
    const size_t r0 = (size_t)blockIdx.y * 128;
    const int n0 = blockIdx.x * 64;
    const int ldc = gridDim.x * 64;

    const int m0i = tid >> 2;
    const int kq  = (tid & 3) * 4;

    float4 ra[2], rbv;

    float acc[2][4][4];
    #pragma unroll
    for (int mt = 0; mt < 2; ++mt)
        #pragma unroll
        for (int nt = 0; nt < 4; ++nt)
            #pragma unroll
            for (int e = 0; e < 4; ++e) acc[mt][nt][e] = 0.f;

    auto ldg_stage = [&](int s) {
        const int kb = s * 16;
        #pragma unroll
        for (int i = 0; i < 2; ++i) {
            int m = m0i + i * 64;
            if (K2 == 0 || kb < K1)
                ra[i] = *(const float4*)(A1 + (r0 + m) * K1 + kb + kq);
            else
                ra[i] = *(const float4*)(A2 + (r0 + m) * K2 + (kb - K1) + kq);
        }
        rbv = *(const float4*)(W + (size_t)(n0 + m0i) * KT + kb + kq);
    };

    auto sts_stage = [&](int buf) {
        uint32_t* Ab = As + buf * (16 * 136);
        uint32_t* Bb = Bs + buf * (16 * 72);
        #pragma unroll
        for (int i = 0; i < 2; ++i) {
            int m = m0i + i * 64;
            float va[4] = {ra[i].x, ra[i].y, ra[i].z, ra[i].w};
            #pragma unroll
            for (int j = 0; j < 4; ++j) {
                int k = kq + j;
                int sw = ((k >> 2) & 3) << 3;
                Ab[k * 136 + (m ^ sw)] = f2tf(va[j]);
            }
        }
        float vb[4] = {rbv.x, rbv.y, rbv.z, rbv.w};
        #pragma unroll
        for (int j = 0; j < 4; ++j) {
            int k = kq + j;
            int sw = ((k >> 2) & 3) << 3;
            Bb[k * 72 + (m0i ^ sw)] = f2tf(vb[j]);
        }
    };

    auto compute_stage = [&](int buf) {
        const uint32_t* Ab = As + buf * (16 * 136);
        const uint32_t* Bb = Bs + buf * (16 * 72);
        #pragma unroll
        for (int k8 = 0; k8 < 2; ++k8) {
            const int kk = k8 * 8;
            const int s0 = ((2 * k8) & 3) << 3;
            const int s1 = ((2 * k8 + 1) & 3) << 3;
            uint32_t a[2][4];
            #pragma unroll
            for (int mt = 0; mt < 2; ++mt) {
                int m0 = wm + mt * 16;
                a[mt][0] = Ab[(kk + tg) * 136 + ((m0 + g) ^ s0)];
                a[mt][1] = Ab[(kk + tg) * 136 + ((m0 + g + 8) ^ s0)];
                a[mt][2] = Ab[(kk + tg + 4) * 136 + ((m0 + g) ^ s1)];
                a[mt][3] = Ab[(kk + tg + 4) * 136 + ((m0 + g + 8) ^ s1)];
            }
            uint32_t bf[4][2];
            #pragma unroll
            for (int nt = 0; nt < 4; ++nt) {
                int q0 = wn + nt * 8 + g;
                bf[nt][0] = Bb[(kk + tg) * 72 + (q0 ^ s0)];
                bf[nt][1] = Bb[(kk + tg + 4) * 72 + (q0 ^ s1)];
            }
            #pragma unroll
            for (int mt = 0; mt < 2; ++mt)
                #pragma unroll
                for (int nt = 0; nt < 4; ++nt)
                    MMA_TF32(acc[mt][nt], a[mt], bf[nt]);
        }
    };

    ldg_stage(0);
    sts_stage(0);
    __syncthreads();
    int buf = 0;
    #pragma unroll 1
    for (int s = 0; s < NS; ++s) {
        if (s < NS - 1) ldg_stage(s + 1);
        compute_stage(buf);
        if (s < NS - 1) {
            sts_stage(buf ^ 1);
            __syncthreads();
            buf ^= 1;
        }
    }

    #pragma unroll
    for (int mt = 0; mt < 2; ++mt) {
        #pragma unroll
        for (int nt = 0; nt < 4; ++nt) {
            size_t r = r0 + wm + mt * 16 + g;
            int    c = n0 + wn + nt * 8 + tg * 2;
            float v0 = acc[mt][nt][0], v1 = acc[mt][nt][1];
            float v2 = acc[mt][nt][2], v3 = acc[mt][nt][3];
            if (EPI >= 1) {
                float b0 = bias[c], b1 = bias[c + 1];
                v0 += b0; v1 += b1; v2 += b0; v3 += b1;
            }
            if (EPI == 2) {
                v0 = fmaxf(v0, 0.f); v1 = fmaxf(v1, 0.f);
                v2 = fmaxf(v2, 0.f); v3 = fmaxf(v3, 0.f);
            }
            if (OUTH) {
                __half* Ch = (__half*)Cout;
                *(__half2*)(Ch + r * ldc + c)       = __floats2half2_rn(v0, v1);
                *(__half2*)(Ch + (r + 8) * ldc + c) = __floats2half2_rn(v2, v3);
            } else {
                float* C = (float*)Cout;
                *(float2*)(C + r * ldc + c)       = make_float2(v0, v1);
                *(float2*)(C + (r + 8) * ldc + c) = make_float2(v2, v3);
            }
        }
    }
}

// ---------------------------------------------------------------------------
// kB2: per-batch masked attention on folded P.
//  ATT[a,c] = sum_hd alpha[hd,a,:] @ P[:, hd*64+c] + bo[c]
//  (bo added here is exact: softmax rows sum to 1.)
//  XE is fully staged to smem before ATT overwrites the same buffer region.
// ---------------------------------------------------------------------------
#define KB_PS    0
#define KB_ALPHA 8224
#define KB_XES   (KB_ALPHA + 4224)       // 12448
#define KB_UF    (KB_XES + 2080)         // 14528
#define KB_SSRC  (KB_UF + 512)           // 15040
#define KB_SDST  (KB_SSRC + 128)         // 15168
#define KB_MSK   (KB_SDST + 128)         // 15296 (int, 1056)
#define KB2_SMEM ((KB_MSK + 1056) * 4)   // 65408 B

__global__ void __launch_bounds__(128) kB_attn2(
    const float* __restrict__ P, const float* __restrict__ XE,
    const int* __restrict__ mask, const float* __restrict__ Ufold,
    const float* __restrict__ bo, float* __restrict__ att)
{
    extern __shared__ float smf[];
    float* Ps    = smf + KB_PS;      // pitch 257
    float* alpha = smf + KB_ALPHA;   // [4][32][33]
    float* XEs   = smf + KB_XES;     // pitch 65
    float* Uf    = smf + KB_UF;      // [8][64]
    float* ssrc  = smf + KB_SSRC;
    float* sdst  = smf + KB_SDST;
    int*   msk   = (int*)(smf + KB_MSK); // pitch 33

    const int tid = threadIdx.x;
    const int b   = blockIdx.x;

    const float* Pb = P + (size_t)b * (32 * 256);
    for (int i = tid; i < 32 * 256; i += 128) {
        int a = i >> 8, c = i & 255;
        Ps[a * 257 + c] = Pb[i];
    }
    const float* XEb = XE + (size_t)b * (32 * 64);
    for (int i = tid; i < 32 * 64; i += 128) {
        int a = i >> 6, e = i & 63;
        XEs[a * 65 + e] = XEb[i];
    }
    for (int i = tid; i < 512; i += 128) Uf[i] = Ufold[i];
    for (int i = tid; i < 32 * 32; i += 128) {
        int r = i >> 5, c = i & 31;
        msk[r * 33 + c] = mask[(size_t)b * (32 * 32) + i];
    }
    __syncthreads();

    // scores: thread = (hd, a)
    {
        int hd = tid >> 5, a = tid & 31;
        const float* xr_ = XEs + a * 65;
        const float* us = Uf + hd * 64;
        const float* ud = Uf + 256 + hd * 64;
        float vs = 0.f, vd = 0.f;
        #pragma unroll
        for (int e = 0; e < 64; ++e) {
            float x = xr_[e];
            vs = fmaf(x, us[e], vs);
            vd = fmaf(x, ud[e], vd);
        }
        ssrc[hd * 32 + a] = vs;
        sdst[hd * 32 + a] = vd;
    }
    __syncthreads();

    // masked softmax: thread = (hd, i)
    {
        int hd = tid >> 5, i = tid & 31;
        float si = ssrc[hd * 32 + i];
        float v[32];
        float m = -3.4e38f;
        #pragma unroll
        for (int j = 0; j < 32; ++j) {
            float e_ = si + sdst[hd * 32 + j];
            float l  = e_ > 0.f ? e_ : 0.2f * e_;
            if (msk[i * 33 + j] <= 0) l = -1e9f;
            v[j] = l; m = fmaxf(m, l);
        }
        float s = 0.f;
        #pragma unroll
        for (int j = 0; j < 32; ++j) { v[j] = __expf(v[j] - m); s += v[j]; }
        float inv = 1.f / s;
        #pragma unroll
        for (int j = 0; j < 32; ++j) alpha[(hd * 32 + i) * 33 + j] = v[j] * inv;
    }
    __syncthreads();

    // ATT: thread owns (c = tid&63, 16 rows of half rh = tid>>6)
    {
        const int c  = tid & 63;
        const int rh = tid >> 6;
        const float bc = bo[c];
        float accv[16];
        #pragma unroll
        for (int a = 0; a < 16; ++a) accv[a] = bc;
        #pragma unroll
        for (int hd = 0; hd < 4; ++hd) {
            float v[32];
            #pragma unroll
            for (int j = 0; j < 32; ++j) v[j] = Ps[j * 257 + hd * 64 + c];
            #pragma unroll
            for (int a16 = 0; a16 < 16; ++a16) {
                const float* al = alpha + (hd * 32 + rh * 16 + a16) * 33;
                float s = accv[a16];
                #pragma unroll
                for (int j = 0; j < 32; ++j) s = fmaf(al[j], v[j], s);
                accv[a16] = s;
            }
        }
        float* attb = att + (size_t)b * (32 * 64);
        #pragma unroll
        for (int a16 = 0; a16 < 16; ++a16)
            attb[(rh * 16 + a16) * 64 + c] = accv[a16];
    }
}

// ---------------------------------------------------------------------------
// k2: GRU via fp16 MMA (m16n8k16) — unchanged proven R9 kernel
// ---------------------------------------------------------------------------
#define K2H_STAGEB 17920
#define K2H_SMEM   (3 * K2H_STAGEB)

__global__ void __launch_bounds__(256, 2) k2_gru_f16(
    const __half* __restrict__ xrh,  const __half* __restrict__ hinh,
    const float*  __restrict__ hin,
    const __half* __restrict__ Wih,  const __half* __restrict__ Whh,
    const float*  __restrict__ bih,  const float*  __restrict__ bhh,
    float* __restrict__ hh_out)
{
    extern __shared__ __half smh[];
    const uint32_t sbase = (uint32_t)__cvta_generic_to_shared(smh);

    const int tid  = threadIdx.x;
    const int lane = tid & 31;
    const int warp = tid >> 5;
    const int wm  = (warp & 3) * 32;
    const int wn  = (warp >> 2) * 48;
    const int g   = lane >> 2;
    const int tg  = lane & 3;
    const size_t r0 = (size_t)blockIdx.y * 128;
    const int c0 = blockIdx.x * 32;

    const int mA = tid >> 2;
    const int jA = tid & 3;
    const size_t aoff0 = (r0 + mA) * 256 + jA * 8;
    const size_t aoff1 = (r0 + mA + 64) * 256 + jA * 8;
    const uint32_t adst0 = (uint32_t)(mA * 80 + jA * 16);
    const uint32_t adst1 = (uint32_t)((mA + 64) * 80 + jA * 16);
    auto wrow_of = [&](int n) {
        int grp = n >> 4, cl = n & 15;
        return (grp % 3) * 256 + c0 + (grp / 3) * 16 + cl;
    };
    const int nB0 = tid >> 2;
    const int jB = tid & 3;
    const size_t boff0 = (size_t)wrow_of(nB0) * 256 + jB * 8;
    const size_t boff1 = (size_t)wrow_of(nB0 + 64) * 256 + jB * 8;
    const uint32_t bdst0 = (uint32_t)(10240 + nB0 * 80 + jB * 16);
    const uint32_t bdst1 = (uint32_t)(10240 + (nB0 + 64) * 80 + jB * 16);

    auto issue = [&](int s) {
        const int buf = s % 3;
        const int kloc = (s & 7) * 32;
        const __half* Asrc = (s < 8) ? xrh : hinh;
        const __half* Wsrc = (s < 8) ? Wih : Whh;
        const uint32_t sb = sbase + (uint32_t)(buf * K2H_STAGEB);
        cpa16(sb + adst0, Asrc + aoff0 + kloc);
        cpa16(sb + adst1, Asrc + aoff1 + kloc);
        cpa16(sb + bdst0, Wsrc + boff0 + kloc);
        if (tid < 128) cpa16(sb + bdst1, Wsrc + boff1 + kloc);
        CPA_COMMIT();
    };

    const int l7 = lane & 7;
    const int aRow = ((lane >> 3) & 1) * 8 + l7;
    const int aKb  = (lane >> 4) * 16;
    const uint32_t aAddr = sbase + (uint32_t)((wm + aRow) * 80 + aKb);
    const int bRow = ((lane >> 4) & 1) * 8 + l7;
    const int bKb  = ((lane >> 3) & 1) * 16;
    const uint32_t bAddr = sbase + (uint32_t)(10240 + (wn + bRow) * 80 + bKb);

    float acc [2][4][4];
    float accd[2][2][2][4];
    #pragma unroll
    for (int mt = 0; mt < 2; ++mt) {
        #pragma unroll
        for (int nt = 0; nt < 4; ++nt)
            #pragma unroll
            for (int e = 0; e < 4; ++e) acc[mt][nt][e] = 0.f;
        #pragma unroll
        for (int p = 0; p < 2; ++p)
            #pragma unroll
            for (int j = 0; j < 2; ++j)
                #pragma unroll
                for (int e = 0; e < 4; ++e) accd[p][mt][j][e] = 0.f;
    }

    auto compute = [&](int buf, int ph) {
        const uint32_t bufoff = (uint32_t)(buf * K2H_STAGEB);
        #pragma unroll
        for (int ks = 0; ks < 2; ++ks) {
            const uint32_t ko = bufoff + ks * 32;
            uint32_t a[2][4];
            LDSM_X4(a[0], aAddr + ko);
            LDSM_X4(a[1], aAddr + ko + 16 * 80);
            uint32_t bf[6][2];
            #pragma unroll
            for (int p = 0; p < 3; ++p) {
                uint32_t t[4];
                LDSM_X4(t, bAddr + ko + p * 16 * 80);
                bf[2 * p][0]     = t[0];
                bf[2 * p][1]     = t[1];
                bf[2 * p + 1][0] = t[2];
                bf[2 * p + 1][1] = t[3];
            }
            #pragma unroll
            for (int mt = 0; mt < 2; ++mt) {
                #pragma unroll
                for (int nt = 0; nt < 4; ++nt)
                    MMA_F16(acc[mt][nt], a[mt], bf[nt]);
                #pragma unroll
                for (int j = 0; j < 2; ++j) {
                    if (ph == 0) { MMA_F16(accd[0][mt][j], a[mt], bf[4 + j]); }
                    else         { MMA_F16(accd[1][mt][j], a[mt], bf[4 + j]); }
                }
            }
        }
    };

    issue(0);
    issue(1);
    CPA_WAIT(1);
    __syncthreads();

    int s = 0;
    #pragma unroll 1
    for (; s < 8; ++s) {
        compute(s % 3, 0);
        if (s + 2 < 16) { issue(s + 2); CPA_WAIT(1); }
        else            { CPA_WAIT(0); }
        __syncthreads();
    }
    #pragma unroll 1
    for (; s < 16; ++s) {
        compute(s % 3, 1);
        if (s + 2 < 16) { issue(s + 2); CPA_WAIT(1); }
        else            { CPA_WAIT(0); }
        __syncthreads();
    }

    const int colbase = c0 + (wn ? 16 : 0);
    #pragma unroll
    for (int mt = 0; mt < 2; ++mt) {
        const size_t rA = r0 + wm + mt * 16 + g;
        const size_t rB = rA + 8;
        #pragma unroll
        for (int j = 0; j < 2; ++j) {
            const int c = colbase + j * 8 + tg * 2;
            const float br0  = bih[c]       + bhh[c];
            const float br1  = bih[c + 1]   + bhh[c + 1];
            const float bz0  = bih[256 + c] + bhh[256 + c];
            const float bz1  = bih[257 + c] + bhh[257 + c];
            const float bni0 = bih[512 + c],  bni1 = bih[513 + c];
            const float bnh0 = bhh[512 + c],  bnh1 = bhh[513 + c];
            const float2 hpA = *(const float2*)(hin + rA * 256 + c);
            const float2 hpB = *(const float2*)(hin + rB * 256 + c);

            float rg, zg, ng;
            rg = sigf(acc[mt][j][0] + br0);
            zg = sigf(acc[mt][2 + j][0] + bz0);
            ng = tanhf(accd[0][mt][j][0] + bni0 + rg * (accd[1][mt][j][0] + bnh0));
            float o0 = (1.f - zg) * ng + zg * hpA.x;

            rg = sigf(acc[mt][j][1] + br1);
            zg = sigf(acc[mt][2 + j][1] + bz1);
            ng = tanhf(accd[0][mt][j][1] + bni1 + rg * (accd[1][mt][j][1] + bnh1));
            float o1 = (1.f - zg) * ng + zg * hpA.y;

            rg = sigf(acc[mt][j][2] + br0);
            zg = sigf(acc[mt][2 + j][2] + bz0);
            ng = tanhf(accd[0][mt][j][2] + bni0 + rg * (accd[1][mt][j][2] + bnh0));
            float o2 = (1.f - zg) * ng + zg * hpB.x;

            rg = sigf(acc[mt][j][3] + br1);
            zg = sigf(acc[mt][2 + j][3] + bz1);
            ng = tanhf(accd[0][mt][j][3] + bni1 + rg * (accd[1][mt][j][3] + bnh1));
            float o3 = (1.f - zg) * ng + zg * hpB.y;

            *(float2*)(hh_out + rA * 256 + c) = make_float2(o0, o1);
            *(float2*)(hh_out + rB * 256 + c) = make_float2(o2, o3);
        }
    }
}

// ---------------------------------------------------------------------------
// k3: LayerNorm + fc2 (one warp per row) — unchanged
// ---------------------------------------------------------------------------
__global__ void __launch_bounds__(256) k3_ln_fc2(
    const float* __restrict__ hh, const float* __restrict__ lng,
    const float* __restrict__ lnb, const float* __restrict__ W2,
    const float* __restrict__ b2, float* __restrict__ q, int nrows)
{
    int warp = (blockIdx.x * blockDim.x + threadIdx.x) >> 5;
    int lane = threadIdx.x & 31;
    if (warp >= nrows) return;
    const float* hr = hh + (size_t)warp * RDIM;

    float v[8];
    float s = 0.f;
    #pragma unroll
    for (int i = 0; i < 8; ++i) { v[i] = hr[lane + 32 * i]; s += v[i]; }
    #pragma unroll
    for (int o = 16; o; o >>= 1) s += __shfl_xor_sync(0xffffffffu, s, o);
    float mu = s * (1.f / 256.f);
    float vs = 0.f;
    #pragma unroll
    for (int i = 0; i < 8; ++i) { float d = v[i] - mu; vs += d * d; }
    #pragma unroll
    for (int o = 16; o; o >>= 1) vs += __shfl_xor_sync(0xffffffffu, vs, o);
    float inv = rsqrtf(vs * (1.f / 256.f) + 1e-5f);

    float hn[8];
    #pragma unroll
    for (int i = 0; i < 8; ++i)
        hn[i] = (v[i] - mu) * inv * lng[lane + 32 * i] + lnb[lane + 32 * i];

    #pragma unroll
    for (int j = 0; j < NACT; ++j) {
        float p = 0.f;
        #pragma unroll
        for (int i = 0; i < 8; ++i) p = fmaf(hn[i], W2[j * RDIM + lane + 32 * i], p);
        #pragma unroll
        for (int o = 16; o; o >>= 1) p += __shfl_xor_sync(0xffffffffu, p, o);
        if (lane == j) q[(size_t)warp * NACT + j] = p + b2[j];
    }
}

// ---------------------------------------------------------------------------
extern "C" void kernel_launch(void* const* d_in, const int* in_sizes, int n_in,
                              void* d_out, int out_size)
{
    const float* inputs = (const float*)d_in[0];
    const float* hidden = (const float*)d_in[1];
    const int*   mask   = (const int*)  d_in[2];
    const float* Wfc    = (const float*)d_in[3];
    const float* bfc    = (const float*)d_in[4];
    const float* Wh     = (const float*)d_in[5];
    const float* asrc   = (const float*)d_in[6];
    const float* adst   = (const float*)d_in[7];
    const float* Wo     = (const float*)d_in[8];
    const float* bo     = (const float*)d_in[9];
    const float* W1     = (const float*)d_in[10];
    const float* b1     = (const float*)d_in[11];
    const float* Wih    = (const float*)d_in[12];
    const float* Whh    = (const float*)d_in[13];
    const float* bih    = (const float*)d_in[14];
    const float* bhh    = (const float*)d_in[15];
    const float* lng    = (const float*)d_in[16];
    const float* lnb    = (const float*)d_in[17];
    const float* W2     = (const float*)d_in[18];
    const float* b2     = (const float*)d_in[19];

    const int B = in_sizes[0] / (AN * OBS);       // 4096
    const int nrows = B * AN;                     // 131072
    const int mblk = nrows / 128;                 // 1024

    float* q_out  = (float*)d_out;
    float* hh_out = (float*)d_out + (size_t)nrows * NACT;

    float *xe, *bp, *qfold, *ufold;
    __half *xrh, *hinh, *wih16, *whh16;
    cudaGetSymbolAddress((void**)&xe,    g_buf64);
    cudaGetSymbolAddress((void**)&bp,    g_bufP);
    cudaGetSymbolAddress((void**)&qfold, g_Qfold);
    cudaGetSymbolAddress((void**)&ufold, g_Ufold);
    cudaGetSymbolAddress((void**)&xrh,   g_xrh);
    cudaGetSymbolAddress((void**)&hinh,  g_hinh);
    cudaGetSymbolAddress((void**)&wih16, g_Wih16);
    cudaGetSymbolAddress((void**)&whh16, g_Whh16);

    cudaFuncSetAttribute(kB_attn2,   cudaFuncAttributeMaxDynamicSharedMemorySize, KB2_SMEM);
    cudaFuncSetAttribute(k2_gru_f16, cudaFuncAttributeMaxDynamicSharedMemorySize, K2H_SMEM);

    // weight folding + fp16 weight conversion
    k0_prep<<<64, 256>>>(Wh, Wo, asrc, adst, Wih, Whh, qfold, ufold, wih16, whh16);
    // hidden -> fp16 copy
    kH_f2h<<<4096, 256>>>(hidden, (__half2*)hinh, nrows * RDIM / 4);

    // G1: XE = inputs @ Wfc^T + bfc            [M,64]
    gemm_tn<128, 0, 1, 0><<<dim3(1, mblk), 256, GEMM_SMEM>>>(inputs, nullptr, Wfc, bfc, xe);
    // G2: P = XE @ Qfold^T                     [M,256] (folded Wh x Wo)
    gemm_tn<64, 0, 0, 0><<<dim3(4, mblk), 256, GEMM_SMEM>>>(xe, nullptr, qfold, nullptr, bp);
    // attention on folded P -> ATT (+bo), overwrites XE buffer (CTA-exclusive)
    kB_attn2<<<B, 128, KB2_SMEM>>>(bp, xe, mask, ufold, bo, xe);
    // G4: XR = relu([inputs | ATT] @ W1^T + b1) -> fp16
    gemm_tn<128, 64, 2, 1><<<dim3(4, mblk), 256, GEMM_SMEM>>>(inputs, xe, W1, b1, xrh);
    // GRU (fp16 MMA pipeline, warp-local gates)
    k2_gru_f16<<<dim3(8, mblk), 256, K2H_SMEM>>>(xrh, hinh, hidden, wih16, whh16,
                                                 bih, bhh, hh_out);
    // LN + fc2
    k3_ln_fc2<<<(nrows + 7) / 8, 256>>>(hh_out, lng, lnb, W2, b2, q_out, nrows);
}

// round 12
// speedup vs baseline: 1.0832x; 1.0832x over previous
#include <cuda_runtime.h>
#include <cuda_fp16.h>
#include <cuda_bf16.h>
#include <stdint.h>

// Problem constants
#define AN   32
#define OBS  128
#define EDIM 64
#define DDIM 64
#define HHEADS 4
#define RDIM 256
#define NACT 16
#define ZDIM 192
#define MAXROWS (4096*32)

// Scratch buffers
__device__ float g_buf64[MAXROWS * 64];    // XE -> ATT
__device__ float g_bufH [MAXROWS * RDIM];  // H
__device__ float g_bufG [MAXROWS * RDIM];  // agg
__device__ float g_WhT  [256 * 64];
__device__ float g_WoT  [64 * 256];
__device__ __align__(16) __half g_xrh  [MAXROWS * RDIM];  // XR (fp16, from G4)
__device__ __align__(16) __half g_hinh [MAXROWS * RDIM];  // hidden (fp16 copy)
__device__ __align__(16) __half g_Wih16[3 * RDIM * RDIM];
__device__ __align__(16) __half g_Whh16[3 * RDIM * RDIM];

__device__ __forceinline__ float sigf(float x) { return 1.0f / (1.0f + __expf(-x)); }

__device__ __forceinline__ uint32_t f2tf(float x) {
    uint32_t r;
    asm("cvt.rna.tf32.f32 %0, %1;" : "=r"(r) : "f"(x));
    return r;
}

#define MMA_TF32(d, a, b)                                                     \
    asm volatile(                                                             \
        "mma.sync.aligned.m16n8k8.row.col.f32.tf32.tf32.f32 "                 \
        "{%0,%1,%2,%3},{%4,%5,%6,%7},{%8,%9},{%0,%1,%2,%3};"                  \
        : "+f"(d[0]), "+f"(d[1]), "+f"(d[2]), "+f"(d[3])                      \
        : "r"(a[0]), "r"(a[1]), "r"(a[2]), "r"(a[3]), "r"(b[0]), "r"(b[1]))

#define MMA_F16(d, a, b)                                                      \
    asm volatile(                                                             \
        "mma.sync.aligned.m16n8k16.row.col.f32.f16.f16.f32 "                  \
        "{%0,%1,%2,%3},{%4,%5,%6,%7},{%8,%9},{%0,%1,%2,%3};"                  \
        : "+f"(d[0]), "+f"(d[1]), "+f"(d[2]), "+f"(d[3])                      \
        : "r"(a[0]), "r"(a[1]), "r"(a[2]), "r"(a[3]), "r"(b[0]), "r"(b[1]))

#define LDSM_X4(r, addr)                                                      \
    asm volatile(                                                             \
        "ldmatrix.sync.aligned.m8n8.x4.shared.b16 {%0,%1,%2,%3}, [%4];"       \
        : "=r"((r)[0]), "=r"((r)[1]), "=r"((r)[2]), "=r"((r)[3])              \
        : "r"(addr))

__device__ __forceinline__ void cpa16(uint32_t dst, const void* src) {
    asm volatile("cp.async.cg.shared.global [%0], [%1], 16;"
                 :: "r"(dst), "l"(src));
}
#define CPA_COMMIT()  asm volatile("cp.async.commit_group;" ::: "memory")
#define CPA_WAIT(N)   asm volatile("cp.async.wait_group %0;" :: "n"(N) : "memory")

// ---------------------------------------------------------------------------
// k0: tiny transposes + weight fp16 conversion  (proven R9)
// ---------------------------------------------------------------------------
__global__ void k0_prep(const float* __restrict__ Wh, const float* __restrict__ Wo,
                        const float* __restrict__ Wih, const float* __restrict__ Whh,
                        float* __restrict__ WhT, float* __restrict__ WoT,
                        __half* __restrict__ Wih16, __half* __restrict__ Whh16)
{
    int tid = blockIdx.x * blockDim.x + threadIdx.x;
    int stride = gridDim.x * blockDim.x;
    for (int i = tid; i < 256 * 64; i += stride) {
        int n = i >> 6, e = i & 63;
        int h = n >> 6, d = n & 63;
        WhT[i] = Wh[(h * 64 + e) * 64 + d];
    }
    for (int i = tid; i < 64 * 256; i += stride) {
        int e = i >> 8, k = i & 255;
        WoT[i] = Wo[k * 64 + e];
    }
    for (int i = tid; i < 3 * 256 * 256; i += stride) {
        Wih16[i] = __float2half(Wih[i]);
        Whh16[i] = __float2half(Whh[i]);
    }
}

// ---------------------------------------------------------------------------
// kH: fp32 -> fp16 conversion (hidden state)
// ---------------------------------------------------------------------------
__global__ void kH_f2h(const float* __restrict__ in, __half2* __restrict__ out, int n4)
{
    int i = blockIdx.x * blockDim.x + threadIdx.x;
    int stride = gridDim.x * blockDim.x;
    for (; i < n4; i += stride) {
        float4 v = ((const float4*)in)[i];
        out[2 * i]     = __floats2half2_rn(v.x, v.y);
        out[2 * i + 1] = __floats2half2_rn(v.z, v.w);
    }
}

// ---------------------------------------------------------------------------
// Generic tf32 GEMM (proven R4). OUTH=1: fp16 output.
// ---------------------------------------------------------------------------
#define GEMM_SMEM ((2*16*136 + 2*16*72) * 4)

template<int K1, int K2, int EPI, int OUTH>
__global__ void __launch_bounds__(256) gemm_tn(
    const float* __restrict__ A1, const float* __restrict__ A2,
    const float* __restrict__ W,  const float* __restrict__ bias,
    void* __restrict__ Cout)
{
    constexpr int KT = K1 + K2;
    constexpr int NS = KT / 16;
    extern __shared__ uint32_t sg[];
    uint32_t* As = sg;
    uint32_t* Bs = sg + 2 * 16 * 136;

    const int tid  = threadIdx.x;
    const int lane = tid & 31;
    const int warp = tid >> 5;
    const int wm = (warp & 3) * 32;
    const int wn = (warp >> 2) * 32;
    const int g  = lane >> 2;
    const int tg = lane & 3;
    const size_t r0 = (size_t)blockIdx.y * 128;
    const int n0 = blockIdx.x * 64;
    const int ldc = gridDim.x * 64;

    const int m0i = tid >> 2;
    const int kq  = (tid & 3) * 4;

    float4 ra[2], rbv;

    float acc[2][4][4];
    #pragma unroll
    for (int mt = 0; mt < 2; ++mt)
        #pragma unroll
        for (int nt = 0; nt < 4; ++nt)
            #pragma unroll
            for (int e = 0; e < 4; ++e) acc[mt][nt][e] = 0.f;

    auto ldg_stage = [&](int s) {
        const int kb = s * 16;
        #pragma unroll
        for (int i = 0; i < 2; ++i) {
            int m = m0i + i * 64;
            if (K2 == 0 || kb < K1)
                ra[i] = *(const float4*)(A1 + (r0 + m) * K1 + kb + kq);
            else
                ra[i] = *(const float4*)(A2 + (r0 + m) * K2 + (kb - K1) + kq);
        }
        rbv = *(const float4*)(W + (size_t)(n0 + m0i) * KT + kb + kq);
    };

    auto sts_stage = [&](int buf) {
        uint32_t* Ab = As + buf * (16 * 136);
        uint32_t* Bb = Bs + buf * (16 * 72);
        #pragma unroll
        for (int i = 0; i < 2; ++i) {
            int m = m0i + i * 64;
            float va[4] = {ra[i].x, ra[i].y, ra[i].z, ra[i].w};
            #pragma unroll
            for (int j = 0; j < 4; ++j) {
                int k = kq + j;
                int sw = ((k >> 2) & 3) << 3;
                Ab[k * 136 + (m ^ sw)] = f2tf(va[j]);
            }
        }
        float vb[4] = {rbv.x, rbv.y, rbv.z, rbv.w};
        #pragma unroll
        for (int j = 0; j < 4; ++j) {
            int k = kq + j;
            int sw = ((k >> 2) & 3) << 3;
            Bb[k * 72 + (m0i ^ sw)] = f2tf(vb[j]);
        }
    };

    auto compute_stage = [&](int buf) {
        const uint32_t* Ab = As + buf * (16 * 136);
        const uint32_t* Bb = Bs + buf * (16 * 72);
        #pragma unroll
        for (int k8 = 0; k8 < 2; ++k8) {
            const int kk = k8 * 8;
            const int s0 = ((2 * k8) & 3) << 3;
            const int s1 = ((2 * k8 + 1) & 3) << 3;
            uint32_t a[2][4];
            #pragma unroll
            for (int mt = 0; mt < 2; ++mt) {
                int m0 = wm + mt * 16;
                a[mt][0] = Ab[(kk + tg) * 136 + ((m0 + g) ^ s0)];
                a[mt][1] = Ab[(kk + tg) * 136 + ((m0 + g + 8) ^ s0)];
                a[mt][2] = Ab[(kk + tg + 4) * 136 + ((m0 + g) ^ s1)];
                a[mt][3] = Ab[(kk + tg + 4) * 136 + ((m0 + g + 8) ^ s1)];
            }
            uint32_t bf[4][2];
            #pragma unroll
            for (int nt = 0; nt < 4; ++nt) {
                int q0 = wn + nt * 8 + g;
                bf[nt][0] = Bb[(kk + tg) * 72 + (q0 ^ s0)];
                bf[nt][1] = Bb[(kk + tg + 4) * 72 + (q0 ^ s1)];
            }
            #pragma unroll
            for (int mt = 0; mt < 2; ++mt)
                #pragma unroll
                for (int nt = 0; nt < 4; ++nt)
                    MMA_TF32(acc[mt][nt], a[mt], bf[nt]);
        }
    };

    ldg_stage(0);
    sts_stage(0);
    __syncthreads();
    int buf = 0;
    #pragma unroll 1
    for (int s = 0; s < NS; ++s) {
        if (s < NS - 1) ldg_stage(s + 1);
        compute_stage(buf);
        if (s < NS - 1) {
            sts_stage(buf ^ 1);
            __syncthreads();
            buf ^= 1;
        }
    }

    #pragma unroll
    for (int mt = 0; mt < 2; ++mt) {
        #pragma unroll
        for (int nt = 0; nt < 4; ++nt) {
            size_t r = r0 + wm + mt * 16 + g;
            int    c = n0 + wn + nt * 8 + tg * 2;
            float v0 = acc[mt][nt][0], v1 = acc[mt][nt][1];
            float v2 = acc[mt][nt][2], v3 = acc[mt][nt][3];
            if (EPI >= 1) {
                float b0 = bias[c], b1 = bias[c + 1];
                v0 += b0; v1 += b1; v2 += b0; v3 += b1;
            }
            if (EPI == 2) {
                v0 = fmaxf(v0, 0.f); v1 = fmaxf(v1, 0.f);
                v2 = fmaxf(v2, 0.f); v3 = fmaxf(v3, 0.f);
            }
            if (OUTH) {
                __half* Ch = (__half*)Cout;
                *(__half2*)(Ch + r * ldc + c)       = __floats2half2_rn(v0, v1);
                *(__half2*)(Ch + (r + 8) * ldc + c) = __floats2half2_rn(v2, v3);
            } else {
                float* C = (float*)Cout;
                *(float2*)(C + r * ldc + c)       = make_float2(v0, v1);
                *(float2*)(C + (r + 8) * ldc + c) = make_float2(v2, v3);
            }
        }
    }
}

// ---------------------------------------------------------------------------
// kB: per-batch masked attention — R9 structure, widened to 256 threads.
//  Scores + softmax run on threads 0-127 (layout identical to proven R9).
//  agg phase: each thread owns ONE column c = tid; hd = tid>>6 (warp-uniform),
//  halving per-thread FMA/LDS chains and doubling resident warps.
// ---------------------------------------------------------------------------
#define KB_HS    0
#define KB_ALPHA 8224
#define KB_SSRC  (KB_ALPHA + 4*32*33)    // 12448
#define KB_SDST  (KB_SSRC + 128)
#define KB_SAS   (KB_SDST + 128)
#define KB_SAD   (KB_SAS + 256)
#define KB_MSK   (KB_SAD + 256)          // int region
#define KB_SMEM  ((KB_MSK + 32*33) * 4)  // 57088 B

__global__ void __launch_bounds__(256) kB_attn(
    const float* __restrict__ H, const int* __restrict__ mask,
    const float* __restrict__ asrc, const float* __restrict__ adst,
    float* __restrict__ agg)
{
    extern __shared__ float smf[];
    float* Hs    = smf + KB_HS;      // pitch 257
    float* alpha = smf + KB_ALPHA;   // [4][32][33]
    float* ssrc  = smf + KB_SSRC;
    float* sdst  = smf + KB_SDST;
    float* sas   = smf + KB_SAS;
    float* sad   = smf + KB_SAD;
    int*   msk   = (int*)(smf + KB_MSK); // pitch 33

    const int tid  = threadIdx.x;
    const int lane = tid & 31;
    const int warp = tid >> 5;
    const int b    = blockIdx.x;

    const float* Hb = H + (size_t)b * (32 * 256);
    for (int i = tid; i < 32 * 256; i += 256) {
        int a = i >> 8, c = i & 255;
        Hs[a * 257 + c] = Hb[i];
    }
    for (int i = tid; i < 256; i += 256) { sas[i] = asrc[i]; sad[i] = adst[i]; }
    for (int i = tid; i < 32 * 32; i += 256) {
        int r = i >> 5, c = i & 31;
        msk[r * 33 + c] = mask[(size_t)b * (32 * 32) + i];
    }
    __syncthreads();

    // scores: warps 0-3 (hd = warp), lane = agent row
    if (warp < 4) {
        int hd = warp;
        float vs = 0.f, vd = 0.f;
        const float* hr = Hs + lane * 257 + hd * 64;
        #pragma unroll
        for (int d = 0; d < 64; ++d) {
            float h = hr[d];
            vs = fmaf(h, sas[hd * 64 + d], vs);
            vd = fmaf(h, sad[hd * 64 + d], vd);
        }
        ssrc[hd * 32 + lane] = vs;
        sdst[hd * 32 + lane] = vd;
    }
    __syncthreads();

    // masked softmax: threads 0-127, thread = (hd, i)
    if (tid < 128) {
        int hd = tid >> 5, i = tid & 31;
        float si = ssrc[hd * 32 + i];
        float v[32];
        float m = -3.4e38f;
        #pragma unroll
        for (int j = 0; j < 32; ++j) {
            float e_ = si + sdst[hd * 32 + j];
            float l  = e_ > 0.f ? e_ : 0.2f * e_;
            if (msk[i * 33 + j] <= 0) l = -1e9f;
            v[j] = l; m = fmaxf(m, l);
        }
        float s = 0.f;
        #pragma unroll
        for (int j = 0; j < 32; ++j) { v[j] = __expf(v[j] - m); s += v[j]; }
        float inv = 1.f / s;
        #pragma unroll
        for (int j = 0; j < 32; ++j) alpha[(hd * 32 + i) * 33 + j] = v[j] * inv;
    }
    __syncthreads();

    // agg: thread owns column c = tid (hd = tid>>6 is warp-uniform)
    {
        float v[32];
        #pragma unroll
        for (int j = 0; j < 32; ++j) v[j] = Hs[j * 257 + tid];
        const int hd = tid >> 6;
        float* aggb = agg + (size_t)b * (32 * 256);
        #pragma unroll 4
        for (int a = 0; a < 32; ++a) {
            const float* al = alpha + (hd * 32 + a) * 33;
            float s = 0.f;
            #pragma unroll
            for (int j = 0; j < 32; ++j) s = fmaf(al[j], v[j], s);
            aggb[a * 256 + tid] = s;
        }
    }
}

// ---------------------------------------------------------------------------
// k2: GRU via fp16 MMA (m16n8k16) — unchanged proven R9 kernel
// ---------------------------------------------------------------------------
#define K2H_STAGEB 17920
#define K2H_SMEM   (3 * K2H_STAGEB)

__global__ void __launch_bounds__(256, 2) k2_gru_f16(
    const __half* __restrict__ xrh,  const __half* __restrict__ hinh,
    const float*  __restrict__ hin,
    const __half* __restrict__ Wih,  const __half* __restrict__ Whh,
    const float*  __restrict__ bih,  const float*  __restrict__ bhh,
    float* __restrict__ hh_out)
{
    extern __shared__ __half smh[];
    const uint32_t sbase = (uint32_t)__cvta_generic_to_shared(smh);

    const int tid  = threadIdx.x;
    const int lane = tid & 31;
    const int warp = tid >> 5;
    const int wm  = (warp & 3) * 32;
    const int wn  = (warp >> 2) * 48;
    const int g   = lane >> 2;
    const int tg  = lane & 3;
    const size_t r0 = (size_t)blockIdx.y * 128;
    const int c0 = blockIdx.x * 32;

    const int mA = tid >> 2;
    const int jA = tid & 3;
    const size_t aoff0 = (r0 + mA) * 256 + jA * 8;
    const size_t aoff1 = (r0 + mA + 64) * 256 + jA * 8;
    const uint32_t adst0 = (uint32_t)(mA * 80 + jA * 16);
    const uint32_t adst1 = (uint32_t)((mA + 64) * 80 + jA * 16);
    auto wrow_of = [&](int n) {
        int grp = n >> 4, cl = n & 15;
        return (grp % 3) * 256 + c0 + (grp / 3) * 16 + cl;
    };
    const int nB0 = tid >> 2;
    const int jB = tid & 3;
    const size_t boff0 = (size_t)wrow_of(nB0) * 256 + jB * 8;
    const size_t boff1 = (size_t)wrow_of(nB0 + 64) * 256 + jB * 8;
    const uint32_t bdst0 = (uint32_t)(10240 + nB0 * 80 + jB * 16);
    const uint32_t bdst1 = (uint32_t)(10240 + (nB0 + 64) * 80 + jB * 16);

    auto issue = [&](int s) {
        const int buf = s % 3;
        const int kloc = (s & 7) * 32;
        const __half* Asrc = (s < 8) ? xrh : hinh;
        const __half* Wsrc = (s < 8) ? Wih : Whh;
        const uint32_t sb = sbase + (uint32_t)(buf * K2H_STAGEB);
        cpa16(sb + adst0, Asrc + aoff0 + kloc);
        cpa16(sb + adst1, Asrc + aoff1 + kloc);
        cpa16(sb + bdst0, Wsrc + boff0 + kloc);
        if (tid < 128) cpa16(sb + bdst1, Wsrc + boff1 + kloc);
        CPA_COMMIT();
    };

    const int l7 = lane & 7;
    const int aRow = ((lane >> 3) & 1) * 8 + l7;
    const int aKb  = (lane >> 4) * 16;
    const uint32_t aAddr = sbase + (uint32_t)((wm + aRow) * 80 + aKb);
    const int bRow = ((lane >> 4) & 1) * 8 + l7;
    const int bKb  = ((lane >> 3) & 1) * 16;
    const uint32_t bAddr = sbase + (uint32_t)(10240 + (wn + bRow) * 80 + bKb);

    float acc [2][4][4];
    float accd[2][2][2][4];
    #pragma unroll
    for (int mt = 0; mt < 2; ++mt) {
        #pragma unroll
        for (int nt = 0; nt < 4; ++nt)
            #pragma unroll
            for (int e = 0; e < 4; ++e) acc[mt][nt][e] = 0.f;
        #pragma unroll
        for (int p = 0; p < 2; ++p)
            #pragma unroll
            for (int j = 0; j < 2; ++j)
                #pragma unroll
                for (int e = 0; e < 4; ++e) accd[p][mt][j][e] = 0.f;
    }

    auto compute = [&](int buf, int ph) {
        const uint32_t bufoff = (uint32_t)(buf * K2H_STAGEB);
        #pragma unroll
        for (int ks = 0; ks < 2; ++ks) {
            const uint32_t ko = bufoff + ks * 32;
            uint32_t a[2][4];
            LDSM_X4(a[0], aAddr + ko);
            LDSM_X4(a[1], aAddr + ko + 16 * 80);
            uint32_t bf[6][2];
            #pragma unroll
            for (int p = 0; p < 3; ++p) {
                uint32_t t[4];
                LDSM_X4(t, bAddr + ko + p * 16 * 80);
                bf[2 * p][0]     = t[0];
                bf[2 * p][1]     = t[1];
                bf[2 * p + 1][0] = t[2];
                bf[2 * p + 1][1] = t[3];
            }
            #pragma unroll
            for (int mt = 0; mt < 2; ++mt) {
                #pragma unroll
                for (int nt = 0; nt < 4; ++nt)
                    MMA_F16(acc[mt][nt], a[mt], bf[nt]);
                #pragma unroll
                for (int j = 0; j < 2; ++j) {
                    if (ph == 0) { MMA_F16(accd[0][mt][j], a[mt], bf[4 + j]); }
                    else         { MMA_F16(accd[1][mt][j], a[mt], bf[4 + j]); }
                }
            }
        }
    };

    issue(0);
    issue(1);
    CPA_WAIT(1);
    __syncthreads();

    int s = 0;
    #pragma unroll 1
    for (; s < 8; ++s) {
        compute(s % 3, 0);
        if (s + 2 < 16) { issue(s + 2); CPA_WAIT(1); }
        else            { CPA_WAIT(0); }
        __syncthreads();
    }
    #pragma unroll 1
    for (; s < 16; ++s) {
        compute(s % 3, 1);
        if (s + 2 < 16) { issue(s + 2); CPA_WAIT(1); }
        else            { CPA_WAIT(0); }
        __syncthreads();
    }

    const int colbase = c0 + (wn ? 16 : 0);
    #pragma unroll
    for (int mt = 0; mt < 2; ++mt) {
        const size_t rA = r0 + wm + mt * 16 + g;
        const size_t rB = rA + 8;
        #pragma unroll
        for (int j = 0; j < 2; ++j) {
            const int c = colbase + j * 8 + tg * 2;
            const float br0  = bih[c]       + bhh[c];
            const float br1  = bih[c + 1]   + bhh[c + 1];
            const float bz0  = bih[256 + c] + bhh[256 + c];
            const float bz1  = bih[257 + c] + bhh[257 + c];
            const float bni0 = bih[512 + c],  bni1 = bih[513 + c];
            const float bnh0 = bhh[512 + c],  bnh1 = bhh[513 + c];
            const float2 hpA = *(const float2*)(hin + rA * 256 + c);
            const float2 hpB = *(const float2*)(hin + rB * 256 + c);

            float rg, zg, ng;
            rg = sigf(acc[mt][j][0] + br0);
            zg = sigf(acc[mt][2 + j][0] + bz0);
            ng = tanhf(accd[0][mt][j][0] + bni0 + rg * (accd[1][mt][j][0] + bnh0));
            float o0 = (1.f - zg) * ng + zg * hpA.x;

            rg = sigf(acc[mt][j][1] + br1);
            zg = sigf(acc[mt][2 + j][1] + bz1);
            ng = tanhf(accd[0][mt][j][1] + bni1 + rg * (accd[1][mt][j][1] + bnh1));
            float o1 = (1.f - zg) * ng + zg * hpA.y;

            rg = sigf(acc[mt][j][2] + br0);
            zg = sigf(acc[mt][2 + j][2] + bz0);
            ng = tanhf(accd[0][mt][j][2] + bni0 + rg * (accd[1][mt][j][2] + bnh0));
            float o2 = (1.f - zg) * ng + zg * hpB.x;

            rg = sigf(acc[mt][j][3] + br1);
            zg = sigf(acc[mt][2 + j][3] + bz1);
            ng = tanhf(accd[0][mt][j][3] + bni1 + rg * (accd[1][mt][j][3] + bnh1));
            float o3 = (1.f - zg) * ng + zg * hpB.y;

            *(float2*)(hh_out + rA * 256 + c) = make_float2(o0, o1);
            *(float2*)(hh_out + rB * 256 + c) = make_float2(o2, o3);
        }
    }
}

// ---------------------------------------------------------------------------
// k3: LayerNorm + fc2 (one warp per row) — unchanged
// ---------------------------------------------------------------------------
__global__ void __launch_bounds__(256) k3_ln_fc2(
    const float* __restrict__ hh, const float* __restrict__ lng,
    const float* __restrict__ lnb, const float* __restrict__ W2,
    const float* __restrict__ b2, float* __restrict__ q, int nrows)
{
    int warp = (blockIdx.x * blockDim.x + threadIdx.x) >> 5;
    int lane = threadIdx.x & 31;
    if (warp >= nrows) return;
    const float* hr = hh + (size_t)warp * RDIM;

    float v[8];
    float s = 0.f;
    #pragma unroll
    for (int i = 0; i < 8; ++i) { v[i] = hr[lane + 32 * i]; s += v[i]; }
    #pragma unroll
    for (int o = 16; o; o >>= 1) s += __shfl_xor_sync(0xffffffffu, s, o);
    float mu = s * (1.f / 256.f);
    float vs = 0.f;
    #pragma unroll
    for (int i = 0; i < 8; ++i) { float d = v[i] - mu; vs += d * d; }
    #pragma unroll
    for (int o = 16; o; o >>= 1) vs += __shfl_xor_sync(0xffffffffu, vs, o);
    float inv = rsqrtf(vs * (1.f / 256.f) + 1e-5f);

    float hn[8];
    #pragma unroll
    for (int i = 0; i < 8; ++i)
        hn[i] = (v[i] - mu) * inv * lng[lane + 32 * i] + lnb[lane + 32 * i];

    #pragma unroll
    for (int j = 0; j < NACT; ++j) {
        float p = 0.f;
        #pragma unroll
        for (int i = 0; i < 8; ++i) p = fmaf(hn[i], W2[j * RDIM + lane + 32 * i], p);
        #pragma unroll
        for (int o = 16; o; o >>= 1) p += __shfl_xor_sync(0xffffffffu, p, o);
        if (lane == j) q[(size_t)warp * NACT + j] = p + b2[j];
    }
}

// ---------------------------------------------------------------------------
extern "C" void kernel_launch(void* const* d_in, const int* in_sizes, int n_in,
                              void* d_out, int out_size)
{
    const float* inputs = (const float*)d_in[0];
    const float* hidden = (const float*)d_in[1];
    const int*   mask   = (const int*)  d_in[2];
    const float* Wfc    = (const float*)d_in[3];
    const float* bfc    = (const float*)d_in[4];
    const float* Wh     = (const float*)d_in[5];
    const float* asrc   = (const float*)d_in[6];
    const float* adst   = (const float*)d_in[7];
    const float* Wo     = (const float*)d_in[8];
    const float* bo     = (const float*)d_in[9];
    const float* W1     = (const float*)d_in[10];
    const float* b1     = (const float*)d_in[11];
    const float* Wih    = (const float*)d_in[12];
    const float* Whh    = (const float*)d_in[13];
    const float* bih    = (const float*)d_in[14];
    const float* bhh    = (const float*)d_in[15];
    const float* lng    = (const float*)d_in[16];
    const float* lnb    = (const float*)d_in[17];
    const float* W2     = (const float*)d_in[18];
    const float* b2     = (const float*)d_in[19];

    const int B = in_sizes[0] / (AN * OBS);       // 4096
    const int nrows = B * AN;                     // 131072
    const int mblk = nrows / 128;                 // 1024

    float* q_out  = (float*)d_out;
    float* hh_out = (float*)d_out + (size_t)nrows * NACT;

    float *xe, *bh, *bg, *wht, *wot;
    __half *xrh, *hinh, *wih16, *whh16;
    cudaGetSymbolAddress((void**)&xe,    g_buf64);
    cudaGetSymbolAddress((void**)&bh,    g_bufH);
    cudaGetSymbolAddress((void**)&bg,    g_bufG);
    cudaGetSymbolAddress((void**)&wht,   g_WhT);
    cudaGetSymbolAddress((void**)&wot,   g_WoT);
    cudaGetSymbolAddress((void**)&xrh,   g_xrh);
    cudaGetSymbolAddress((void**)&hinh,  g_hinh);
    cudaGetSymbolAddress((void**)&wih16, g_Wih16);
    cudaGetSymbolAddress((void**)&whh16, g_Whh16);

    cudaFuncSetAttribute(kB_attn,    cudaFuncAttributeMaxDynamicSharedMemorySize, KB_SMEM);
    cudaFuncSetAttribute(k2_gru_f16, cudaFuncAttributeMaxDynamicSharedMemorySize, K2H_SMEM);

    k0_prep<<<64, 256>>>(Wh, Wo, Wih, Whh, wht, wot, wih16, whh16);
    // hidden -> fp16 copy (independent of GAT chain)
    kH_f2h<<<4096, 256>>>(hidden, (__half2*)hinh, nrows * RDIM / 4);

    // G1: XE = inputs @ Wfc^T + bfc          [M,64]
    gemm_tn<128, 0, 1, 0><<<dim3(1, mblk), 256, GEMM_SMEM>>>(inputs, nullptr, Wfc, bfc, xe);
    // G2: H = XE @ WhT^T                     [M,256]
    gemm_tn<64, 0, 0, 0><<<dim3(4, mblk), 256, GEMM_SMEM>>>(xe, nullptr, wht, nullptr, bh);
    // attention: agg = softmax(mask, leaky(s_i+s_j)) @ H   (256-thread CTAs)
    kB_attn<<<B, 256, KB_SMEM>>>(bh, mask, asrc, adst, bg);
    // G3: ATT = agg @ WoT^T + bo             [M,64] (overwrites XE)
    gemm_tn<256, 0, 1, 0><<<dim3(1, mblk), 256, GEMM_SMEM>>>(bg, nullptr, wot, bo, xe);
    // G4: XR = relu([inputs|ATT] @ W1^T+b1)  [M,256] fp16 output
    gemm_tn<128, 64, 2, 1><<<dim3(4, mblk), 256, GEMM_SMEM>>>(inputs, xe, W1, b1, xrh);
    // GRU (fp16 MMA pipeline, warp-local gates)
    k2_gru_f16<<<dim3(8, mblk), 256, K2H_SMEM>>>(xrh, hinh, hidden, wih16, whh16,
                                                 bih, bhh, hh_out);
    // LN + fc2
    k3_ln_fc2<<<(nrows + 7) / 8, 256>>>(hh_out, lng, lnb, W2, b2, q_out, nrows);
}

// round 13
// speedup vs baseline: 1.2546x; 1.1583x over previous
#include <cuda_runtime.h>
#include <cuda_fp16.h>
#include <cuda_bf16.h>
#include <stdint.h>

// Problem constants
#define AN   32
#define OBS  128
#define EDIM 64
#define DDIM 64
#define HHEADS 4
#define RDIM 256
#define NACT 16
#define ZDIM 192
#define MAXROWS (4096*32)

// Scratch buffers
__device__ float g_bufH [MAXROWS * RDIM];  // H (fp32, for attention)
__device__ __align__(16) __half g_inh  [MAXROWS * OBS];   // inputs fp16
__device__ __align__(16) __half g_xeh  [MAXROWS * 64];    // XE fp16
__device__ __align__(16) __half g_aggh [MAXROWS * RDIM];  // agg fp16
__device__ __align__(16) __half g_atth [MAXROWS * 64];    // ATT fp16
__device__ __align__(16) __half g_xrh  [MAXROWS * RDIM];  // XR fp16
__device__ __align__(16) __half g_hinh [MAXROWS * RDIM];  // hidden fp16
__device__ __align__(16) __half g_Wfch [64 * OBS];
__device__ __align__(16) __half g_WhTh [256 * 64];
__device__ __align__(16) __half g_WoTh [64 * 256];
__device__ __align__(16) __half g_W1h  [RDIM * ZDIM];
__device__ __align__(16) __half g_Wih16[3 * RDIM * RDIM];
__device__ __align__(16) __half g_Whh16[3 * RDIM * RDIM];

__device__ __forceinline__ float sigf(float x) { return 1.0f / (1.0f + __expf(-x)); }

#define MMA_F16(d, a, b)                                                      \
    asm volatile(                                                             \
        "mma.sync.aligned.m16n8k16.row.col.f32.f16.f16.f32 "                  \
        "{%0,%1,%2,%3},{%4,%5,%6,%7},{%8,%9},{%0,%1,%2,%3};"                  \
        : "+f"(d[0]), "+f"(d[1]), "+f"(d[2]), "+f"(d[3])                      \
        : "r"(a[0]), "r"(a[1]), "r"(a[2]), "r"(a[3]), "r"(b[0]), "r"(b[1]))

#define LDSM_X4(r, addr)                                                      \
    asm volatile(                                                             \
        "ldmatrix.sync.aligned.m8n8.x4.shared.b16 {%0,%1,%2,%3}, [%4];"       \
        : "=r"((r)[0]), "=r"((r)[1]), "=r"((r)[2]), "=r"((r)[3])              \
        : "r"(addr))

__device__ __forceinline__ void cpa16(uint32_t dst, const void* src) {
    asm volatile("cp.async.cg.shared.global [%0], [%1], 16;"
                 :: "r"(dst), "l"(src));
}
#define CPA_COMMIT()  asm volatile("cp.async.commit_group;" ::: "memory")
#define CPA_WAIT(N)   asm volatile("cp.async.wait_group %0;" :: "n"(N) : "memory")

// ---------------------------------------------------------------------------
// k0: weight transposes + fp16 conversions
// ---------------------------------------------------------------------------
__global__ void k0_prep(const float* __restrict__ Wfc, const float* __restrict__ Wh,
                        const float* __restrict__ Wo, const float* __restrict__ W1,
                        const float* __restrict__ Wih, const float* __restrict__ Whh,
                        __half* __restrict__ Wfch, __half* __restrict__ WhTh,
                        __half* __restrict__ WoTh, __half* __restrict__ W1h,
                        __half* __restrict__ Wih16, __half* __restrict__ Whh16)
{
    int tid = blockIdx.x * blockDim.x + threadIdx.x;
    int stride = gridDim.x * blockDim.x;
    for (int i = tid; i < 64 * OBS; i += stride) Wfch[i] = __float2half(Wfc[i]);
    for (int i = tid; i < 256 * 64; i += stride) {
        int n = i >> 6, e = i & 63;
        int h = n >> 6, d = n & 63;
        WhTh[i] = __float2half(Wh[(h * 64 + e) * 64 + d]);
    }
    for (int i = tid; i < 64 * 256; i += stride) {
        int e = i >> 8, k = i & 255;
        WoTh[i] = __float2half(Wo[k * 64 + e]);
    }
    for (int i = tid; i < RDIM * ZDIM; i += stride) W1h[i] = __float2half(W1[i]);
    for (int i = tid; i < 3 * 256 * 256; i += stride) {
        Wih16[i] = __float2half(Wih[i]);
        Whh16[i] = __float2half(Whh[i]);
    }
}

// ---------------------------------------------------------------------------
// kH: fp32 -> fp16 conversion
// ---------------------------------------------------------------------------
__global__ void kH_f2h(const float* __restrict__ in, __half2* __restrict__ out, int n4)
{
    int i = blockIdx.x * blockDim.x + threadIdx.x;
    int stride = gridDim.x * blockDim.x;
    for (; i < n4; i += stride) {
        float4 v = ((const float4*)in)[i];
        out[2 * i]     = __floats2half2_rn(v.x, v.y);
        out[2 * i + 1] = __floats2half2_rn(v.z, v.w);
    }
}

// ---------------------------------------------------------------------------
// Generic fp16 GEMM (k2-proven layout):  C[M,N64] = EPI([A1|A2] @ W^T + bias)
//   A1: [M,K1] fp16, A2: [M,K2] fp16, W: [N, K1+K2] fp16 row-major.
//   CTA 128x64, 8 warps (32x32), BK=32 halves, 3-buffer cp.async pipeline,
//   pitch-80B rows (conflict-free ldmatrix, no XOR swizzle).
//   EPI: 0 none, 1 +bias, 2 relu(+bias).  OUTH: 0 fp32 out, 1 fp16 out.
// ---------------------------------------------------------------------------
#define GH_STAGEB (128*80 + 64*80)       // 15360 B per stage
#define GH_SMEM   (3 * GH_STAGEB)        // 46080 B

template<int K1, int K2, int EPI, int OUTH>
__global__ void __launch_bounds__(256, 2) gemm_hn(
    const __half* __restrict__ A1, const __half* __restrict__ A2,
    const __half* __restrict__ W,  const float* __restrict__ bias,
    void* __restrict__ Cout)
{
    constexpr int KT = K1 + K2;
    constexpr int NS = KT / 32;
    extern __shared__ __half smh[];
    const uint32_t sbase = (uint32_t)__cvta_generic_to_shared(smh);

    const int tid  = threadIdx.x;
    const int lane = tid & 31;
    const int warp = tid >> 5;
    const int wm = (warp & 3) * 32;
    const int wn = (warp >> 2) * 32;
    const int g  = lane >> 2;
    const int tg = lane & 3;
    const size_t r0 = (size_t)blockIdx.y * 128;
    const int n0 = blockIdx.x * 64;
    const int ldc = gridDim.x * 64;

    // staging: A 512 chunks (2/thread), B 256 chunks (1/thread)
    const int mA = tid >> 2;             // 0..63 (+64 second)
    const int jA = tid & 3;              // 16B chunk = 8 halves
    const uint32_t adst0 = (uint32_t)(mA * 80 + jA * 16);
    const uint32_t adst1 = (uint32_t)((mA + 64) * 80 + jA * 16);
    const int nB = tid >> 2;             // 0..63
    const uint32_t bdst = (uint32_t)(10240 + nB * 80 + jA * 16);

    auto issue = [&](int s) {
        const int buf = s % 3;
        const int kb  = s * 32;          // halves
        const uint32_t sb = sbase + (uint32_t)(buf * GH_STAGEB);
        const int kh = jA * 8;
        if (K2 == 0 || kb < K1) {
            const __half* src = A1 + (size_t)(r0 + mA) * K1 + kb + kh;
            cpa16(sb + adst0, src);
            cpa16(sb + adst1, src + (size_t)64 * K1);
        } else {
            const __half* src = A2 + (size_t)(r0 + mA) * K2 + (kb - K1) + kh;
            cpa16(sb + adst0, src);
            cpa16(sb + adst1, src + (size_t)64 * K2);
        }
        cpa16(sb + bdst, W + (size_t)(n0 + nB) * KT + kb + kh);
        CPA_COMMIT();
    };

    // ldmatrix lane addressing (pitch 80 B) — proven in k2
    const int l7 = lane & 7;
    const int aRow = ((lane >> 3) & 1) * 8 + l7;
    const int aKb  = (lane >> 4) * 16;
    const uint32_t aAddr = sbase + (uint32_t)((wm + aRow) * 80 + aKb);
    const int bRow = ((lane >> 4) & 1) * 8 + l7;
    const int bKb  = ((lane >> 3) & 1) * 16;
    const uint32_t bAddr = sbase + (uint32_t)(10240 + (wn + bRow) * 80 + bKb);

    float acc[2][4][4];
    #pragma unroll
    for (int mt = 0; mt < 2; ++mt)
        #pragma unroll
        for (int nt = 0; nt < 4; ++nt)
            #pragma unroll
            for (int e = 0; e < 4; ++e) acc[mt][nt][e] = 0.f;

    auto compute = [&](int buf) {
        const uint32_t bufoff = (uint32_t)(buf * GH_STAGEB);
        #pragma unroll
        for (int ks = 0; ks < 2; ++ks) {
            const uint32_t ko = bufoff + ks * 32;   // 16 halves = 32 B
            uint32_t a[2][4];
            LDSM_X4(a[0], aAddr + ko);
            LDSM_X4(a[1], aAddr + ko + 16 * 80);
            uint32_t bf[4][2];
            #pragma unroll
            for (int p = 0; p < 2; ++p) {
                uint32_t t[4];
                LDSM_X4(t, bAddr + ko + p * 16 * 80);
                bf[2 * p][0]     = t[0];
                bf[2 * p][1]     = t[1];
                bf[2 * p + 1][0] = t[2];
                bf[2 * p + 1][1] = t[3];
            }
            #pragma unroll
            for (int mt = 0; mt < 2; ++mt)
                #pragma unroll
                for (int nt = 0; nt < 4; ++nt)
                    MMA_F16(acc[mt][nt], a[mt], bf[nt]);
        }
    };

    issue(0);
    if (NS > 1) issue(1);
    CPA_WAIT(1);
    __syncthreads();

    #pragma unroll 1
    for (int s = 0; s < NS; ++s) {
        compute(s % 3);
        if (s + 2 < NS) { issue(s + 2); CPA_WAIT(1); }
        else            { CPA_WAIT(0); }
        __syncthreads();
    }

    #pragma unroll
    for (int mt = 0; mt < 2; ++mt) {
        #pragma unroll
        for (int nt = 0; nt < 4; ++nt) {
            size_t r = r0 + wm + mt * 16 + g;
            int    c = n0 + wn + nt * 8 + tg * 2;
            float v0 = acc[mt][nt][0], v1 = acc[mt][nt][1];
            float v2 = acc[mt][nt][2], v3 = acc[mt][nt][3];
            if (EPI >= 1) {
                float b0 = bias[c], b1 = bias[c + 1];
                v0 += b0; v1 += b1; v2 += b0; v3 += b1;
            }
            if (EPI == 2) {
                v0 = fmaxf(v0, 0.f); v1 = fmaxf(v1, 0.f);
                v2 = fmaxf(v2, 0.f); v3 = fmaxf(v3, 0.f);
            }
            if (OUTH) {
                __half* Ch = (__half*)Cout;
                *(__half2*)(Ch + r * ldc + c)       = __floats2half2_rn(v0, v1);
                *(__half2*)(Ch + (r + 8) * ldc + c) = __floats2half2_rn(v2, v3);
            } else {
                float* C = (float*)Cout;
                *(float2*)(C + r * ldc + c)       = make_float2(v0, v1);
                *(float2*)(C + (r + 8) * ldc + c) = make_float2(v2, v3);
            }
        }
    }
}

// ---------------------------------------------------------------------------
// kB: per-batch masked attention (proven R11, 256 threads; agg out fp16)
// ---------------------------------------------------------------------------
#define KB_HS    0
#define KB_ALPHA 8224
#define KB_SSRC  (KB_ALPHA + 4*32*33)
#define KB_SDST  (KB_SSRC + 128)
#define KB_SAS   (KB_SDST + 128)
#define KB_SAD   (KB_SAS + 256)
#define KB_MSK   (KB_SAD + 256)
#define KB_SMEM  ((KB_MSK + 32*33) * 4)  // 57088 B

__global__ void __launch_bounds__(256) kB_attn(
    const float* __restrict__ H, const int* __restrict__ mask,
    const float* __restrict__ asrc, const float* __restrict__ adst,
    __half* __restrict__ agg)
{
    extern __shared__ float smf[];
    float* Hs    = smf + KB_HS;      // pitch 257
    float* alpha = smf + KB_ALPHA;   // [4][32][33]
    float* ssrc  = smf + KB_SSRC;
    float* sdst  = smf + KB_SDST;
    float* sas   = smf + KB_SAS;
    float* sad   = smf + KB_SAD;
    int*   msk   = (int*)(smf + KB_MSK); // pitch 33

    const int tid  = threadIdx.x;
    const int lane = tid & 31;
    const int warp = tid >> 5;
    const int b    = blockIdx.x;

    const float* Hb = H + (size_t)b * (32 * 256);
    for (int i = tid; i < 32 * 256; i += 256) {
        int a = i >> 8, c = i & 255;
        Hs[a * 257 + c] = Hb[i];
    }
    for (int i = tid; i < 256; i += 256) { sas[i] = asrc[i]; sad[i] = adst[i]; }
    for (int i = tid; i < 32 * 32; i += 256) {
        int r = i >> 5, c = i & 31;
        msk[r * 33 + c] = mask[(size_t)b * (32 * 32) + i];
    }
    __syncthreads();

    if (warp < 4) {
        int hd = warp;
        float vs = 0.f, vd = 0.f;
        const float* hr = Hs + lane * 257 + hd * 64;
        #pragma unroll
        for (int d = 0; d < 64; ++d) {
            float h = hr[d];
            vs = fmaf(h, sas[hd * 64 + d], vs);
            vd = fmaf(h, sad[hd * 64 + d], vd);
        }
        ssrc[hd * 32 + lane] = vs;
        sdst[hd * 32 + lane] = vd;
    }
    __syncthreads();

    if (tid < 128) {
        int hd = tid >> 5, i = tid & 31;
        float si = ssrc[hd * 32 + i];
        float v[32];
        float m = -3.4e38f;
        #pragma unroll
        for (int j = 0; j < 32; ++j) {
            float e_ = si + sdst[hd * 32 + j];
            float l  = e_ > 0.f ? e_ : 0.2f * e_;
            if (msk[i * 33 + j] <= 0) l = -1e9f;
            v[j] = l; m = fmaxf(m, l);
        }
        float s = 0.f;
        #pragma unroll
        for (int j = 0; j < 32; ++j) { v[j] = __expf(v[j] - m); s += v[j]; }
        float inv = 1.f / s;
        #pragma unroll
        for (int j = 0; j < 32; ++j) alpha[(hd * 32 + i) * 33 + j] = v[j] * inv;
    }
    __syncthreads();

    {
        float v[32];
        #pragma unroll
        for (int j = 0; j < 32; ++j) v[j] = Hs[j * 257 + tid];
        const int hd = tid >> 6;
        __half* aggb = agg + (size_t)b * (32 * 256);
        #pragma unroll 4
        for (int a = 0; a < 32; ++a) {
            const float* al = alpha + (hd * 32 + a) * 33;
            float s = 0.f;
            #pragma unroll
            for (int j = 0; j < 32; ++j) s = fmaf(al[j], v[j], s);
            aggb[a * 256 + tid] = __float2half(s);
        }
    }
}

// ---------------------------------------------------------------------------
// k2: GRU via fp16 MMA — unchanged proven R9 kernel
// ---------------------------------------------------------------------------
#define K2H_STAGEB 17920
#define K2H_SMEM   (3 * K2H_STAGEB)

__global__ void __launch_bounds__(256, 2) k2_gru_f16(
    const __half* __restrict__ xrh,  const __half* __restrict__ hinh,
    const float*  __restrict__ hin,
    const __half* __restrict__ Wih,  const __half* __restrict__ Whh,
    const float*  __restrict__ bih,  const float*  __restrict__ bhh,
    float* __restrict__ hh_out)
{
    extern __shared__ __half smh[];
    const uint32_t sbase = (uint32_t)__cvta_generic_to_shared(smh);

    const int tid  = threadIdx.x;
    const int lane = tid & 31;
    const int warp = tid >> 5;
    const int wm  = (warp & 3) * 32;
    const int wn  = (warp >> 2) * 48;
    const int g   = lane >> 2;
    const int tg  = lane & 3;
    const size_t r0 = (size_t)blockIdx.y * 128;
    const int c0 = blockIdx.x * 32;

    const int mA = tid >> 2;
    const int jA = tid & 3;
    const size_t aoff0 = (r0 + mA) * 256 + jA * 8;
    const size_t aoff1 = (r0 + mA + 64) * 256 + jA * 8;
    const uint32_t adst0 = (uint32_t)(mA * 80 + jA * 16);
    const uint32_t adst1 = (uint32_t)((mA + 64) * 80 + jA * 16);
    auto wrow_of = [&](int n) {
        int grp = n >> 4, cl = n & 15;
        return (grp % 3) * 256 + c0 + (grp / 3) * 16 + cl;
    };
    const int nB0 = tid >> 2;
    const int jB = tid & 3;
    const size_t boff0 = (size_t)wrow_of(nB0) * 256 + jB * 8;
    const size_t boff1 = (size_t)wrow_of(nB0 + 64) * 256 + jB * 8;
    const uint32_t bdst0 = (uint32_t)(10240 + nB0 * 80 + jB * 16);
    const uint32_t bdst1 = (uint32_t)(10240 + (nB0 + 64) * 80 + jB * 16);

    auto issue = [&](int s) {
        const int buf = s % 3;
        const int kloc = (s & 7) * 32;
        const __half* Asrc = (s < 8) ? xrh : hinh;
        const __half* Wsrc = (s < 8) ? Wih : Whh;
        const uint32_t sb = sbase + (uint32_t)(buf * K2H_STAGEB);
        cpa16(sb + adst0, Asrc + aoff0 + kloc);
        cpa16(sb + adst1, Asrc + aoff1 + kloc);
        cpa16(sb + bdst0, Wsrc + boff0 + kloc);
        if (tid < 128) cpa16(sb + bdst1, Wsrc + boff1 + kloc);
        CPA_COMMIT();
    };

    const int l7 = lane & 7;
    const int aRow = ((lane >> 3) & 1) * 8 + l7;
    const int aKb  = (lane >> 4) * 16;
    const uint32_t aAddr = sbase + (uint32_t)((wm + aRow) * 80 + aKb);
    const int bRow = ((lane >> 4) & 1) * 8 + l7;
    const int bKb  = ((lane >> 3) & 1) * 16;
    const uint32_t bAddr = sbase + (uint32_t)(10240 + (wn + bRow) * 80 + bKb);

    float acc [2][4][4];
    float accd[2][2][2][4];
    #pragma unroll
    for (int mt = 0; mt < 2; ++mt) {
        #pragma unroll
        for (int nt = 0; nt < 4; ++nt)
            #pragma unroll
            for (int e = 0; e < 4; ++e) acc[mt][nt][e] = 0.f;
        #pragma unroll
        for (int p = 0; p < 2; ++p)
            #pragma unroll
            for (int j = 0; j < 2; ++j)
                #pragma unroll
                for (int e = 0; e < 4; ++e) accd[p][mt][j][e] = 0.f;
    }

    auto compute = [&](int buf, int ph) {
        const uint32_t bufoff = (uint32_t)(buf * K2H_STAGEB);
        #pragma unroll
        for (int ks = 0; ks < 2; ++ks) {
            const uint32_t ko = bufoff + ks * 32;
            uint32_t a[2][4];
            LDSM_X4(a[0], aAddr + ko);
            LDSM_X4(a[1], aAddr + ko + 16 * 80);
            uint32_t bf[6][2];
            #pragma unroll
            for (int p = 0; p < 3; ++p) {
                uint32_t t[4];
                LDSM_X4(t, bAddr + ko + p * 16 * 80);
                bf[2 * p][0]     = t[0];
                bf[2 * p][1]     = t[1];
                bf[2 * p + 1][0] = t[2];
                bf[2 * p + 1][1] = t[3];
            }
            #pragma unroll
            for (int mt = 0; mt < 2; ++mt) {
                #pragma unroll
                for (int nt = 0; nt < 4; ++nt)
                    MMA_F16(acc[mt][nt], a[mt], bf[nt]);
                #pragma unroll
                for (int j = 0; j < 2; ++j) {
                    if (ph == 0) { MMA_F16(accd[0][mt][j], a[mt], bf[4 + j]); }
                    else         { MMA_F16(accd[1][mt][j], a[mt], bf[4 + j]); }
                }
            }
        }
    };

    issue(0);
    issue(1);
    CPA_WAIT(1);
    __syncthreads();

    int s = 0;
    #pragma unroll 1
    for (; s < 8; ++s) {
        compute(s % 3, 0);
        if (s + 2 < 16) { issue(s + 2); CPA_WAIT(1); }
        else            { CPA_WAIT(0); }
        __syncthreads();
    }
    #pragma unroll 1
    for (; s < 16; ++s) {
        compute(s % 3, 1);
        if (s + 2 < 16) { issue(s + 2); CPA_WAIT(1); }
        else            { CPA_WAIT(0); }
        __syncthreads();
    }

    const int colbase = c0 + (wn ? 16 : 0);
    #pragma unroll
    for (int mt = 0; mt < 2; ++mt) {
        const size_t rA = r0 + wm + mt * 16 + g;
        const size_t rB = rA + 8;
        #pragma unroll
        for (int j = 0; j < 2; ++j) {
            const int c = colbase + j * 8 + tg * 2;
            const float br0  = bih[c]       + bhh[c];
            const float br1  = bih[c + 1]   + bhh[c + 1];
            const float bz0  = bih[256 + c] + bhh[256 + c];
            const float bz1  = bih[257 + c] + bhh[257 + c];
            const float bni0 = bih[512 + c],  bni1 = bih[513 + c];
            const float bnh0 = bhh[512 + c],  bnh1 = bhh[513 + c];
            const float2 hpA = *(const float2*)(hin + rA * 256 + c);
            const float2 hpB = *(const float2*)(hin + rB * 256 + c);

            float rg, zg, ng;
            rg = sigf(acc[mt][j][0] + br0);
            zg = sigf(acc[mt][2 + j][0] + bz0);
            ng = tanhf(accd[0][mt][j][0] + bni0 + rg * (accd[1][mt][j][0] + bnh0));
            float o0 = (1.f - zg) * ng + zg * hpA.x;

            rg = sigf(acc[mt][j][1] + br1);
            zg = sigf(acc[mt][2 + j][1] + bz1);
            ng = tanhf(accd[0][mt][j][1] + bni1 + rg * (accd[1][mt][j][1] + bnh1));
            float o1 = (1.f - zg) * ng + zg * hpA.y;

            rg = sigf(acc[mt][j][2] + br0);
            zg = sigf(acc[mt][2 + j][2] + bz0);
            ng = tanhf(accd[0][mt][j][2] + bni0 + rg * (accd[1][mt][j][2] + bnh0));
            float o2 = (1.f - zg) * ng + zg * hpB.x;

            rg = sigf(acc[mt][j][3] + br1);
            zg = sigf(acc[mt][2 + j][3] + bz1);
            ng = tanhf(accd[0][mt][j][3] + bni1 + rg * (accd[1][mt][j][3] + bnh1));
            float o3 = (1.f - zg) * ng + zg * hpB.y;

            *(float2*)(hh_out + rA * 256 + c) = make_float2(o0, o1);
            *(float2*)(hh_out + rB * 256 + c) = make_float2(o2, o3);
        }
    }
}

// ---------------------------------------------------------------------------
// k3: LayerNorm + fc2 (one warp per row) — unchanged
// ---------------------------------------------------------------------------
__global__ void __launch_bounds__(256) k3_ln_fc2(
    const float* __restrict__ hh, const float* __restrict__ lng,
    const float* __restrict__ lnb, const float* __restrict__ W2,
    const float* __restrict__ b2, float* __restrict__ q, int nrows)
{
    int warp = (blockIdx.x * blockDim.x + threadIdx.x) >> 5;
    int lane = threadIdx.x & 31;
    if (warp >= nrows) return;
    const float* hr = hh + (size_t)warp * RDIM;

    float v[8];
    float s = 0.f;
    #pragma unroll
    for (int i = 0; i < 8; ++i) { v[i] = hr[lane + 32 * i]; s += v[i]; }
    #pragma unroll
    for (int o = 16; o; o >>= 1) s += __shfl_xor_sync(0xffffffffu, s, o);
    float mu = s * (1.f / 256.f);
    float vs = 0.f;
    #pragma unroll
    for (int i = 0; i < 8; ++i) { float d = v[i] - mu; vs += d * d; }
    #pragma unroll
    for (int o = 16; o; o >>= 1) vs += __shfl_xor_sync(0xffffffffu, vs, o);
    float inv = rsqrtf(vs * (1.f / 256.f) + 1e-5f);

    float hn[8];
    #pragma unroll
    for (int i = 0; i < 8; ++i)
        hn[i] = (v[i] - mu) * inv * lng[lane + 32 * i] + lnb[lane + 32 * i];

    #pragma unroll
    for (int j = 0; j < NACT; ++j) {
        float p = 0.f;
        #pragma unroll
        for (int i = 0; i < 8; ++i) p = fmaf(hn[i], W2[j * RDIM + lane + 32 * i], p);
        #pragma unroll
        for (int o = 16; o; o >>= 1) p += __shfl_xor_sync(0xffffffffu, p, o);
        if (lane == j) q[(size_t)warp * NACT + j] = p + b2[j];
    }
}

// ---------------------------------------------------------------------------
extern "C" void kernel_launch(void* const* d_in, const int* in_sizes, int n_in,
                              void* d_out, int out_size)
{
    const float* inputs = (const float*)d_in[0];
    const float* hidden = (const float*)d_in[1];
    const int*   mask   = (const int*)  d_in[2];
    const float* Wfc    = (const float*)d_in[3];
    const float* bfc    = (const float*)d_in[4];
    const float* Wh     = (const float*)d_in[5];
    const float* asrc   = (const float*)d_in[6];
    const float* adst   = (const float*)d_in[7];
    const float* Wo     = (const float*)d_in[8];
    const float* bo     = (const float*)d_in[9];
    const float* W1     = (const float*)d_in[10];
    const float* b1     = (const float*)d_in[11];
    const float* Wih    = (const float*)d_in[12];
    const float* Whh    = (const float*)d_in[13];
    const float* bih    = (const float*)d_in[14];
    const float* bhh    = (const float*)d_in[15];
    const float* lng    = (const float*)d_in[16];
    const float* lnb    = (const float*)d_in[17];
    const float* W2     = (const float*)d_in[18];
    const float* b2     = (const float*)d_in[19];

    const int B = in_sizes[0] / (AN * OBS);       // 4096
    const int nrows = B * AN;                     // 131072
    const int mblk = nrows / 128;                 // 1024

    float* q_out  = (float*)d_out;
    float* hh_out = (float*)d_out + (size_t)nrows * NACT;

    float *bh;
    __half *inh, *xeh, *aggh, *atth, *xrh, *hinh;
    __half *wfch, *whth, *woth, *w1h, *wih16, *whh16;
    cudaGetSymbolAddress((void**)&bh,    g_bufH);
    cudaGetSymbolAddress((void**)&inh,   g_inh);
    cudaGetSymbolAddress((void**)&xeh,   g_xeh);
    cudaGetSymbolAddress((void**)&aggh,  g_aggh);
    cudaGetSymbolAddress((void**)&atth,  g_atth);
    cudaGetSymbolAddress((void**)&xrh,   g_xrh);
    cudaGetSymbolAddress((void**)&hinh,  g_hinh);
    cudaGetSymbolAddress((void**)&wfch,  g_Wfch);
    cudaGetSymbolAddress((void**)&whth,  g_WhTh);
    cudaGetSymbolAddress((void**)&woth,  g_WoTh);
    cudaGetSymbolAddress((void**)&w1h,   g_W1h);
    cudaGetSymbolAddress((void**)&wih16, g_Wih16);
    cudaGetSymbolAddress((void**)&whh16, g_Whh16);

    cudaFuncSetAttribute(kB_attn,    cudaFuncAttributeMaxDynamicSharedMemorySize, KB_SMEM);
    cudaFuncSetAttribute(k2_gru_f16, cudaFuncAttributeMaxDynamicSharedMemorySize, K2H_SMEM);
    cudaFuncSetAttribute(gemm_hn<128, 0, 1, 1>, cudaFuncAttributeMaxDynamicSharedMemorySize, GH_SMEM);
    cudaFuncSetAttribute(gemm_hn<64, 0, 0, 0>,  cudaFuncAttributeMaxDynamicSharedMemorySize, GH_SMEM);
    cudaFuncSetAttribute(gemm_hn<256, 0, 1, 1>, cudaFuncAttributeMaxDynamicSharedMemorySize, GH_SMEM);
    cudaFuncSetAttribute(gemm_hn<128, 64, 2, 1>,cudaFuncAttributeMaxDynamicSharedMemorySize, GH_SMEM);

    k0_prep<<<64, 256>>>(Wfc, Wh, Wo, W1, Wih, Whh,
                         wfch, whth, woth, w1h, wih16, whh16);
    kH_f2h<<<4096, 256>>>(hidden, (__half2*)hinh, nrows * RDIM / 4);
    kH_f2h<<<4096, 256>>>(inputs, (__half2*)inh,  nrows * OBS / 4);

    // G1: XE = inputs @ Wfc^T + bfc          [M,64] fp16
    gemm_hn<128, 0, 1, 1><<<dim3(1, mblk), 256, GH_SMEM>>>(inh, nullptr, wfch, bfc, xeh);
    // G2: H = XE @ WhT^T                     [M,256] fp32 (for attention)
    gemm_hn<64, 0, 0, 0><<<dim3(4, mblk), 256, GH_SMEM>>>(xeh, nullptr, whth, nullptr, bh);
    // attention: agg = softmax(mask, leaky(s_i+s_j)) @ H  -> fp16
    kB_attn<<<B, 256, KB_SMEM>>>(bh, mask, asrc, adst, aggh);
    // G3: ATT = agg @ WoT^T + bo             [M,64] fp16
    gemm_hn<256, 0, 1, 1><<<dim3(1, mblk), 256, GH_SMEM>>>(aggh, nullptr, woth, bo, atth);
    // G4: XR = relu([inputs|ATT] @ W1^T+b1)  [M,256] fp16
    gemm_hn<128, 64, 2, 1><<<dim3(4, mblk), 256, GH_SMEM>>>(inh, atth, w1h, b1, xrh);
    // GRU (fp16 MMA pipeline, warp-local gates)
    k2_gru_f16<<<dim3(8, mblk), 256, K2H_SMEM>>>(xrh, hinh, hidden, wih16, whh16,
                                                 bih, bhh, hh_out);
    // LN + fc2
    k3_ln_fc2<<<(nrows + 7) / 8, 256>>>(hh_out, lng, lnb, W2, b2, q_out, nrows);
}

// round 14
// speedup vs baseline: 1.2910x; 1.0289x over previous
#include <cuda_runtime.h>
#include <cuda_fp16.h>
#include <cuda_bf16.h>
#include <stdint.h>

// Problem constants
#define AN   32
#define OBS  128
#define EDIM 64
#define DDIM 64
#define HHEADS 4
#define RDIM 256
#define NACT 16
#define ZDIM 192
#define MAXROWS (4096*32)

// Scratch buffers
__device__ __align__(16) __half g_bufHh[MAXROWS * RDIM];  // H fp16
__device__ __align__(16) __half g_inh  [MAXROWS * OBS];   // inputs fp16
__device__ __align__(16) __half g_xeh  [MAXROWS * 64];    // XE fp16
__device__ __align__(16) __half g_aggh [MAXROWS * RDIM];  // agg fp16
__device__ __align__(16) __half g_atth [MAXROWS * 64];    // ATT fp16
__device__ __align__(16) __half g_xrh  [MAXROWS * RDIM];  // XR fp16
__device__ __align__(16) __half g_hinh [MAXROWS * RDIM];  // hidden fp16
__device__ __align__(16) __half g_Wfch [64 * OBS];
__device__ __align__(16) __half g_WhTh [256 * 64];
__device__ __align__(16) __half g_WoTh [64 * 256];
__device__ __align__(16) __half g_W1h  [RDIM * ZDIM];
__device__ __align__(16) __half g_Wih16[3 * RDIM * RDIM];
__device__ __align__(16) __half g_Whh16[3 * RDIM * RDIM];

__device__ __forceinline__ float sigf(float x) { return 1.0f / (1.0f + __expf(-x)); }

#define MMA_F16(d, a, b)                                                      \
    asm volatile(                                                             \
        "mma.sync.aligned.m16n8k16.row.col.f32.f16.f16.f32 "                  \
        "{%0,%1,%2,%3},{%4,%5,%6,%7},{%8,%9},{%0,%1,%2,%3};"                  \
        : "+f"(d[0]), "+f"(d[1]), "+f"(d[2]), "+f"(d[3])                      \
        : "r"(a[0]), "r"(a[1]), "r"(a[2]), "r"(a[3]), "r"(b[0]), "r"(b[1]))

#define LDSM_X4(r, addr)                                                      \
    asm volatile(                                                             \
        "ldmatrix.sync.aligned.m8n8.x4.shared.b16 {%0,%1,%2,%3}, [%4];"       \
        : "=r"((r)[0]), "=r"((r)[1]), "=r"((r)[2]), "=r"((r)[3])              \
        : "r"(addr))

__device__ __forceinline__ void cpa16(uint32_t dst, const void* src) {
    asm volatile("cp.async.cg.shared.global [%0], [%1], 16;"
                 :: "r"(dst), "l"(src));
}
#define CPA_COMMIT()  asm volatile("cp.async.commit_group;" ::: "memory")
#define CPA_WAIT(N)   asm volatile("cp.async.wait_group %0;" :: "n"(N) : "memory")

// ---------------------------------------------------------------------------
// k0: weight transposes + fp16 conversions
// ---------------------------------------------------------------------------
__global__ void k0_prep(const float* __restrict__ Wfc, const float* __restrict__ Wh,
                        const float* __restrict__ Wo, const float* __restrict__ W1,
                        const float* __restrict__ Wih, const float* __restrict__ Whh,
                        __half* __restrict__ Wfch, __half* __restrict__ WhTh,
                        __half* __restrict__ WoTh, __half* __restrict__ W1h,
                        __half* __restrict__ Wih16, __half* __restrict__ Whh16)
{
    int tid = blockIdx.x * blockDim.x + threadIdx.x;
    int stride = gridDim.x * blockDim.x;
    for (int i = tid; i < 64 * OBS; i += stride) Wfch[i] = __float2half(Wfc[i]);
    for (int i = tid; i < 256 * 64; i += stride) {
        int n = i >> 6, e = i & 63;
        int h = n >> 6, d = n & 63;
        WhTh[i] = __float2half(Wh[(h * 64 + e) * 64 + d]);
    }
    for (int i = tid; i < 64 * 256; i += stride) {
        int e = i >> 8, k = i & 255;
        WoTh[i] = __float2half(Wo[k * 64 + e]);
    }
    for (int i = tid; i < RDIM * ZDIM; i += stride) W1h[i] = __float2half(W1[i]);
    for (int i = tid; i < 3 * 256 * 256; i += stride) {
        Wih16[i] = __float2half(Wih[i]);
        Whh16[i] = __float2half(Whh[i]);
    }
}

// ---------------------------------------------------------------------------
// kH: fp32 -> fp16 conversion
// ---------------------------------------------------------------------------
__global__ void kH_f2h(const float* __restrict__ in, __half2* __restrict__ out, int n4)
{
    int i = blockIdx.x * blockDim.x + threadIdx.x;
    int stride = gridDim.x * blockDim.x;
    for (; i < n4; i += stride) {
        float4 v = ((const float4*)in)[i];
        out[2 * i]     = __floats2half2_rn(v.x, v.y);
        out[2 * i + 1] = __floats2half2_rn(v.z, v.w);
    }
}

// ---------------------------------------------------------------------------
// Generic fp16 GEMM (k2-proven layout) — unchanged from R12
// ---------------------------------------------------------------------------
#define GH_STAGEB (128*80 + 64*80)       // 15360 B per stage
#define GH_SMEM   (3 * GH_STAGEB)        // 46080 B

template<int K1, int K2, int EPI, int OUTH>
__global__ void __launch_bounds__(256, 2) gemm_hn(
    const __half* __restrict__ A1, const __half* __restrict__ A2,
    const __half* __restrict__ W,  const float* __restrict__ bias,
    void* __restrict__ Cout)
{
    constexpr int KT = K1 + K2;
    constexpr int NS = KT / 32;
    extern __shared__ __half smh[];
    const uint32_t sbase = (uint32_t)__cvta_generic_to_shared(smh);

    const int tid  = threadIdx.x;
    const int lane = tid & 31;
    const int warp = tid >> 5;
    const int wm = (warp & 3) * 32;
    const int wn = (warp >> 2) * 32;
    const int g  = lane >> 2;
    const int tg = lane & 3;
    const size_t r0 = (size_t)blockIdx.y * 128;
    const int n0 = blockIdx.x * 64;
    const int ldc = gridDim.x * 64;

    const int mA = tid >> 2;
    const int jA = tid & 3;
    const uint32_t adst0 = (uint32_t)(mA * 80 + jA * 16);
    const uint32_t adst1 = (uint32_t)((mA + 64) * 80 + jA * 16);
    const int nB = tid >> 2;
    const uint32_t bdst = (uint32_t)(10240 + nB * 80 + jA * 16);

    auto issue = [&](int s) {
        const int buf = s % 3;
        const int kb  = s * 32;
        const uint32_t sb = sbase + (uint32_t)(buf * GH_STAGEB);
        const int kh = jA * 8;
        if (K2 == 0 || kb < K1) {
            const __half* src = A1 + (size_t)(r0 + mA) * K1 + kb + kh;
            cpa16(sb + adst0, src);
            cpa16(sb + adst1, src + (size_t)64 * K1);
        } else {
            const __half* src = A2 + (size_t)(r0 + mA) * K2 + (kb - K1) + kh;
            cpa16(sb + adst0, src);
            cpa16(sb + adst1, src + (size_t)64 * K2);
        }
        cpa16(sb + bdst, W + (size_t)(n0 + nB) * KT + kb + kh);
        CPA_COMMIT();
    };

    const int l7 = lane & 7;
    const int aRow = ((lane >> 3) & 1) * 8 + l7;
    const int aKb  = (lane >> 4) * 16;
    const uint32_t aAddr = sbase + (uint32_t)((wm + aRow) * 80 + aKb);
    const int bRow = ((lane >> 4) & 1) * 8 + l7;
    const int bKb  = ((lane >> 3) & 1) * 16;
    const uint32_t bAddr = sbase + (uint32_t)(10240 + (wn + bRow) * 80 + bKb);

    float acc[2][4][4];
    #pragma unroll
    for (int mt = 0; mt < 2; ++mt)
        #pragma unroll
        for (int nt = 0; nt < 4; ++nt)
            #pragma unroll
            for (int e = 0; e < 4; ++e) acc[mt][nt][e] = 0.f;

    auto compute = [&](int buf) {
        const uint32_t bufoff = (uint32_t)(buf * GH_STAGEB);
        #pragma unroll
        for (int ks = 0; ks < 2; ++ks) {
            const uint32_t ko = bufoff + ks * 32;
            uint32_t a[2][4];
            LDSM_X4(a[0], aAddr + ko);
            LDSM_X4(a[1], aAddr + ko + 16 * 80);
            uint32_t bf[4][2];
            #pragma unroll
            for (int p = 0; p < 2; ++p) {
                uint32_t t[4];
                LDSM_X4(t, bAddr + ko + p * 16 * 80);
                bf[2 * p][0]     = t[0];
                bf[2 * p][1]     = t[1];
                bf[2 * p + 1][0] = t[2];
                bf[2 * p + 1][1] = t[3];
            }
            #pragma unroll
            for (int mt = 0; mt < 2; ++mt)
                #pragma unroll
                for (int nt = 0; nt < 4; ++nt)
                    MMA_F16(acc[mt][nt], a[mt], bf[nt]);
        }
    };

    issue(0);
    if (NS > 1) issue(1);
    CPA_WAIT(1);
    __syncthreads();

    #pragma unroll 1
    for (int s = 0; s < NS; ++s) {
        compute(s % 3);
        if (s + 2 < NS) { issue(s + 2); CPA_WAIT(1); }
        else            { CPA_WAIT(0); }
        __syncthreads();
    }

    #pragma unroll
    for (int mt = 0; mt < 2; ++mt) {
        #pragma unroll
        for (int nt = 0; nt < 4; ++nt) {
            size_t r = r0 + wm + mt * 16 + g;
            int    c = n0 + wn + nt * 8 + tg * 2;
            float v0 = acc[mt][nt][0], v1 = acc[mt][nt][1];
            float v2 = acc[mt][nt][2], v3 = acc[mt][nt][3];
            if (EPI >= 1) {
                float b0 = bias[c], b1 = bias[c + 1];
                v0 += b0; v1 += b1; v2 += b0; v3 += b1;
            }
            if (EPI == 2) {
                v0 = fmaxf(v0, 0.f); v1 = fmaxf(v1, 0.f);
                v2 = fmaxf(v2, 0.f); v3 = fmaxf(v3, 0.f);
            }
            if (OUTH) {
                __half* Ch = (__half*)Cout;
                *(__half2*)(Ch + r * ldc + c)       = __floats2half2_rn(v0, v1);
                *(__half2*)(Ch + (r + 8) * ldc + c) = __floats2half2_rn(v2, v3);
            } else {
                float* C = (float*)Cout;
                *(float2*)(C + r * ldc + c)       = make_float2(v0, v1);
                *(float2*)(C + (r + 8) * ldc + c) = make_float2(v2, v3);
            }
        }
    }
}

// ---------------------------------------------------------------------------
// kB: per-batch masked attention — fp16 H input (halved load traffic),
// 256 threads (proven R11 structure), fp16 agg output.
// ---------------------------------------------------------------------------
#define KB_HS    0
#define KB_ALPHA 8224
#define KB_SSRC  (KB_ALPHA + 4*32*33)
#define KB_SDST  (KB_SSRC + 128)
#define KB_SAS   (KB_SDST + 128)
#define KB_SAD   (KB_SAS + 256)
#define KB_MSK   (KB_SAD + 256)
#define KB_SMEM  ((KB_MSK + 32*33) * 4)  // 57088 B

__global__ void __launch_bounds__(256) kB_attn(
    const __half* __restrict__ H, const int* __restrict__ mask,
    const float* __restrict__ asrc, const float* __restrict__ adst,
    __half* __restrict__ agg)
{
    extern __shared__ float smf[];
    float* Hs    = smf + KB_HS;      // pitch 257
    float* alpha = smf + KB_ALPHA;   // [4][32][33]
    float* ssrc  = smf + KB_SSRC;
    float* sdst  = smf + KB_SDST;
    float* sas   = smf + KB_SAS;
    float* sad   = smf + KB_SAD;
    int*   msk   = (int*)(smf + KB_MSK); // pitch 33

    const int tid  = threadIdx.x;
    const int lane = tid & 31;
    const int warp = tid >> 5;
    const int b    = blockIdx.x;

    // load H[b] (fp16) into fp32 smem, half2-vectorized
    const __half2* Hb2 = (const __half2*)(H + (size_t)b * (32 * 256));
    for (int i = tid; i < 32 * 128; i += 256) {
        int a = i >> 7, c2 = i & 127;
        float2 v = __half22float2(Hb2[i]);
        Hs[a * 257 + 2 * c2]     = v.x;
        Hs[a * 257 + 2 * c2 + 1] = v.y;
    }
    for (int i = tid; i < 256; i += 256) { sas[i] = asrc[i]; sad[i] = adst[i]; }
    for (int i = tid; i < 32 * 32; i += 256) {
        int r = i >> 5, c = i & 31;
        msk[r * 33 + c] = mask[(size_t)b * (32 * 32) + i];
    }
    __syncthreads();

    if (warp < 4) {
        int hd = warp;
        float vs = 0.f, vd = 0.f;
        const float* hr = Hs + lane * 257 + hd * 64;
        #pragma unroll
        for (int d = 0; d < 64; ++d) {
            float h = hr[d];
            vs = fmaf(h, sas[hd * 64 + d], vs);
            vd = fmaf(h, sad[hd * 64 + d], vd);
        }
        ssrc[hd * 32 + lane] = vs;
        sdst[hd * 32 + lane] = vd;
    }
    __syncthreads();

    if (tid < 128) {
        int hd = tid >> 5, i = tid & 31;
        float si = ssrc[hd * 32 + i];
        float v[32];
        float m = -3.4e38f;
        #pragma unroll
        for (int j = 0; j < 32; ++j) {
            float e_ = si + sdst[hd * 32 + j];
            float l  = e_ > 0.f ? e_ : 0.2f * e_;
            if (msk[i * 33 + j] <= 0) l = -1e9f;
            v[j] = l; m = fmaxf(m, l);
        }
        float s = 0.f;
        #pragma unroll
        for (int j = 0; j < 32; ++j) { v[j] = __expf(v[j] - m); s += v[j]; }
        float inv = 1.f / s;
        #pragma unroll
        for (int j = 0; j < 32; ++j) alpha[(hd * 32 + i) * 33 + j] = v[j] * inv;
    }
    __syncthreads();

    {
        float v[32];
        #pragma unroll
        for (int j = 0; j < 32; ++j) v[j] = Hs[j * 257 + tid];
        const int hd = tid >> 6;
        __half* aggb = agg + (size_t)b * (32 * 256);
        #pragma unroll 4
        for (int a = 0; a < 32; ++a) {
            const float* al = alpha + (hd * 32 + a) * 33;
            float s = 0.f;
            #pragma unroll
            for (int j = 0; j < 32; ++j) s = fmaf(al[j], v[j], s);
            aggb[a * 256 + tid] = __float2half(s);
        }
    }
}

// ---------------------------------------------------------------------------
// k2: GRU via fp16 MMA — unchanged proven R9 kernel
// ---------------------------------------------------------------------------
#define K2H_STAGEB 17920
#define K2H_SMEM   (3 * K2H_STAGEB)

__global__ void __launch_bounds__(256, 2) k2_gru_f16(
    const __half* __restrict__ xrh,  const __half* __restrict__ hinh,
    const float*  __restrict__ hin,
    const __half* __restrict__ Wih,  const __half* __restrict__ Whh,
    const float*  __restrict__ bih,  const float*  __restrict__ bhh,
    float* __restrict__ hh_out)
{
    extern __shared__ __half smh[];
    const uint32_t sbase = (uint32_t)__cvta_generic_to_shared(smh);

    const int tid  = threadIdx.x;
    const int lane = tid & 31;
    const int warp = tid >> 5;
    const int wm  = (warp & 3) * 32;
    const int wn  = (warp >> 2) * 48;
    const int g   = lane >> 2;
    const int tg  = lane & 3;
    const size_t r0 = (size_t)blockIdx.y * 128;
    const int c0 = blockIdx.x * 32;

    const int mA = tid >> 2;
    const int jA = tid & 3;
    const size_t aoff0 = (r0 + mA) * 256 + jA * 8;
    const size_t aoff1 = (r0 + mA + 64) * 256 + jA * 8;
    const uint32_t adst0 = (uint32_t)(mA * 80 + jA * 16);
    const uint32_t adst1 = (uint32_t)((mA + 64) * 80 + jA * 16);
    auto wrow_of = [&](int n) {
        int grp = n >> 4, cl = n & 15;
        return (grp % 3) * 256 + c0 + (grp / 3) * 16 + cl;
    };
    const int nB0 = tid >> 2;
    const int jB = tid & 3;
    const size_t boff0 = (size_t)wrow_of(nB0) * 256 + jB * 8;
    const size_t boff1 = (size_t)wrow_of(nB0 + 64) * 256 + jB * 8;
    const uint32_t bdst0 = (uint32_t)(10240 + nB0 * 80 + jB * 16);
    const uint32_t bdst1 = (uint32_t)(10240 + (nB0 + 64) * 80 + jB * 16);

    auto issue = [&](int s) {
        const int buf = s % 3;
        const int kloc = (s & 7) * 32;
        const __half* Asrc = (s < 8) ? xrh : hinh;
        const __half* Wsrc = (s < 8) ? Wih : Whh;
        const uint32_t sb = sbase + (uint32_t)(buf * K2H_STAGEB);
        cpa16(sb + adst0, Asrc + aoff0 + kloc);
        cpa16(sb + adst1, Asrc + aoff1 + kloc);
        cpa16(sb + bdst0, Wsrc + boff0 + kloc);
        if (tid < 128) cpa16(sb + bdst1, Wsrc + boff1 + kloc);
        CPA_COMMIT();
    };

    const int l7 = lane & 7;
    const int aRow = ((lane >> 3) & 1) * 8 + l7;
    const int aKb  = (lane >> 4) * 16;
    const uint32_t aAddr = sbase + (uint32_t)((wm + aRow) * 80 + aKb);
    const int bRow = ((lane >> 4) & 1) * 8 + l7;
    const int bKb  = ((lane >> 3) & 1) * 16;
    const uint32_t bAddr = sbase + (uint32_t)(10240 + (wn + bRow) * 80 + bKb);

    float acc [2][4][4];
    float accd[2][2][2][4];
    #pragma unroll
    for (int mt = 0; mt < 2; ++mt) {
        #pragma unroll
        for (int nt = 0; nt < 4; ++nt)
            #pragma unroll
            for (int e = 0; e < 4; ++e) acc[mt][nt][e] = 0.f;
        #pragma unroll
        for (int p = 0; p < 2; ++p)
            #pragma unroll
            for (int j = 0; j < 2; ++j)
                #pragma unroll
                for (int e = 0; e < 4; ++e) accd[p][mt][j][e] = 0.f;
    }

    auto compute = [&](int buf, int ph) {
        const uint32_t bufoff = (uint32_t)(buf * K2H_STAGEB);
        #pragma unroll
        for (int ks = 0; ks < 2; ++ks) {
            const uint32_t ko = bufoff + ks * 32;
            uint32_t a[2][4];
            LDSM_X4(a[0], aAddr + ko);
            LDSM_X4(a[1], aAddr + ko + 16 * 80);
            uint32_t bf[6][2];
            #pragma unroll
            for (int p = 0; p < 3; ++p) {
                uint32_t t[4];
                LDSM_X4(t, bAddr + ko + p * 16 * 80);
                bf[2 * p][0]     = t[0];
                bf[2 * p][1]     = t[1];
                bf[2 * p + 1][0] = t[2];
                bf[2 * p + 1][1] = t[3];
            }
            #pragma unroll
            for (int mt = 0; mt < 2; ++mt) {
                #pragma unroll
                for (int nt = 0; nt < 4; ++nt)
                    MMA_F16(acc[mt][nt], a[mt], bf[nt]);
                #pragma unroll
                for (int j = 0; j < 2; ++j) {
                    if (ph == 0) { MMA_F16(accd[0][mt][j], a[mt], bf[4 + j]); }
                    else         { MMA_F16(accd[1][mt][j], a[mt], bf[4 + j]); }
                }
            }
        }
    };

    issue(0);
    issue(1);
    CPA_WAIT(1);
    __syncthreads();

    int s = 0;
    #pragma unroll 1
    for (; s < 8; ++s) {
        compute(s % 3, 0);
        if (s + 2 < 16) { issue(s + 2); CPA_WAIT(1); }
        else            { CPA_WAIT(0); }
        __syncthreads();
    }
    #pragma unroll 1
    for (; s < 16; ++s) {
        compute(s % 3, 1);
        if (s + 2 < 16) { issue(s + 2); CPA_WAIT(1); }
        else            { CPA_WAIT(0); }
        __syncthreads();
    }

    const int colbase = c0 + (wn ? 16 : 0);
    #pragma unroll
    for (int mt = 0; mt < 2; ++mt) {
        const size_t rA = r0 + wm + mt * 16 + g;
        const size_t rB = rA + 8;
        #pragma unroll
        for (int j = 0; j < 2; ++j) {
            const int c = colbase + j * 8 + tg * 2;
            const float br0  = bih[c]       + bhh[c];
            const float br1  = bih[c + 1]   + bhh[c + 1];
            const float bz0  = bih[256 + c] + bhh[256 + c];
            const float bz1  = bih[257 + c] + bhh[257 + c];
            const float bni0 = bih[512 + c],  bni1 = bih[513 + c];
            const float bnh0 = bhh[512 + c],  bnh1 = bhh[513 + c];
            const float2 hpA = *(const float2*)(hin + rA * 256 + c);
            const float2 hpB = *(const float2*)(hin + rB * 256 + c);

            float rg, zg, ng;
            rg = sigf(acc[mt][j][0] + br0);
            zg = sigf(acc[mt][2 + j][0] + bz0);
            ng = tanhf(accd[0][mt][j][0] + bni0 + rg * (accd[1][mt][j][0] + bnh0));
            float o0 = (1.f - zg) * ng + zg * hpA.x;

            rg = sigf(acc[mt][j][1] + br1);
            zg = sigf(acc[mt][2 + j][1] + bz1);
            ng = tanhf(accd[0][mt][j][1] + bni1 + rg * (accd[1][mt][j][1] + bnh1));
            float o1 = (1.f - zg) * ng + zg * hpA.y;

            rg = sigf(acc[mt][j][2] + br0);
            zg = sigf(acc[mt][2 + j][2] + bz0);
            ng = tanhf(accd[0][mt][j][2] + bni0 + rg * (accd[1][mt][j][2] + bnh0));
            float o2 = (1.f - zg) * ng + zg * hpB.x;

            rg = sigf(acc[mt][j][3] + br1);
            zg = sigf(acc[mt][2 + j][3] + bz1);
            ng = tanhf(accd[0][mt][j][3] + bni1 + rg * (accd[1][mt][j][3] + bnh1));
            float o3 = (1.f - zg) * ng + zg * hpB.y;

            *(float2*)(hh_out + rA * 256 + c) = make_float2(o0, o1);
            *(float2*)(hh_out + rB * 256 + c) = make_float2(o2, o3);
        }
    }
}

// ---------------------------------------------------------------------------
// k3: LayerNorm + fc2 — dual-row warps (2 independent shuffle chains for ILP)
// ---------------------------------------------------------------------------
__global__ void __launch_bounds__(256) k3_ln_fc2(
    const float* __restrict__ hh, const float* __restrict__ lng,
    const float* __restrict__ lnb, const float* __restrict__ W2,
    const float* __restrict__ b2, float* __restrict__ q, int nrows)
{
    int warp = (blockIdx.x * blockDim.x + threadIdx.x) >> 5;
    int lane = threadIdx.x & 31;
    size_t rA = (size_t)warp * 2;
    if (rA >= (size_t)nrows) return;
    size_t rB = rA + 1;
    const float* hA = hh + rA * RDIM;
    const float* hB = hh + rB * RDIM;

    float vA[8], vB[8];
    float sA = 0.f, sB = 0.f;
    #pragma unroll
    for (int i = 0; i < 8; ++i) {
        vA[i] = hA[lane + 32 * i]; sA += vA[i];
        vB[i] = hB[lane + 32 * i]; sB += vB[i];
    }
    #pragma unroll
    for (int o = 16; o; o >>= 1) {
        sA += __shfl_xor_sync(0xffffffffu, sA, o);
        sB += __shfl_xor_sync(0xffffffffu, sB, o);
    }
    float muA = sA * (1.f / 256.f), muB = sB * (1.f / 256.f);
    float qA = 0.f, qB = 0.f;
    #pragma unroll
    for (int i = 0; i < 8; ++i) {
        float dA = vA[i] - muA; qA += dA * dA;
        float dB = vB[i] - muB; qB += dB * dB;
    }
    #pragma unroll
    for (int o = 16; o; o >>= 1) {
        qA += __shfl_xor_sync(0xffffffffu, qA, o);
        qB += __shfl_xor_sync(0xffffffffu, qB, o);
    }
    float invA = rsqrtf(qA * (1.f / 256.f) + 1e-5f);
    float invB = rsqrtf(qB * (1.f / 256.f) + 1e-5f);

    float nA[8], nB[8];
    #pragma unroll
    for (int i = 0; i < 8; ++i) {
        float gg = lng[lane + 32 * i], bb = lnb[lane + 32 * i];
        nA[i] = (vA[i] - muA) * invA * gg + bb;
        nB[i] = (vB[i] - muB) * invB * gg + bb;
    }

    #pragma unroll
    for (int j = 0; j < NACT; ++j) {
        float pA = 0.f, pB = 0.f;
        #pragma unroll
        for (int i = 0; i < 8; ++i) {
            float w = W2[j * RDIM + lane + 32 * i];
            pA = fmaf(nA[i], w, pA);
            pB = fmaf(nB[i], w, pB);
        }
        #pragma unroll
        for (int o = 16; o; o >>= 1) {
            pA += __shfl_xor_sync(0xffffffffu, pA, o);
            pB += __shfl_xor_sync(0xffffffffu, pB, o);
        }
        if (lane == j) {
            q[rA * NACT + j] = pA + b2[j];
            q[rB * NACT + j] = pB + b2[j];
        }
    }
}

// ---------------------------------------------------------------------------
extern "C" void kernel_launch(void* const* d_in, const int* in_sizes, int n_in,
                              void* d_out, int out_size)
{
    const float* inputs = (const float*)d_in[0];
    const float* hidden = (const float*)d_in[1];
    const int*   mask   = (const int*)  d_in[2];
    const float* Wfc    = (const float*)d_in[3];
    const float* bfc    = (const float*)d_in[4];
    const float* Wh     = (const float*)d_in[5];
    const float* asrc   = (const float*)d_in[6];
    const float* adst   = (const float*)d_in[7];
    const float* Wo     = (const float*)d_in[8];
    const float* bo     = (const float*)d_in[9];
    const float* W1     = (const float*)d_in[10];
    const float* b1     = (const float*)d_in[11];
    const float* Wih    = (const float*)d_in[12];
    const float* Whh    = (const float*)d_in[13];
    const float* bih    = (const float*)d_in[14];
    const float* bhh    = (const float*)d_in[15];
    const float* lng    = (const float*)d_in[16];
    const float* lnb    = (const float*)d_in[17];
    const float* W2     = (const float*)d_in[18];
    const float* b2     = (const float*)d_in[19];

    const int B = in_sizes[0] / (AN * OBS);       // 4096
    const int nrows = B * AN;                     // 131072
    const int mblk = nrows / 128;                 // 1024

    float* q_out  = (float*)d_out;
    float* hh_out = (float*)d_out + (size_t)nrows * NACT;

    __half *bhh16buf, *inh, *xeh, *aggh, *atth, *xrh, *hinh;
    __half *wfch, *whth, *woth, *w1h, *wih16, *whh16;
    cudaGetSymbolAddress((void**)&bhh16buf, g_bufHh);
    cudaGetSymbolAddress((void**)&inh,   g_inh);
    cudaGetSymbolAddress((void**)&xeh,   g_xeh);
    cudaGetSymbolAddress((void**)&aggh,  g_aggh);
    cudaGetSymbolAddress((void**)&atth,  g_atth);
    cudaGetSymbolAddress((void**)&xrh,   g_xrh);
    cudaGetSymbolAddress((void**)&hinh,  g_hinh);
    cudaGetSymbolAddress((void**)&wfch,  g_Wfch);
    cudaGetSymbolAddress((void**)&whth,  g_WhTh);
    cudaGetSymbolAddress((void**)&woth,  g_WoTh);
    cudaGetSymbolAddress((void**)&w1h,   g_W1h);
    cudaGetSymbolAddress((void**)&wih16, g_Wih16);
    cudaGetSymbolAddress((void**)&whh16, g_Whh16);

    cudaFuncSetAttribute(kB_attn,    cudaFuncAttributeMaxDynamicSharedMemorySize, KB_SMEM);
    cudaFuncSetAttribute(k2_gru_f16, cudaFuncAttributeMaxDynamicSharedMemorySize, K2H_SMEM);
    cudaFuncSetAttribute(gemm_hn<128, 0, 1, 1>, cudaFuncAttributeMaxDynamicSharedMemorySize, GH_SMEM);
    cudaFuncSetAttribute(gemm_hn<64, 0, 0, 1>,  cudaFuncAttributeMaxDynamicSharedMemorySize, GH_SMEM);
    cudaFuncSetAttribute(gemm_hn<256, 0, 1, 1>, cudaFuncAttributeMaxDynamicSharedMemorySize, GH_SMEM);
    cudaFuncSetAttribute(gemm_hn<128, 64, 2, 1>,cudaFuncAttributeMaxDynamicSharedMemorySize, GH_SMEM);

    k0_prep<<<64, 256>>>(Wfc, Wh, Wo, W1, Wih, Whh,
                         wfch, whth, woth, w1h, wih16, whh16);
    kH_f2h<<<4096, 256>>>(hidden, (__half2*)hinh, nrows * RDIM / 4);
    kH_f2h<<<4096, 256>>>(inputs, (__half2*)inh,  nrows * OBS / 4);

    // G1: XE = inputs @ Wfc^T + bfc          [M,64] fp16
    gemm_hn<128, 0, 1, 1><<<dim3(1, mblk), 256, GH_SMEM>>>(inh, nullptr, wfch, bfc, xeh);
    // G2: H = XE @ WhT^T                     [M,256] fp16
    gemm_hn<64, 0, 0, 1><<<dim3(4, mblk), 256, GH_SMEM>>>(xeh, nullptr, whth, nullptr, bhh16buf);
    // attention (fp16 H in, fp16 agg out)
    kB_attn<<<B, 256, KB_SMEM>>>(bhh16buf, mask, asrc, adst, aggh);
    // G3: ATT = agg @ WoT^T + bo             [M,64] fp16
    gemm_hn<256, 0, 1, 1><<<dim3(1, mblk), 256, GH_SMEM>>>(aggh, nullptr, woth, bo, atth);
    // G4: XR = relu([inputs|ATT] @ W1^T+b1)  [M,256] fp16
    gemm_hn<128, 64, 2, 1><<<dim3(4, mblk), 256, GH_SMEM>>>(inh, atth, w1h, b1, xrh);
    // GRU (fp16 MMA pipeline, warp-local gates)
    k2_gru_f16<<<dim3(8, mblk), 256, K2H_SMEM>>>(xrh, hinh, hidden, wih16, whh16,
                                                 bih, bhh, hh_out);
    // LN + fc2 (dual-row warps)
    k3_ln_fc2<<<(nrows / 2 + 7) / 8, 256>>>(hh_out, lng, lnb, W2, b2, q_out, nrows);
}

// round 15
// speedup vs baseline: 1.3044x; 1.0104x over previous
#include <cuda_runtime.h>
#include <cuda_fp16.h>
#include <cuda_bf16.h>
#include <stdint.h>

// Problem constants
#define AN   32
#define OBS  128
#define EDIM 64
#define DDIM 64
#define HHEADS 4
#define RDIM 256
#define NACT 16
#define ZDIM 192
#define MAXROWS (4096*32)

// Scratch buffers
__device__ __align__(16) __half g_bufHh[MAXROWS * RDIM];  // H fp16
__device__ __align__(16) __half g_inh  [MAXROWS * OBS];   // inputs fp16
__device__ __align__(16) __half g_xeh  [MAXROWS * 64];    // XE fp16
__device__ __align__(16) __half g_aggh [MAXROWS * RDIM];  // agg fp16
__device__ __align__(16) __half g_atth [MAXROWS * 64];    // ATT fp16
__device__ __align__(16) __half g_xrh  [MAXROWS * RDIM];  // XR fp16
__device__ __align__(16) __half g_hinh [MAXROWS * RDIM];  // hidden fp16
__device__ __align__(16) __half g_Wfch [64 * OBS];
__device__ __align__(16) __half g_WhTh [256 * 64];
__device__ __align__(16) __half g_WoTh [64 * 256];
__device__ __align__(16) __half g_W1h  [RDIM * ZDIM];
__device__ __align__(16) __half g_Wih16[3 * RDIM * RDIM];
__device__ __align__(16) __half g_Whh16[3 * RDIM * RDIM];

__device__ __forceinline__ float sigf(float x) { return 1.0f / (1.0f + __expf(-x)); }

#define MMA_F16(d, a, b)                                                      \
    asm volatile(                                                             \
        "mma.sync.aligned.m16n8k16.row.col.f32.f16.f16.f32 "                  \
        "{%0,%1,%2,%3},{%4,%5,%6,%7},{%8,%9},{%0,%1,%2,%3};"                  \
        : "+f"(d[0]), "+f"(d[1]), "+f"(d[2]), "+f"(d[3])                      \
        : "r"(a[0]), "r"(a[1]), "r"(a[2]), "r"(a[3]), "r"(b[0]), "r"(b[1]))

#define LDSM_X4(r, addr)                                                      \
    asm volatile(                                                             \
        "ldmatrix.sync.aligned.m8n8.x4.shared.b16 {%0,%1,%2,%3}, [%4];"       \
        : "=r"((r)[0]), "=r"((r)[1]), "=r"((r)[2]), "=r"((r)[3])              \
        : "r"(addr))

__device__ __forceinline__ void cpa16(uint32_t dst, const void* src) {
    asm volatile("cp.async.cg.shared.global [%0], [%1], 16;"
                 :: "r"(dst), "l"(src));
}
#define CPA_COMMIT()  asm volatile("cp.async.commit_group;" ::: "memory")
#define CPA_WAIT(N)   asm volatile("cp.async.wait_group %0;" :: "n"(N) : "memory")

// ---------------------------------------------------------------------------
// k0: weight transposes + fp16 conversions
// ---------------------------------------------------------------------------
__global__ void k0_prep(const float* __restrict__ Wfc, const float* __restrict__ Wh,
                        const float* __restrict__ Wo, const float* __restrict__ W1,
                        const float* __restrict__ Wih, const float* __restrict__ Whh,
                        __half* __restrict__ Wfch, __half* __restrict__ WhTh,
                        __half* __restrict__ WoTh, __half* __restrict__ W1h,
                        __half* __restrict__ Wih16, __half* __restrict__ Whh16)
{
    int tid = blockIdx.x * blockDim.x + threadIdx.x;
    int stride = gridDim.x * blockDim.x;
    for (int i = tid; i < 64 * OBS; i += stride) Wfch[i] = __float2half(Wfc[i]);
    for (int i = tid; i < 256 * 64; i += stride) {
        int n = i >> 6, e = i & 63;
        int h = n >> 6, d = n & 63;
        WhTh[i] = __float2half(Wh[(h * 64 + e) * 64 + d]);
    }
    for (int i = tid; i < 64 * 256; i += stride) {
        int e = i >> 8, k = i & 255;
        WoTh[i] = __float2half(Wo[k * 64 + e]);
    }
    for (int i = tid; i < RDIM * ZDIM; i += stride) W1h[i] = __float2half(W1[i]);
    for (int i = tid; i < 3 * 256 * 256; i += stride) {
        Wih16[i] = __float2half(Wih[i]);
        Whh16[i] = __float2half(Whh[i]);
    }
}

// ---------------------------------------------------------------------------
// kH: fused fp32 -> fp16 conversion for hidden AND inputs in one launch
// ---------------------------------------------------------------------------
__global__ void kH_f2h2(const float* __restrict__ inA, __half2* __restrict__ outA, int n4A,
                        const float* __restrict__ inB, __half2* __restrict__ outB, int n4B)
{
    int i = blockIdx.x * blockDim.x + threadIdx.x;
    int stride = gridDim.x * blockDim.x;
    int total = n4A + n4B;
    for (; i < total; i += stride) {
        if (i < n4A) {
            float4 v = ((const float4*)inA)[i];
            outA[2 * i]     = __floats2half2_rn(v.x, v.y);
            outA[2 * i + 1] = __floats2half2_rn(v.z, v.w);
        } else {
            int j = i - n4A;
            float4 v = ((const float4*)inB)[j];
            outB[2 * j]     = __floats2half2_rn(v.x, v.y);
            outB[2 * j + 1] = __floats2half2_rn(v.z, v.w);
        }
    }
}

// ---------------------------------------------------------------------------
// Generic fp16 GEMM (k2-proven layout) — unchanged from R12
// ---------------------------------------------------------------------------
#define GH_STAGEB (128*80 + 64*80)       // 15360 B per stage
#define GH_SMEM   (3 * GH_STAGEB)        // 46080 B

template<int K1, int K2, int EPI, int OUTH>
__global__ void __launch_bounds__(256, 2) gemm_hn(
    const __half* __restrict__ A1, const __half* __restrict__ A2,
    const __half* __restrict__ W,  const float* __restrict__ bias,
    void* __restrict__ Cout)
{
    constexpr int KT = K1 + K2;
    constexpr int NS = KT / 32;
    extern __shared__ __half smh[];
    const uint32_t sbase = (uint32_t)__cvta_generic_to_shared(smh);

    const int tid  = threadIdx.x;
    const int lane = tid & 31;
    const int warp = tid >> 5;
    const int wm = (warp & 3) * 32;
    const int wn = (warp >> 2) * 32;
    const int g  = lane >> 2;
    const int tg = lane & 3;
    const size_t r0 = (size_t)blockIdx.y * 128;
    const int n0 = blockIdx.x * 64;
    const int ldc = gridDim.x * 64;

    const int mA = tid >> 2;
    const int jA = tid & 3;
    const uint32_t adst0 = (uint32_t)(mA * 80 + jA * 16);
    const uint32_t adst1 = (uint32_t)((mA + 64) * 80 + jA * 16);
    const int nB = tid >> 2;
    const uint32_t bdst = (uint32_t)(10240 + nB * 80 + jA * 16);

    auto issue = [&](int s) {
        const int buf = s % 3;
        const int kb  = s * 32;
        const uint32_t sb = sbase + (uint32_t)(buf * GH_STAGEB);
        const int kh = jA * 8;
        if (K2 == 0 || kb < K1) {
            const __half* src = A1 + (size_t)(r0 + mA) * K1 + kb + kh;
            cpa16(sb + adst0, src);
            cpa16(sb + adst1, src + (size_t)64 * K1);
        } else {
            const __half* src = A2 + (size_t)(r0 + mA) * K2 + (kb - K1) + kh;
            cpa16(sb + adst0, src);
            cpa16(sb + adst1, src + (size_t)64 * K2);
        }
        cpa16(sb + bdst, W + (size_t)(n0 + nB) * KT + kb + kh);
        CPA_COMMIT();
    };

    const int l7 = lane & 7;
    const int aRow = ((lane >> 3) & 1) * 8 + l7;
    const int aKb  = (lane >> 4) * 16;
    const uint32_t aAddr = sbase + (uint32_t)((wm + aRow) * 80 + aKb);
    const int bRow = ((lane >> 4) & 1) * 8 + l7;
    const int bKb  = ((lane >> 3) & 1) * 16;
    const uint32_t bAddr = sbase + (uint32_t)(10240 + (wn + bRow) * 80 + bKb);

    float acc[2][4][4];
    #pragma unroll
    for (int mt = 0; mt < 2; ++mt)
        #pragma unroll
        for (int nt = 0; nt < 4; ++nt)
            #pragma unroll
            for (int e = 0; e < 4; ++e) acc[mt][nt][e] = 0.f;

    auto compute = [&](int buf) {
        const uint32_t bufoff = (uint32_t)(buf * GH_STAGEB);
        #pragma unroll
        for (int ks = 0; ks < 2; ++ks) {
            const uint32_t ko = bufoff + ks * 32;
            uint32_t a[2][4];
            LDSM_X4(a[0], aAddr + ko);
            LDSM_X4(a[1], aAddr + ko + 16 * 80);
            uint32_t bf[4][2];
            #pragma unroll
            for (int p = 0; p < 2; ++p) {
                uint32_t t[4];
                LDSM_X4(t, bAddr + ko + p * 16 * 80);
                bf[2 * p][0]     = t[0];
                bf[2 * p][1]     = t[1];
                bf[2 * p + 1][0] = t[2];
                bf[2 * p + 1][1] = t[3];
            }
            #pragma unroll
            for (int mt = 0; mt < 2; ++mt)
                #pragma unroll
                for (int nt = 0; nt < 4; ++nt)
                    MMA_F16(acc[mt][nt], a[mt], bf[nt]);
        }
    };

    issue(0);
    if (NS > 1) issue(1);
    CPA_WAIT(1);
    __syncthreads();

    #pragma unroll 1
    for (int s = 0; s < NS; ++s) {
        compute(s % 3);
        if (s + 2 < NS) { issue(s + 2); CPA_WAIT(1); }
        else            { CPA_WAIT(0); }
        __syncthreads();
    }

    #pragma unroll
    for (int mt = 0; mt < 2; ++mt) {
        #pragma unroll
        for (int nt = 0; nt < 4; ++nt) {
            size_t r = r0 + wm + mt * 16 + g;
            int    c = n0 + wn + nt * 8 + tg * 2;
            float v0 = acc[mt][nt][0], v1 = acc[mt][nt][1];
            float v2 = acc[mt][nt][2], v3 = acc[mt][nt][3];
            if (EPI >= 1) {
                float b0 = bias[c], b1 = bias[c + 1];
                v0 += b0; v1 += b1; v2 += b0; v3 += b1;
            }
            if (EPI == 2) {
                v0 = fmaxf(v0, 0.f); v1 = fmaxf(v1, 0.f);
                v2 = fmaxf(v2, 0.f); v3 = fmaxf(v3, 0.f);
            }
            if (OUTH) {
                __half* Ch = (__half*)Cout;
                *(__half2*)(Ch + r * ldc + c)       = __floats2half2_rn(v0, v1);
                *(__half2*)(Ch + (r + 8) * ldc + c) = __floats2half2_rn(v2, v3);
            } else {
                float* C = (float*)Cout;
                *(float2*)(C + r * ldc + c)       = make_float2(v0, v1);
                *(float2*)(C + (r + 8) * ldc + c) = make_float2(v2, v3);
            }
        }
    }
}

// ---------------------------------------------------------------------------
// kB: per-batch masked attention — unchanged from proven R13
// ---------------------------------------------------------------------------
#define KB_HS    0
#define KB_ALPHA 8224
#define KB_SSRC  (KB_ALPHA + 4*32*33)
#define KB_SDST  (KB_SSRC + 128)
#define KB_SAS   (KB_SDST + 128)
#define KB_SAD   (KB_SAS + 256)
#define KB_MSK   (KB_SAD + 256)
#define KB_SMEM  ((KB_MSK + 32*33) * 4)  // 57088 B

__global__ void __launch_bounds__(256) kB_attn(
    const __half* __restrict__ H, const int* __restrict__ mask,
    const float* __restrict__ asrc, const float* __restrict__ adst,
    __half* __restrict__ agg)
{
    extern __shared__ float smf[];
    float* Hs    = smf + KB_HS;
    float* alpha = smf + KB_ALPHA;
    float* ssrc  = smf + KB_SSRC;
    float* sdst  = smf + KB_SDST;
    float* sas   = smf + KB_SAS;
    float* sad   = smf + KB_SAD;
    int*   msk   = (int*)(smf + KB_MSK);

    const int tid  = threadIdx.x;
    const int lane = tid & 31;
    const int warp = tid >> 5;
    const int b    = blockIdx.x;

    const __half2* Hb2 = (const __half2*)(H + (size_t)b * (32 * 256));
    for (int i = tid; i < 32 * 128; i += 256) {
        int a = i >> 7, c2 = i & 127;
        float2 v = __half22float2(Hb2[i]);
        Hs[a * 257 + 2 * c2]     = v.x;
        Hs[a * 257 + 2 * c2 + 1] = v.y;
    }
    for (int i = tid; i < 256; i += 256) { sas[i] = asrc[i]; sad[i] = adst[i]; }
    for (int i = tid; i < 32 * 32; i += 256) {
        int r = i >> 5, c = i & 31;
        msk[r * 33 + c] = mask[(size_t)b * (32 * 32) + i];
    }
    __syncthreads();

    if (warp < 4) {
        int hd = warp;
        float vs = 0.f, vd = 0.f;
        const float* hr = Hs + lane * 257 + hd * 64;
        #pragma unroll
        for (int d = 0; d < 64; ++d) {
            float h = hr[d];
            vs = fmaf(h, sas[hd * 64 + d], vs);
            vd = fmaf(h, sad[hd * 64 + d], vd);
        }
        ssrc[hd * 32 + lane] = vs;
        sdst[hd * 32 + lane] = vd;
    }
    __syncthreads();

    if (tid < 128) {
        int hd = tid >> 5, i = tid & 31;
        float si = ssrc[hd * 32 + i];
        float v[32];
        float m = -3.4e38f;
        #pragma unroll
        for (int j = 0; j < 32; ++j) {
            float e_ = si + sdst[hd * 32 + j];
            float l  = e_ > 0.f ? e_ : 0.2f * e_;
            if (msk[i * 33 + j] <= 0) l = -1e9f;
            v[j] = l; m = fmaxf(m, l);
        }
        float s = 0.f;
        #pragma unroll
        for (int j = 0; j < 32; ++j) { v[j] = __expf(v[j] - m); s += v[j]; }
        float inv = 1.f / s;
        #pragma unroll
        for (int j = 0; j < 32; ++j) alpha[(hd * 32 + i) * 33 + j] = v[j] * inv;
    }
    __syncthreads();

    {
        float v[32];
        #pragma unroll
        for (int j = 0; j < 32; ++j) v[j] = Hs[j * 257 + tid];
        const int hd = tid >> 6;
        __half* aggb = agg + (size_t)b * (32 * 256);
        #pragma unroll 4
        for (int a = 0; a < 32; ++a) {
            const float* al = alpha + (hd * 32 + a) * 33;
            float s = 0.f;
            #pragma unroll
            for (int j = 0; j < 32; ++j) s = fmaf(al[j], v[j], s);
            aggb[a * 256 + tid] = __float2half(s);
        }
    }
}

// ---------------------------------------------------------------------------
// k2: GRU via fp16 MMA — R9 structure, 4-buffer pipeline (WAIT(2)),
// hprev read from fp16 hinh (hin fp32 no longer needed).
// ---------------------------------------------------------------------------
#define K2H_STAGEB 17920
#define K2H_SMEM   (4 * K2H_STAGEB)      // 71680 B

__global__ void __launch_bounds__(256, 2) k2_gru_f16(
    const __half* __restrict__ xrh,  const __half* __restrict__ hinh,
    const __half* __restrict__ Wih,  const __half* __restrict__ Whh,
    const float*  __restrict__ bih,  const float*  __restrict__ bhh,
    float* __restrict__ hh_out)
{
    extern __shared__ __half smh[];
    const uint32_t sbase = (uint32_t)__cvta_generic_to_shared(smh);

    const int tid  = threadIdx.x;
    const int lane = tid & 31;
    const int warp = tid >> 5;
    const int wm  = (warp & 3) * 32;
    const int wn  = (warp >> 2) * 48;
    const int g   = lane >> 2;
    const int tg  = lane & 3;
    const size_t r0 = (size_t)blockIdx.y * 128;
    const int c0 = blockIdx.x * 32;

    const int mA = tid >> 2;
    const int jA = tid & 3;
    const size_t aoff0 = (r0 + mA) * 256 + jA * 8;
    const size_t aoff1 = (r0 + mA + 64) * 256 + jA * 8;
    const uint32_t adst0 = (uint32_t)(mA * 80 + jA * 16);
    const uint32_t adst1 = (uint32_t)((mA + 64) * 80 + jA * 16);
    auto wrow_of = [&](int n) {
        int grp = n >> 4, cl = n & 15;
        return (grp % 3) * 256 + c0 + (grp / 3) * 16 + cl;
    };
    const int nB0 = tid >> 2;
    const int jB = tid & 3;
    const size_t boff0 = (size_t)wrow_of(nB0) * 256 + jB * 8;
    const size_t boff1 = (size_t)wrow_of(nB0 + 64) * 256 + jB * 8;
    const uint32_t bdst0 = (uint32_t)(10240 + nB0 * 80 + jB * 16);
    const uint32_t bdst1 = (uint32_t)(10240 + (nB0 + 64) * 80 + jB * 16);

    auto issue = [&](int s) {
        const int buf = s & 3;
        const int kloc = (s & 7) * 32;
        const __half* Asrc = (s < 8) ? xrh : hinh;
        const __half* Wsrc = (s < 8) ? Wih : Whh;
        const uint32_t sb = sbase + (uint32_t)(buf * K2H_STAGEB);
        cpa16(sb + adst0, Asrc + aoff0 + kloc);
        cpa16(sb + adst1, Asrc + aoff1 + kloc);
        cpa16(sb + bdst0, Wsrc + boff0 + kloc);
        if (tid < 128) cpa16(sb + bdst1, Wsrc + boff1 + kloc);
        CPA_COMMIT();
    };

    const int l7 = lane & 7;
    const int aRow = ((lane >> 3) & 1) * 8 + l7;
    const int aKb  = (lane >> 4) * 16;
    const uint32_t aAddr = sbase + (uint32_t)((wm + aRow) * 80 + aKb);
    const int bRow = ((lane >> 4) & 1) * 8 + l7;
    const int bKb  = ((lane >> 3) & 1) * 16;
    const uint32_t bAddr = sbase + (uint32_t)(10240 + (wn + bRow) * 80 + bKb);

    float acc [2][4][4];
    float accd[2][2][2][4];
    #pragma unroll
    for (int mt = 0; mt < 2; ++mt) {
        #pragma unroll
        for (int nt = 0; nt < 4; ++nt)
            #pragma unroll
            for (int e = 0; e < 4; ++e) acc[mt][nt][e] = 0.f;
        #pragma unroll
        for (int p = 0; p < 2; ++p)
            #pragma unroll
            for (int j = 0; j < 2; ++j)
                #pragma unroll
                for (int e = 0; e < 4; ++e) accd[p][mt][j][e] = 0.f;
    }

    auto compute = [&](int buf, int ph) {
        const uint32_t bufoff = (uint32_t)(buf * K2H_STAGEB);
        #pragma unroll
        for (int ks = 0; ks < 2; ++ks) {
            const uint32_t ko = bufoff + ks * 32;
            uint32_t a[2][4];
            LDSM_X4(a[0], aAddr + ko);
            LDSM_X4(a[1], aAddr + ko + 16 * 80);
            uint32_t bf[6][2];
            #pragma unroll
            for (int p = 0; p < 3; ++p) {
                uint32_t t[4];
                LDSM_X4(t, bAddr + ko + p * 16 * 80);
                bf[2 * p][0]     = t[0];
                bf[2 * p][1]     = t[1];
                bf[2 * p + 1][0] = t[2];
                bf[2 * p + 1][1] = t[3];
            }
            #pragma unroll
            for (int mt = 0; mt < 2; ++mt) {
                #pragma unroll
                for (int nt = 0; nt < 4; ++nt)
                    MMA_F16(acc[mt][nt], a[mt], bf[nt]);
                #pragma unroll
                for (int j = 0; j < 2; ++j) {
                    if (ph == 0) { MMA_F16(accd[0][mt][j], a[mt], bf[4 + j]); }
                    else         { MMA_F16(accd[1][mt][j], a[mt], bf[4 + j]); }
                }
            }
        }
    };

    // 4-buffer pipeline: 3 stages in flight, WAIT(2)
    issue(0);
    issue(1);
    issue(2);
    CPA_WAIT(2);
    __syncthreads();

    int s = 0;
    #pragma unroll 1
    for (; s < 8; ++s) {
        compute(s & 3, 0);
        if (s + 3 < 16) { issue(s + 3); CPA_WAIT(2); }
        else if (s + 2 < 16) { CPA_WAIT(1); }
        else { CPA_WAIT(0); }
        __syncthreads();
    }
    #pragma unroll 1
    for (; s < 16; ++s) {
        compute(s & 3, 1);
        if (s + 3 < 16) { issue(s + 3); CPA_WAIT(2); }
        else if (s + 2 < 16) { CPA_WAIT(1); }
        else { CPA_WAIT(0); }
        __syncthreads();
    }

    // epilogue: gates in registers; hprev from fp16 hinh
    const int colbase = c0 + (wn ? 16 : 0);
    #pragma unroll
    for (int mt = 0; mt < 2; ++mt) {
        const size_t rA = r0 + wm + mt * 16 + g;
        const size_t rB = rA + 8;
        #pragma unroll
        for (int j = 0; j < 2; ++j) {
            const int c = colbase + j * 8 + tg * 2;
            const float br0  = bih[c]       + bhh[c];
            const float br1  = bih[c + 1]   + bhh[c + 1];
            const float bz0  = bih[256 + c] + bhh[256 + c];
            const float bz1  = bih[257 + c] + bhh[257 + c];
            const float bni0 = bih[512 + c],  bni1 = bih[513 + c];
            const float bnh0 = bhh[512 + c],  bnh1 = bhh[513 + c];
            const float2 hpA = __half22float2(*(const __half2*)(hinh + rA * 256 + c));
            const float2 hpB = __half22float2(*(const __half2*)(hinh + rB * 256 + c));

            float rg, zg, ng;
            rg = sigf(acc[mt][j][0] + br0);
            zg = sigf(acc[mt][2 + j][0] + bz0);
            ng = tanhf(accd[0][mt][j][0] + bni0 + rg * (accd[1][mt][j][0] + bnh0));
            float o0 = (1.f - zg) * ng + zg * hpA.x;

            rg = sigf(acc[mt][j][1] + br1);
            zg = sigf(acc[mt][2 + j][1] + bz1);
            ng = tanhf(accd[0][mt][j][1] + bni1 + rg * (accd[1][mt][j][1] + bnh1));
            float o1 = (1.f - zg) * ng + zg * hpA.y;

            rg = sigf(acc[mt][j][2] + br0);
            zg = sigf(acc[mt][2 + j][2] + bz0);
            ng = tanhf(accd[0][mt][j][2] + bni0 + rg * (accd[1][mt][j][2] + bnh0));
            float o2 = (1.f - zg) * ng + zg * hpB.x;

            rg = sigf(acc[mt][j][3] + br1);
            zg = sigf(acc[mt][2 + j][3] + bz1);
            ng = tanhf(accd[0][mt][j][3] + bni1 + rg * (accd[1][mt][j][3] + bnh1));
            float o3 = (1.f - zg) * ng + zg * hpB.y;

            *(float2*)(hh_out + rA * 256 + c) = make_float2(o0, o1);
            *(float2*)(hh_out + rB * 256 + c) = make_float2(o2, o3);
        }
    }
}

// ---------------------------------------------------------------------------
// k3: LayerNorm + fc2 — dual-row warps (proven R13)
// ---------------------------------------------------------------------------
__global__ void __launch_bounds__(256) k3_ln_fc2(
    const float* __restrict__ hh, const float* __restrict__ lng,
    const float* __restrict__ lnb, const float* __restrict__ W2,
    const float* __restrict__ b2, float* __restrict__ q, int nrows)
{
    int warp = (blockIdx.x * blockDim.x + threadIdx.x) >> 5;
    int lane = threadIdx.x & 31;
    size_t rA = (size_t)warp * 2;
    if (rA >= (size_t)nrows) return;
    size_t rB = rA + 1;
    const float* hA = hh + rA * RDIM;
    const float* hB = hh + rB * RDIM;

    float vA[8], vB[8];
    float sA = 0.f, sB = 0.f;
    #pragma unroll
    for (int i = 0; i < 8; ++i) {
        vA[i] = hA[lane + 32 * i]; sA += vA[i];
        vB[i] = hB[lane + 32 * i]; sB += vB[i];
    }
    #pragma unroll
    for (int o = 16; o; o >>= 1) {
        sA += __shfl_xor_sync(0xffffffffu, sA, o);
        sB += __shfl_xor_sync(0xffffffffu, sB, o);
    }
    float muA = sA * (1.f / 256.f), muB = sB * (1.f / 256.f);
    float qA = 0.f, qB = 0.f;
    #pragma unroll
    for (int i = 0; i < 8; ++i) {
        float dA = vA[i] - muA; qA += dA * dA;
        float dB = vB[i] - muB; qB += dB * dB;
    }
    #pragma unroll
    for (int o = 16; o; o >>= 1) {
        qA += __shfl_xor_sync(0xffffffffu, qA, o);
        qB += __shfl_xor_sync(0xffffffffu, qB, o);
    }
    float invA = rsqrtf(qA * (1.f / 256.f) + 1e-5f);
    float invB = rsqrtf(qB * (1.f / 256.f) + 1e-5f);

    float nA[8], nB[8];
    #pragma unroll
    for (int i = 0; i < 8; ++i) {
        float gg = lng[lane + 32 * i], bb = lnb[lane + 32 * i];
        nA[i] = (vA[i] - muA) * invA * gg + bb;
        nB[i] = (vB[i] - muB) * invB * gg + bb;
    }

    #pragma unroll
    for (int j = 0; j < NACT; ++j) {
        float pA = 0.f, pB = 0.f;
        #pragma unroll
        for (int i = 0; i < 8; ++i) {
            float w = W2[j * RDIM + lane + 32 * i];
            pA = fmaf(nA[i], w, pA);
            pB = fmaf(nB[i], w, pB);
        }
        #pragma unroll
        for (int o = 16; o; o >>= 1) {
            pA += __shfl_xor_sync(0xffffffffu, pA, o);
            pB += __shfl_xor_sync(0xffffffffu, pB, o);
        }
        if (lane == j) {
            q[rA * NACT + j] = pA + b2[j];
            q[rB * NACT + j] = pB + b2[j];
        }
    }
}

// ---------------------------------------------------------------------------
extern "C" void kernel_launch(void* const* d_in, const int* in_sizes, int n_in,
                              void* d_out, int out_size)
{
    const float* inputs = (const float*)d_in[0];
    const float* hidden = (const float*)d_in[1];
    const int*   mask   = (const int*)  d_in[2];
    const float* Wfc    = (const float*)d_in[3];
    const float* bfc    = (const float*)d_in[4];
    const float* Wh     = (const float*)d_in[5];
    const float* asrc   = (const float*)d_in[6];
    const float* adst   = (const float*)d_in[7];
    const float* Wo     = (const float*)d_in[8];
    const float* bo     = (const float*)d_in[9];
    const float* W1     = (const float*)d_in[10];
    const float* b1     = (const float*)d_in[11];
    const float* Wih    = (const float*)d_in[12];
    const float* Whh    = (const float*)d_in[13];
    const float* bih    = (const float*)d_in[14];
    const float* bhh    = (const float*)d_in[15];
    const float* lng    = (const float*)d_in[16];
    const float* lnb    = (const float*)d_in[17];
    const float* W2     = (const float*)d_in[18];
    const float* b2     = (const float*)d_in[19];

    const int B = in_sizes[0] / (AN * OBS);       // 4096
    const int nrows = B * AN;                     // 131072
    const int mblk = nrows / 128;                 // 1024

    float* q_out  = (float*)d_out;
    float* hh_out = (float*)d_out + (size_t)nrows * NACT;

    __half *bhh16buf, *inh, *xeh, *aggh, *atth, *xrh, *hinh;
    __half *wfch, *whth, *woth, *w1h, *wih16, *whh16;
    cudaGetSymbolAddress((void**)&bhh16buf, g_bufHh);
    cudaGetSymbolAddress((void**)&inh,   g_inh);
    cudaGetSymbolAddress((void**)&xeh,   g_xeh);
    cudaGetSymbolAddress((void**)&aggh,  g_aggh);
    cudaGetSymbolAddress((void**)&atth,  g_atth);
    cudaGetSymbolAddress((void**)&xrh,   g_xrh);
    cudaGetSymbolAddress((void**)&hinh,  g_hinh);
    cudaGetSymbolAddress((void**)&wfch,  g_Wfch);
    cudaGetSymbolAddress((void**)&whth,  g_WhTh);
    cudaGetSymbolAddress((void**)&woth,  g_WoTh);
    cudaGetSymbolAddress((void**)&w1h,   g_W1h);
    cudaGetSymbolAddress((void**)&wih16, g_Wih16);
    cudaGetSymbolAddress((void**)&whh16, g_Whh16);

    cudaFuncSetAttribute(kB_attn,    cudaFuncAttributeMaxDynamicSharedMemorySize, KB_SMEM);
    cudaFuncSetAttribute(k2_gru_f16, cudaFuncAttributeMaxDynamicSharedMemorySize, K2H_SMEM);
    cudaFuncSetAttribute(gemm_hn<128, 0, 1, 1>, cudaFuncAttributeMaxDynamicSharedMemorySize, GH_SMEM);
    cudaFuncSetAttribute(gemm_hn<64, 0, 0, 1>,  cudaFuncAttributeMaxDynamicSharedMemorySize, GH_SMEM);
    cudaFuncSetAttribute(gemm_hn<256, 0, 1, 1>, cudaFuncAttributeMaxDynamicSharedMemorySize, GH_SMEM);
    cudaFuncSetAttribute(gemm_hn<128, 64, 2, 1>,cudaFuncAttributeMaxDynamicSharedMemorySize, GH_SMEM);

    k0_prep<<<64, 256>>>(Wfc, Wh, Wo, W1, Wih, Whh,
                         wfch, whth, woth, w1h, wih16, whh16);
    // fused fp32->fp16 conversions (hidden + inputs) in one launch
    kH_f2h2<<<4096, 256>>>(hidden, (__half2*)hinh, nrows * RDIM / 4,
                           inputs, (__half2*)inh,  nrows * OBS / 4);

    // G1: XE = inputs @ Wfc^T + bfc          [M,64] fp16
    gemm_hn<128, 0, 1, 1><<<dim3(1, mblk), 256, GH_SMEM>>>(inh, nullptr, wfch, bfc, xeh);
    // G2: H = XE @ WhT^T                     [M,256] fp16
    gemm_hn<64, 0, 0, 1><<<dim3(4, mblk), 256, GH_SMEM>>>(xeh, nullptr, whth, nullptr, bhh16buf);
    // attention (fp16 H in, fp16 agg out)
    kB_attn<<<B, 256, KB_SMEM>>>(bhh16buf, mask, asrc, adst, aggh);
    // G3: ATT = agg @ WoT^T + bo             [M,64] fp16
    gemm_hn<256, 0, 1, 1><<<dim3(1, mblk), 256, GH_SMEM>>>(aggh, nullptr, woth, bo, atth);
    // G4: XR = relu([inputs|ATT] @ W1^T+b1)  [M,256] fp16
    gemm_hn<128, 64, 2, 1><<<dim3(4, mblk), 256, GH_SMEM>>>(inh, atth, w1h, b1, xrh);
    // GRU (fp16 MMA, 4-buffer pipeline, fp16 hprev)
    k2_gru_f16<<<dim3(8, mblk), 256, K2H_SMEM>>>(xrh, hinh, wih16, whh16,
                                                 bih, bhh, hh_out);
    // LN + fc2 (dual-row warps)
    k3_ln_fc2<<<(nrows / 2 + 7) / 8, 256>>>(hh_out, lng, lnb, W2, b2, q_out, nrows);
}

// round 16
// speedup vs baseline: 1.3243x; 1.0153x over previous
#include <cuda_runtime.h>
#include <cuda_fp16.h>
#include <cuda_bf16.h>
#include <stdint.h>

// Problem constants
#define AN   32
#define OBS  128
#define EDIM 64
#define DDIM 64
#define HHEADS 4
#define RDIM 256
#define NACT 16
#define ZDIM 192
#define MAXROWS (4096*32)

// Scratch buffers
__device__ __align__(16) __half g_bufHh[MAXROWS * RDIM];  // H fp16
__device__ __align__(16) __half g_inh  [MAXROWS * OBS];   // inputs fp16
__device__ __align__(16) __half g_xeh  [MAXROWS * 64];    // XE fp16
__device__ __align__(16) __half g_aggh [MAXROWS * RDIM];  // agg fp16
__device__ __align__(16) __half g_atth [MAXROWS * 64];    // ATT fp16
__device__ __align__(16) __half g_xrh  [MAXROWS * RDIM];  // XR fp16
__device__ __align__(16) __half g_hinh [MAXROWS * RDIM];  // hidden fp16
__device__ __align__(16) __half g_Wfch [64 * OBS];
__device__ __align__(16) __half g_WhTh [256 * 64];
__device__ __align__(16) __half g_WoTh [64 * 256];
__device__ __align__(16) __half g_W1h  [RDIM * ZDIM];
__device__ __align__(16) __half g_Wih16[3 * RDIM * RDIM];
__device__ __align__(16) __half g_Whh16[3 * RDIM * RDIM];

__device__ __forceinline__ float sigf(float x) { return 1.0f / (1.0f + __expf(-x)); }

#define MMA_F16(d, a, b)                                                      \
    asm volatile(                                                             \
        "mma.sync.aligned.m16n8k16.row.col.f32.f16.f16.f32 "                  \
        "{%0,%1,%2,%3},{%4,%5,%6,%7},{%8,%9},{%0,%1,%2,%3};"                  \
        : "+f"(d[0]), "+f"(d[1]), "+f"(d[2]), "+f"(d[3])                      \
        : "r"(a[0]), "r"(a[1]), "r"(a[2]), "r"(a[3]), "r"(b[0]), "r"(b[1]))

#define LDSM_X4(r, addr)                                                      \
    asm volatile(                                                             \
        "ldmatrix.sync.aligned.m8n8.x4.shared.b16 {%0,%1,%2,%3}, [%4];"       \
        : "=r"((r)[0]), "=r"((r)[1]), "=r"((r)[2]), "=r"((r)[3])              \
        : "r"(addr))

__device__ __forceinline__ void cpa16(uint32_t dst, const void* src) {
    asm volatile("cp.async.cg.shared.global [%0], [%1], 16;"
                 :: "r"(dst), "l"(src));
}
#define CPA_COMMIT()  asm volatile("cp.async.commit_group;" ::: "memory")
#define CPA_WAIT(N)   asm volatile("cp.async.wait_group %0;" :: "n"(N) : "memory")

// ---------------------------------------------------------------------------
// k0: weight transposes + fp16 conversions
// ---------------------------------------------------------------------------
__global__ void k0_prep(const float* __restrict__ Wfc, const float* __restrict__ Wh,
                        const float* __restrict__ Wo, const float* __restrict__ W1,
                        const float* __restrict__ Wih, const float* __restrict__ Whh,
                        __half* __restrict__ Wfch, __half* __restrict__ WhTh,
                        __half* __restrict__ WoTh, __half* __restrict__ W1h,
                        __half* __restrict__ Wih16, __half* __restrict__ Whh16)
{
    int tid = blockIdx.x * blockDim.x + threadIdx.x;
    int stride = gridDim.x * blockDim.x;
    for (int i = tid; i < 64 * OBS; i += stride) Wfch[i] = __float2half(Wfc[i]);
    for (int i = tid; i < 256 * 64; i += stride) {
        int n = i >> 6, e = i & 63;
        int h = n >> 6, d = n & 63;
        WhTh[i] = __float2half(Wh[(h * 64 + e) * 64 + d]);
    }
    for (int i = tid; i < 64 * 256; i += stride) {
        int e = i >> 8, k = i & 255;
        WoTh[i] = __float2half(Wo[k * 64 + e]);
    }
    for (int i = tid; i < RDIM * ZDIM; i += stride) W1h[i] = __float2half(W1[i]);
    for (int i = tid; i < 3 * 256 * 256; i += stride) {
        Wih16[i] = __float2half(Wih[i]);
        Whh16[i] = __float2half(Whh[i]);
    }
}

// ---------------------------------------------------------------------------
// kH: fused fp32 -> fp16 conversion for hidden AND inputs in one launch
// ---------------------------------------------------------------------------
__global__ void kH_f2h2(const float* __restrict__ inA, __half2* __restrict__ outA, int n4A,
                        const float* __restrict__ inB, __half2* __restrict__ outB, int n4B)
{
    int i = blockIdx.x * blockDim.x + threadIdx.x;
    int stride = gridDim.x * blockDim.x;
    int total = n4A + n4B;
    for (; i < total; i += stride) {
        if (i < n4A) {
            float4 v = ((const float4*)inA)[i];
            outA[2 * i]     = __floats2half2_rn(v.x, v.y);
            outA[2 * i + 1] = __floats2half2_rn(v.z, v.w);
        } else {
            int j = i - n4A;
            float4 v = ((const float4*)inB)[j];
            outB[2 * j]     = __floats2half2_rn(v.x, v.y);
            outB[2 * j + 1] = __floats2half2_rn(v.z, v.w);
        }
    }
}

// ---------------------------------------------------------------------------
// Generic fp16 GEMM (k2-proven layout) — unchanged from R12
// ---------------------------------------------------------------------------
#define GH_STAGEB (128*80 + 64*80)       // 15360 B per stage
#define GH_SMEM   (3 * GH_STAGEB)        // 46080 B

template<int K1, int K2, int EPI, int OUTH>
__global__ void __launch_bounds__(256, 2) gemm_hn(
    const __half* __restrict__ A1, const __half* __restrict__ A2,
    const __half* __restrict__ W,  const float* __restrict__ bias,
    void* __restrict__ Cout)
{
    constexpr int KT = K1 + K2;
    constexpr int NS = KT / 32;
    extern __shared__ __half smh[];
    const uint32_t sbase = (uint32_t)__cvta_generic_to_shared(smh);

    const int tid  = threadIdx.x;
    const int lane = tid & 31;
    const int warp = tid >> 5;
    const int wm = (warp & 3) * 32;
    const int wn = (warp >> 2) * 32;
    const int g  = lane >> 2;
    const int tg = lane & 3;
    const size_t r0 = (size_t)blockIdx.y * 128;
    const int n0 = blockIdx.x * 64;
    const int ldc = gridDim.x * 64;

    const int mA = tid >> 2;
    const int jA = tid & 3;
    const uint32_t adst0 = (uint32_t)(mA * 80 + jA * 16);
    const uint32_t adst1 = (uint32_t)((mA + 64) * 80 + jA * 16);
    const int nB = tid >> 2;
    const uint32_t bdst = (uint32_t)(10240 + nB * 80 + jA * 16);

    auto issue = [&](int s) {
        const int buf = s % 3;
        const int kb  = s * 32;
        const uint32_t sb = sbase + (uint32_t)(buf * GH_STAGEB);
        const int kh = jA * 8;
        if (K2 == 0 || kb < K1) {
            const __half* src = A1 + (size_t)(r0 + mA) * K1 + kb + kh;
            cpa16(sb + adst0, src);
            cpa16(sb + adst1, src + (size_t)64 * K1);
        } else {
            const __half* src = A2 + (size_t)(r0 + mA) * K2 + (kb - K1) + kh;
            cpa16(sb + adst0, src);
            cpa16(sb + adst1, src + (size_t)64 * K2);
        }
        cpa16(sb + bdst, W + (size_t)(n0 + nB) * KT + kb + kh);
        CPA_COMMIT();
    };

    const int l7 = lane & 7;
    const int aRow = ((lane >> 3) & 1) * 8 + l7;
    const int aKb  = (lane >> 4) * 16;
    const uint32_t aAddr = sbase + (uint32_t)((wm + aRow) * 80 + aKb);
    const int bRow = ((lane >> 4) & 1) * 8 + l7;
    const int bKb  = ((lane >> 3) & 1) * 16;
    const uint32_t bAddr = sbase + (uint32_t)(10240 + (wn + bRow) * 80 + bKb);

    float acc[2][4][4];
    #pragma unroll
    for (int mt = 0; mt < 2; ++mt)
        #pragma unroll
        for (int nt = 0; nt < 4; ++nt)
            #pragma unroll
            for (int e = 0; e < 4; ++e) acc[mt][nt][e] = 0.f;

    auto compute = [&](int buf) {
        const uint32_t bufoff = (uint32_t)(buf * GH_STAGEB);
        #pragma unroll
        for (int ks = 0; ks < 2; ++ks) {
            const uint32_t ko = bufoff + ks * 32;
            uint32_t a[2][4];
            LDSM_X4(a[0], aAddr + ko);
            LDSM_X4(a[1], aAddr + ko + 16 * 80);
            uint32_t bf[4][2];
            #pragma unroll
            for (int p = 0; p < 2; ++p) {
                uint32_t t[4];
                LDSM_X4(t, bAddr + ko + p * 16 * 80);
                bf[2 * p][0]     = t[0];
                bf[2 * p][1]     = t[1];
                bf[2 * p + 1][0] = t[2];
                bf[2 * p + 1][1] = t[3];
            }
            #pragma unroll
            for (int mt = 0; mt < 2; ++mt)
                #pragma unroll
                for (int nt = 0; nt < 4; ++nt)
                    MMA_F16(acc[mt][nt], a[mt], bf[nt]);
        }
    };

    issue(0);
    if (NS > 1) issue(1);
    CPA_WAIT(1);
    __syncthreads();

    #pragma unroll 1
    for (int s = 0; s < NS; ++s) {
        compute(s % 3);
        if (s + 2 < NS) { issue(s + 2); CPA_WAIT(1); }
        else            { CPA_WAIT(0); }
        __syncthreads();
    }

    #pragma unroll
    for (int mt = 0; mt < 2; ++mt) {
        #pragma unroll
        for (int nt = 0; nt < 4; ++nt) {
            size_t r = r0 + wm + mt * 16 + g;
            int    c = n0 + wn + nt * 8 + tg * 2;
            float v0 = acc[mt][nt][0], v1 = acc[mt][nt][1];
            float v2 = acc[mt][nt][2], v3 = acc[mt][nt][3];
            if (EPI >= 1) {
                float b0 = bias[c], b1 = bias[c + 1];
                v0 += b0; v1 += b1; v2 += b0; v3 += b1;
            }
            if (EPI == 2) {
                v0 = fmaxf(v0, 0.f); v1 = fmaxf(v1, 0.f);
                v2 = fmaxf(v2, 0.f); v3 = fmaxf(v3, 0.f);
            }
            if (OUTH) {
                __half* Ch = (__half*)Cout;
                *(__half2*)(Ch + r * ldc + c)       = __floats2half2_rn(v0, v1);
                *(__half2*)(Ch + (r + 8) * ldc + c) = __floats2half2_rn(v2, v3);
            } else {
                float* C = (float*)Cout;
                *(float2*)(C + r * ldc + c)       = make_float2(v0, v1);
                *(float2*)(C + (r + 8) * ldc + c) = make_float2(v2, v3);
            }
        }
    }
}

// ---------------------------------------------------------------------------
// kB: per-batch masked attention — unchanged from proven R13
// ---------------------------------------------------------------------------
#define KB_HS    0
#define KB_ALPHA 8224
#define KB_SSRC  (KB_ALPHA + 4*32*33)
#define KB_SDST  (KB_SSRC + 128)
#define KB_SAS   (KB_SDST + 128)
#define KB_SAD   (KB_SAS + 256)
#define KB_MSK   (KB_SAD + 256)
#define KB_SMEM  ((KB_MSK + 32*33) * 4)  // 57088 B

__global__ void __launch_bounds__(256) kB_attn(
    const __half* __restrict__ H, const int* __restrict__ mask,
    const float* __restrict__ asrc, const float* __restrict__ adst,
    __half* __restrict__ agg)
{
    extern __shared__ float smf[];
    float* Hs    = smf + KB_HS;
    float* alpha = smf + KB_ALPHA;
    float* ssrc  = smf + KB_SSRC;
    float* sdst  = smf + KB_SDST;
    float* sas   = smf + KB_SAS;
    float* sad   = smf + KB_SAD;
    int*   msk   = (int*)(smf + KB_MSK);

    const int tid  = threadIdx.x;
    const int lane = tid & 31;
    const int warp = tid >> 5;
    const int b    = blockIdx.x;

    const __half2* Hb2 = (const __half2*)(H + (size_t)b * (32 * 256));
    for (int i = tid; i < 32 * 128; i += 256) {
        int a = i >> 7, c2 = i & 127;
        float2 v = __half22float2(Hb2[i]);
        Hs[a * 257 + 2 * c2]     = v.x;
        Hs[a * 257 + 2 * c2 + 1] = v.y;
    }
    for (int i = tid; i < 256; i += 256) { sas[i] = asrc[i]; sad[i] = adst[i]; }
    for (int i = tid; i < 32 * 32; i += 256) {
        int r = i >> 5, c = i & 31;
        msk[r * 33 + c] = mask[(size_t)b * (32 * 32) + i];
    }
    __syncthreads();

    if (warp < 4) {
        int hd = warp;
        float vs = 0.f, vd = 0.f;
        const float* hr = Hs + lane * 257 + hd * 64;
        #pragma unroll
        for (int d = 0; d < 64; ++d) {
            float h = hr[d];
            vs = fmaf(h, sas[hd * 64 + d], vs);
            vd = fmaf(h, sad[hd * 64 + d], vd);
        }
        ssrc[hd * 32 + lane] = vs;
        sdst[hd * 32 + lane] = vd;
    }
    __syncthreads();

    if (tid < 128) {
        int hd = tid >> 5, i = tid & 31;
        float si = ssrc[hd * 32 + i];
        float v[32];
        float m = -3.4e38f;
        #pragma unroll
        for (int j = 0; j < 32; ++j) {
            float e_ = si + sdst[hd * 32 + j];
            float l  = e_ > 0.f ? e_ : 0.2f * e_;
            if (msk[i * 33 + j] <= 0) l = -1e9f;
            v[j] = l; m = fmaxf(m, l);
        }
        float s = 0.f;
        #pragma unroll
        for (int j = 0; j < 32; ++j) { v[j] = __expf(v[j] - m); s += v[j]; }
        float inv = 1.f / s;
        #pragma unroll
        for (int j = 0; j < 32; ++j) alpha[(hd * 32 + i) * 33 + j] = v[j] * inv;
    }
    __syncthreads();

    {
        float v[32];
        #pragma unroll
        for (int j = 0; j < 32; ++j) v[j] = Hs[j * 257 + tid];
        const int hd = tid >> 6;
        __half* aggb = agg + (size_t)b * (32 * 256);
        #pragma unroll 4
        for (int a = 0; a < 32; ++a) {
            const float* al = alpha + (hd * 32 + a) * 33;
            float s = 0.f;
            #pragma unroll
            for (int j = 0; j < 32; ++j) s = fmaf(al[j], v[j], s);
            aggb[a * 256 + tid] = __float2half(s);
        }
    }
}

// ---------------------------------------------------------------------------
// k2: GRU via fp16 MMA — BK=64 stages (8 stages total, half the syncs),
// 3 buffers, pitch 144 B (conflict-free ldmatrix), fp16 hprev.
// ---------------------------------------------------------------------------
#define K2H_STAGEB (128*144 + 96*144)    // 32256 B per stage
#define K2H_SMEM   (3 * K2H_STAGEB)      // 96768 B

__global__ void __launch_bounds__(256, 2) k2_gru_f16(
    const __half* __restrict__ xrh,  const __half* __restrict__ hinh,
    const __half* __restrict__ Wih,  const __half* __restrict__ Whh,
    const float*  __restrict__ bih,  const float*  __restrict__ bhh,
    float* __restrict__ hh_out)
{
    extern __shared__ __half smh[];
    const uint32_t sbase = (uint32_t)__cvta_generic_to_shared(smh);

    const int tid  = threadIdx.x;
    const int lane = tid & 31;
    const int warp = tid >> 5;
    const int wm  = (warp & 3) * 32;
    const int wn  = (warp >> 2) * 48;
    const int g   = lane >> 2;
    const int tg  = lane & 3;
    const size_t r0 = (size_t)blockIdx.y * 128;
    const int c0 = blockIdx.x * 32;

    auto wrow_of = [&](int n) {
        int grp = n >> 4, cl = n & 15;
        return (grp % 3) * 256 + c0 + (grp / 3) * 16 + cl;
    };

    // staging: A = 1024 16B-chunks (4/thread), B = 768 (3/thread)
    const int mS = tid >> 3;             // helper base row per 32-row group
    const int jS = tid & 7;              // chunk within row (8 x 16B = 128 B)

    auto issue = [&](int s) {
        const int buf = s % 3;
        const int kb  = (s & 3) * 64;    // halves within the 256-wide K
        const __half* Asrc = (s < 4) ? xrh : hinh;
        const __half* Wsrc = (s < 4) ? Wih : Whh;
        const uint32_t sb = sbase + (uint32_t)(buf * K2H_STAGEB);
        #pragma unroll
        for (int i = 0; i < 4; ++i) {
            int m = mS + i * 32;         // 0..127
            cpa16(sb + (uint32_t)(m * 144 + jS * 16),
                  Asrc + (r0 + m) * 256 + kb + jS * 8);
        }
        #pragma unroll
        for (int i = 0; i < 3; ++i) {
            int n = mS + i * 32;         // 0..95
            cpa16(sb + (uint32_t)(18432 + n * 144 + jS * 16),
                  Wsrc + (size_t)wrow_of(n) * 256 + kb + jS * 8);
        }
        CPA_COMMIT();
    };

    // ldmatrix lane addressing (pitch 144 B)
    const int l7 = lane & 7;
    const int aRow = ((lane >> 3) & 1) * 8 + l7;
    const int aKb  = (lane >> 4) * 16;
    const uint32_t aAddr = sbase + (uint32_t)((wm + aRow) * 144 + aKb);
    const int bRow = ((lane >> 4) & 1) * 8 + l7;
    const int bKb  = ((lane >> 3) & 1) * 16;
    const uint32_t bAddr = sbase + (uint32_t)(18432 + (wn + bRow) * 144 + bKb);

    float acc [2][4][4];
    float accd[2][2][2][4];
    #pragma unroll
    for (int mt = 0; mt < 2; ++mt) {
        #pragma unroll
        for (int nt = 0; nt < 4; ++nt)
            #pragma unroll
            for (int e = 0; e < 4; ++e) acc[mt][nt][e] = 0.f;
        #pragma unroll
        for (int p = 0; p < 2; ++p)
            #pragma unroll
            for (int j = 0; j < 2; ++j)
                #pragma unroll
                for (int e = 0; e < 4; ++e) accd[p][mt][j][e] = 0.f;
    }

    auto compute = [&](int buf, int ph) {
        const uint32_t bufoff = (uint32_t)(buf * K2H_STAGEB);
        #pragma unroll
        for (int ks = 0; ks < 4; ++ks) {
            const uint32_t ko = bufoff + ks * 32;   // 16 halves = 32 B per k16
            uint32_t a[2][4];
            LDSM_X4(a[0], aAddr + ko);
            LDSM_X4(a[1], aAddr + ko + 16 * 144);
            uint32_t bf[6][2];
            #pragma unroll
            for (int p = 0; p < 3; ++p) {
                uint32_t t[4];
                LDSM_X4(t, bAddr + ko + p * 16 * 144);
                bf[2 * p][0]     = t[0];
                bf[2 * p][1]     = t[1];
                bf[2 * p + 1][0] = t[2];
                bf[2 * p + 1][1] = t[3];
            }
            #pragma unroll
            for (int mt = 0; mt < 2; ++mt) {
                #pragma unroll
                for (int nt = 0; nt < 4; ++nt)
                    MMA_F16(acc[mt][nt], a[mt], bf[nt]);
                #pragma unroll
                for (int j = 0; j < 2; ++j) {
                    if (ph == 0) { MMA_F16(accd[0][mt][j], a[mt], bf[4 + j]); }
                    else         { MMA_F16(accd[1][mt][j], a[mt], bf[4 + j]); }
                }
            }
        }
    };

    // pipeline: 8 stages (4 per phase), 3 buffers, 1 stage ahead
    issue(0);
    issue(1);
    CPA_WAIT(1);
    __syncthreads();

    #pragma unroll 1
    for (int s = 0; s < 8; ++s) {
        compute(s % 3, (s < 4) ? 0 : 1);
        if (s + 2 < 8) { issue(s + 2); CPA_WAIT(1); }
        else           { CPA_WAIT(0); }
        __syncthreads();
    }

    // epilogue: gates in registers; hprev from fp16 hinh
    const int colbase = c0 + (wn ? 16 : 0);
    #pragma unroll
    for (int mt = 0; mt < 2; ++mt) {
        const size_t rA = r0 + wm + mt * 16 + g;
        const size_t rB = rA + 8;
        #pragma unroll
        for (int j = 0; j < 2; ++j) {
            const int c = colbase + j * 8 + tg * 2;
            const float br0  = bih[c]       + bhh[c];
            const float br1  = bih[c + 1]   + bhh[c + 1];
            const float bz0  = bih[256 + c] + bhh[256 + c];
            const float bz1  = bih[257 + c] + bhh[257 + c];
            const float bni0 = bih[512 + c],  bni1 = bih[513 + c];
            const float bnh0 = bhh[512 + c],  bnh1 = bhh[513 + c];
            const float2 hpA = __half22float2(*(const __half2*)(hinh + rA * 256 + c));
            const float2 hpB = __half22float2(*(const __half2*)(hinh + rB * 256 + c));

            float rg, zg, ng;
            rg = sigf(acc[mt][j][0] + br0);
            zg = sigf(acc[mt][2 + j][0] + bz0);
            ng = tanhf(accd[0][mt][j][0] + bni0 + rg * (accd[1][mt][j][0] + bnh0));
            float o0 = (1.f - zg) * ng + zg * hpA.x;

            rg = sigf(acc[mt][j][1] + br1);
            zg = sigf(acc[mt][2 + j][1] + bz1);
            ng = tanhf(accd[0][mt][j][1] + bni1 + rg * (accd[1][mt][j][1] + bnh1));
            float o1 = (1.f - zg) * ng + zg * hpA.y;

            rg = sigf(acc[mt][j][2] + br0);
            zg = sigf(acc[mt][2 + j][2] + bz0);
            ng = tanhf(accd[0][mt][j][2] + bni0 + rg * (accd[1][mt][j][2] + bnh0));
            float o2 = (1.f - zg) * ng + zg * hpB.x;

            rg = sigf(acc[mt][j][3] + br1);
            zg = sigf(acc[mt][2 + j][3] + bz1);
            ng = tanhf(accd[0][mt][j][3] + bni1 + rg * (accd[1][mt][j][3] + bnh1));
            float o3 = (1.f - zg) * ng + zg * hpB.y;

            *(float2*)(hh_out + rA * 256 + c) = make_float2(o0, o1);
            *(float2*)(hh_out + rB * 256 + c) = make_float2(o2, o3);
        }
    }
}

// ---------------------------------------------------------------------------
// k3: LayerNorm + fc2 — dual-row warps (proven R13)
// ---------------------------------------------------------------------------
__global__ void __launch_bounds__(256) k3_ln_fc2(
    const float* __restrict__ hh, const float* __restrict__ lng,
    const float* __restrict__ lnb, const float* __restrict__ W2,
    const float* __restrict__ b2, float* __restrict__ q, int nrows)
{
    int warp = (blockIdx.x * blockDim.x + threadIdx.x) >> 5;
    int lane = threadIdx.x & 31;
    size_t rA = (size_t)warp * 2;
    if (rA >= (size_t)nrows) return;
    size_t rB = rA + 1;
    const float* hA = hh + rA * RDIM;
    const float* hB = hh + rB * RDIM;

    float vA[8], vB[8];
    float sA = 0.f, sB = 0.f;
    #pragma unroll
    for (int i = 0; i < 8; ++i) {
        vA[i] = hA[lane + 32 * i]; sA += vA[i];
        vB[i] = hB[lane + 32 * i]; sB += vB[i];
    }
    #pragma unroll
    for (int o = 16; o; o >>= 1) {
        sA += __shfl_xor_sync(0xffffffffu, sA, o);
        sB += __shfl_xor_sync(0xffffffffu, sB, o);
    }
    float muA = sA * (1.f / 256.f), muB = sB * (1.f / 256.f);
    float qA = 0.f, qB = 0.f;
    #pragma unroll
    for (int i = 0; i < 8; ++i) {
        float dA = vA[i] - muA; qA += dA * dA;
        float dB = vB[i] - muB; qB += dB * dB;
    }
    #pragma unroll
    for (int o = 16; o; o >>= 1) {
        qA += __shfl_xor_sync(0xffffffffu, qA, o);
        qB += __shfl_xor_sync(0xffffffffu, qB, o);
    }
    float invA = rsqrtf(qA * (1.f / 256.f) + 1e-5f);
    float invB = rsqrtf(qB * (1.f / 256.f) + 1e-5f);

    float nA[8], nB[8];
    #pragma unroll
    for (int i = 0; i < 8; ++i) {
        float gg = lng[lane + 32 * i], bb = lnb[lane + 32 * i];
        nA[i] = (vA[i] - muA) * invA * gg + bb;
        nB[i] = (vB[i] - muB) * invB * gg + bb;
    }

    #pragma unroll
    for (int j = 0; j < NACT; ++j) {
        float pA = 0.f, pB = 0.f;
        #pragma unroll
        for (int i = 0; i < 8; ++i) {
            float w = W2[j * RDIM + lane + 32 * i];
            pA = fmaf(nA[i], w, pA);
            pB = fmaf(nB[i], w, pB);
        }
        #pragma unroll
        for (int o = 16; o; o >>= 1) {
            pA += __shfl_xor_sync(0xffffffffu, pA, o);
            pB += __shfl_xor_sync(0xffffffffu, pB, o);
        }
        if (lane == j) {
            q[rA * NACT + j] = pA + b2[j];
            q[rB * NACT + j] = pB + b2[j];
        }
    }
}

// ---------------------------------------------------------------------------
extern "C" void kernel_launch(void* const* d_in, const int* in_sizes, int n_in,
                              void* d_out, int out_size)
{
    const float* inputs = (const float*)d_in[0];
    const float* hidden = (const float*)d_in[1];
    const int*   mask   = (const int*)  d_in[2];
    const float* Wfc    = (const float*)d_in[3];
    const float* bfc    = (const float*)d_in[4];
    const float* Wh     = (const float*)d_in[5];
    const float* asrc   = (const float*)d_in[6];
    const float* adst   = (const float*)d_in[7];
    const float* Wo     = (const float*)d_in[8];
    const float* bo     = (const float*)d_in[9];
    const float* W1     = (const float*)d_in[10];
    const float* b1     = (const float*)d_in[11];
    const float* Wih    = (const float*)d_in[12];
    const float* Whh    = (const float*)d_in[13];
    const float* bih    = (const float*)d_in[14];
    const float* bhh    = (const float*)d_in[15];
    const float* lng    = (const float*)d_in[16];
    const float* lnb    = (const float*)d_in[17];
    const float* W2     = (const float*)d_in[18];
    const float* b2     = (const float*)d_in[19];

    const int B = in_sizes[0] / (AN * OBS);       // 4096
    const int nrows = B * AN;                     // 131072
    const int mblk = nrows / 128;                 // 1024

    float* q_out  = (float*)d_out;
    float* hh_out = (float*)d_out + (size_t)nrows * NACT;

    __half *bhh16buf, *inh, *xeh, *aggh, *atth, *xrh, *hinh;
    __half *wfch, *whth, *woth, *w1h, *wih16, *whh16;
    cudaGetSymbolAddress((void**)&bhh16buf, g_bufHh);
    cudaGetSymbolAddress((void**)&inh,   g_inh);
    cudaGetSymbolAddress((void**)&xeh,   g_xeh);
    cudaGetSymbolAddress((void**)&aggh,  g_aggh);
    cudaGetSymbolAddress((void**)&atth,  g_atth);
    cudaGetSymbolAddress((void**)&xrh,   g_xrh);
    cudaGetSymbolAddress((void**)&hinh,  g_hinh);
    cudaGetSymbolAddress((void**)&wfch,  g_Wfch);
    cudaGetSymbolAddress((void**)&whth,  g_WhTh);
    cudaGetSymbolAddress((void**)&woth,  g_WoTh);
    cudaGetSymbolAddress((void**)&w1h,   g_W1h);
    cudaGetSymbolAddress((void**)&wih16, g_Wih16);
    cudaGetSymbolAddress((void**)&whh16, g_Whh16);

    cudaFuncSetAttribute(kB_attn,    cudaFuncAttributeMaxDynamicSharedMemorySize, KB_SMEM);
    cudaFuncSetAttribute(k2_gru_f16, cudaFuncAttributeMaxDynamicSharedMemorySize, K2H_SMEM);
    cudaFuncSetAttribute(gemm_hn<128, 0, 1, 1>, cudaFuncAttributeMaxDynamicSharedMemorySize, GH_SMEM);
    cudaFuncSetAttribute(gemm_hn<64, 0, 0, 1>,  cudaFuncAttributeMaxDynamicSharedMemorySize, GH_SMEM);
    cudaFuncSetAttribute(gemm_hn<256, 0, 1, 1>, cudaFuncAttributeMaxDynamicSharedMemorySize, GH_SMEM);
    cudaFuncSetAttribute(gemm_hn<128, 64, 2, 1>,cudaFuncAttributeMaxDynamicSharedMemorySize, GH_SMEM);

    k0_prep<<<64, 256>>>(Wfc, Wh, Wo, W1, Wih, Whh,
                         wfch, whth, woth, w1h, wih16, whh16);
    kH_f2h2<<<4096, 256>>>(hidden, (__half2*)hinh, nrows * RDIM / 4,
                           inputs, (__half2*)inh,  nrows * OBS / 4);

    // G1: XE = inputs @ Wfc^T + bfc          [M,64] fp16
    gemm_hn<128, 0, 1, 1><<<dim3(1, mblk), 256, GH_SMEM>>>(inh, nullptr, wfch, bfc, xeh);
    // G2: H = XE @ WhT^T                     [M,256] fp16
    gemm_hn<64, 0, 0, 1><<<dim3(4, mblk), 256, GH_SMEM>>>(xeh, nullptr, whth, nullptr, bhh16buf);
    // attention (fp16 H in, fp16 agg out)
    kB_attn<<<B, 256, KB_SMEM>>>(bhh16buf, mask, asrc, adst, aggh);
    // G3: ATT = agg @ WoT^T + bo             [M,64] fp16
    gemm_hn<256, 0, 1, 1><<<dim3(1, mblk), 256, GH_SMEM>>>(aggh, nullptr, woth, bo, atth);
    // G4: XR = relu([inputs|ATT] @ W1^T+b1)  [M,256] fp16
    gemm_hn<128, 64, 2, 1><<<dim3(4, mblk), 256, GH_SMEM>>>(inh, atth, w1h, b1, xrh);
    // GRU (fp16 MMA, BK=64 stages, fp16 hprev)
    k2_gru_f16<<<dim3(8, mblk), 256, K2H_SMEM>>>(xrh, hinh, wih16, whh16,
                                                 bih, bhh, hh_out);
    // LN + fc2 (dual-row warps)
    k3_ln_fc2<<<(nrows / 2 + 7) / 8, 256>>>(hh_out, lng, lnb, W2, b2, q_out, nrows);
}

// round 17
// speedup vs baseline: 1.3488x; 1.0185x over previous
#include <cuda_runtime.h>
#include <cuda_fp16.h>
#include <cuda_bf16.h>
#include <stdint.h>

// Problem constants
#define AN   32
#define OBS  128
#define EDIM 64
#define DDIM 64
#define HHEADS 4
#define RDIM 256
#define NACT 16
#define ZDIM 192
#define MAXROWS (4096*32)

// Scratch buffers
__device__ __align__(16) __half g_bufHh[MAXROWS * RDIM];  // H fp16
__device__ __align__(16) __half g_inh  [MAXROWS * OBS];   // inputs fp16
__device__ __align__(16) __half g_xeh  [MAXROWS * 64];    // XE fp16
__device__ __align__(16) __half g_aggh [MAXROWS * RDIM];  // agg fp16
__device__ __align__(16) __half g_atth [MAXROWS * 64];    // ATT fp16
__device__ __align__(16) __half g_xrh  [MAXROWS * RDIM];  // XR fp16
__device__ __align__(16) __half g_hinh [MAXROWS * RDIM];  // hidden fp16
__device__ __align__(16) __half g_Wfch [64 * OBS];
__device__ __align__(16) __half g_WhTh [256 * 64];
__device__ __align__(16) __half g_WoTh [64 * 256];
__device__ __align__(16) __half g_W1h  [RDIM * ZDIM];
__device__ __align__(16) __half g_Wih16[3 * RDIM * RDIM];
__device__ __align__(16) __half g_Whh16[3 * RDIM * RDIM];

__device__ __forceinline__ float sigf(float x) { return 1.0f / (1.0f + __expf(-x)); }

#define MMA_F16(d, a, b)                                                      \
    asm volatile(                                                             \
        "mma.sync.aligned.m16n8k16.row.col.f32.f16.f16.f32 "                  \
        "{%0,%1,%2,%3},{%4,%5,%6,%7},{%8,%9},{%0,%1,%2,%3};"                  \
        : "+f"(d[0]), "+f"(d[1]), "+f"(d[2]), "+f"(d[3])                      \
        : "r"(a[0]), "r"(a[1]), "r"(a[2]), "r"(a[3]), "r"(b[0]), "r"(b[1]))

#define LDSM_X4(r, addr)                                                      \
    asm volatile(                                                             \
        "ldmatrix.sync.aligned.m8n8.x4.shared.b16 {%0,%1,%2,%3}, [%4];"       \
        : "=r"((r)[0]), "=r"((r)[1]), "=r"((r)[2]), "=r"((r)[3])              \
        : "r"(addr))

__device__ __forceinline__ void cpa16(uint32_t dst, const void* src) {
    asm volatile("cp.async.cg.shared.global [%0], [%1], 16;"
                 :: "r"(dst), "l"(src));
}
#define CPA_COMMIT()  asm volatile("cp.async.commit_group;" ::: "memory")
#define CPA_WAIT(N)   asm volatile("cp.async.wait_group %0;" :: "n"(N) : "memory")

// ---------------------------------------------------------------------------
// k0: merged prologue — weight transposes/conversions + hidden/inputs fp16
// ---------------------------------------------------------------------------
__global__ void k0_prep(const float* __restrict__ Wfc, const float* __restrict__ Wh,
                        const float* __restrict__ Wo, const float* __restrict__ W1,
                        const float* __restrict__ Wih, const float* __restrict__ Whh,
                        const float* __restrict__ hidden, const float* __restrict__ inputs,
                        __half* __restrict__ Wfch, __half* __restrict__ WhTh,
                        __half* __restrict__ WoTh, __half* __restrict__ W1h,
                        __half* __restrict__ Wih16, __half* __restrict__ Whh16,
                        __half2* __restrict__ hinh2, __half2* __restrict__ inh2,
                        int n4hid, int n4in)
{
    int tid = blockIdx.x * blockDim.x + threadIdx.x;
    int stride = gridDim.x * blockDim.x;
    for (int i = tid; i < 64 * OBS; i += stride) Wfch[i] = __float2half(Wfc[i]);
    for (int i = tid; i < 256 * 64; i += stride) {
        int n = i >> 6, e = i & 63;
        int h = n >> 6, d = n & 63;
        WhTh[i] = __float2half(Wh[(h * 64 + e) * 64 + d]);
    }
    for (int i = tid; i < 64 * 256; i += stride) {
        int e = i >> 8, k = i & 255;
        WoTh[i] = __float2half(Wo[k * 64 + e]);
    }
    for (int i = tid; i < RDIM * ZDIM; i += stride) W1h[i] = __float2half(W1[i]);
    for (int i = tid; i < 3 * 256 * 256; i += stride) {
        Wih16[i] = __float2half(Wih[i]);
        Whh16[i] = __float2half(Whh[i]);
    }
    for (int i = tid; i < n4hid; i += stride) {
        float4 v = ((const float4*)hidden)[i];
        hinh2[2 * i]     = __floats2half2_rn(v.x, v.y);
        hinh2[2 * i + 1] = __floats2half2_rn(v.z, v.w);
    }
    for (int i = tid; i < n4in; i += stride) {
        float4 v = ((const float4*)inputs)[i];
        inh2[2 * i]     = __floats2half2_rn(v.x, v.y);
        inh2[2 * i + 1] = __floats2half2_rn(v.z, v.w);
    }
}

// ---------------------------------------------------------------------------
// Single-shot fp16 GEMM for small K (latency-bound stages G1, G2):
//   C[M, NBLK*64] = EPI( A[M,KT] @ W[NT,KT]^T + bias )
//   One cp.async batch loads the full 128xKT A-tile AND all NT weight rows,
//   then ONE wait + pure compute over NBLK output blocks. PITCH = KT+8 halves
//   (272 B / 144 B: ldmatrix rows hit disjoint 4-bank groups, conflict-free).
// ---------------------------------------------------------------------------
template<int KT, int NBLK, int EPI>
__global__ void __launch_bounds__(256, 2) gemm_ss(
    const __half* __restrict__ A, const __half* __restrict__ W,
    const float* __restrict__ bias, __half* __restrict__ C)
{
    constexpr int PITCHH = KT + 8;
    constexpr int PITCHB = PITCHH * 2;
    constexpr int NT = NBLK * 64;
    constexpr int CPR = KT / 8;          // 16B chunks per row
    extern __shared__ __half smh[];
    const uint32_t sbase = (uint32_t)__cvta_generic_to_shared(smh);
    const uint32_t bOff = (uint32_t)(128 * PITCHB);

    const int tid  = threadIdx.x;
    const int lane = tid & 31;
    const int warp = tid >> 5;
    const int wm = (warp & 3) * 32;
    const int wn = (warp >> 2) * 32;
    const int g  = lane >> 2;
    const int tg = lane & 3;
    const size_t r0 = (size_t)blockIdx.y * 128;

    // one-shot load: A (128*CPR chunks) + B (NT*CPR chunks)
    #pragma unroll
    for (int i = 0; i < (128 * CPR) / 256; ++i) {
        int idx = tid + i * 256;
        int m = idx / CPR, j = idx % CPR;
        cpa16(sbase + (uint32_t)(m * PITCHB + j * 16),
              A + (r0 + m) * KT + j * 8);
    }
    #pragma unroll
    for (int i = 0; i < (NT * CPR) / 256; ++i) {
        int idx = tid + i * 256;
        int n = idx / CPR, j = idx % CPR;
        cpa16(sbase + bOff + (uint32_t)(n * PITCHB + j * 16),
              W + (size_t)n * KT + j * 8);
    }
    CPA_COMMIT();
    CPA_WAIT(0);
    __syncthreads();

    const int l7 = lane & 7;
    const int aRow = ((lane >> 3) & 1) * 8 + l7;
    const int aKb  = (lane >> 4) * 16;
    const uint32_t aAddr = sbase + (uint32_t)((wm + aRow) * PITCHB + aKb);
    const int bRow = ((lane >> 4) & 1) * 8 + l7;
    const int bKb  = ((lane >> 3) & 1) * 16;
    const uint32_t bAddr = sbase + bOff + (uint32_t)((wn + bRow) * PITCHB + bKb);

    #pragma unroll
    for (int nb = 0; nb < NBLK; ++nb) {
        float acc[2][4][4];
        #pragma unroll
        for (int mt = 0; mt < 2; ++mt)
            #pragma unroll
            for (int nt = 0; nt < 4; ++nt)
                #pragma unroll
                for (int e = 0; e < 4; ++e) acc[mt][nt][e] = 0.f;

        const uint32_t bBlk = bAddr + (uint32_t)(nb * 64 * PITCHB);
        #pragma unroll
        for (int ks = 0; ks < KT / 16; ++ks) {
            const uint32_t ko = ks * 32;
            uint32_t a[2][4];
            LDSM_X4(a[0], aAddr + ko);
            LDSM_X4(a[1], aAddr + ko + 16 * PITCHB);
            uint32_t bf[4][2];
            #pragma unroll
            for (int p = 0; p < 2; ++p) {
                uint32_t t[4];
                LDSM_X4(t, bBlk + ko + p * 16 * PITCHB);
                bf[2 * p][0]     = t[0];
                bf[2 * p][1]     = t[1];
                bf[2 * p + 1][0] = t[2];
                bf[2 * p + 1][1] = t[3];
            }
            #pragma unroll
            for (int mt = 0; mt < 2; ++mt)
                #pragma unroll
                for (int nt = 0; nt < 4; ++nt)
                    MMA_F16(acc[mt][nt], a[mt], bf[nt]);
        }

        #pragma unroll
        for (int mt = 0; mt < 2; ++mt) {
            #pragma unroll
            for (int nt = 0; nt < 4; ++nt) {
                size_t r = r0 + wm + mt * 16 + g;
                int    c = nb * 64 + wn + nt * 8 + tg * 2;
                float v0 = acc[mt][nt][0], v1 = acc[mt][nt][1];
                float v2 = acc[mt][nt][2], v3 = acc[mt][nt][3];
                if (EPI >= 1) {
                    float b0 = bias[c], b1 = bias[c + 1];
                    v0 += b0; v1 += b1; v2 += b0; v3 += b1;
                }
                if (EPI == 2) {
                    v0 = fmaxf(v0, 0.f); v1 = fmaxf(v1, 0.f);
                    v2 = fmaxf(v2, 0.f); v3 = fmaxf(v3, 0.f);
                }
                *(__half2*)(C + r * NT + c)       = __floats2half2_rn(v0, v1);
                *(__half2*)(C + (r + 8) * NT + c) = __floats2half2_rn(v2, v3);
            }
        }
    }
}

// ---------------------------------------------------------------------------
// Generic fp16 pipelined GEMM (proven R12) — used for G3, G4
// ---------------------------------------------------------------------------
#define GH_STAGEB (128*80 + 64*80)
#define GH_SMEM   (3 * GH_STAGEB)

template<int K1, int K2, int EPI, int OUTH>
__global__ void __launch_bounds__(256, 2) gemm_hn(
    const __half* __restrict__ A1, const __half* __restrict__ A2,
    const __half* __restrict__ W,  const float* __restrict__ bias,
    void* __restrict__ Cout)
{
    constexpr int KT = K1 + K2;
    constexpr int NS = KT / 32;
    extern __shared__ __half smh[];
    const uint32_t sbase = (uint32_t)__cvta_generic_to_shared(smh);

    const int tid  = threadIdx.x;
    const int lane = tid & 31;
    const int warp = tid >> 5;
    const int wm = (warp & 3) * 32;
    const int wn = (warp >> 2) * 32;
    const int g  = lane >> 2;
    const int tg = lane & 3;
    const size_t r0 = (size_t)blockIdx.y * 128;
    const int n0 = blockIdx.x * 64;
    const int ldc = gridDim.x * 64;

    const int mA = tid >> 2;
    const int jA = tid & 3;
    const uint32_t adst0 = (uint32_t)(mA * 80 + jA * 16);
    const uint32_t adst1 = (uint32_t)((mA + 64) * 80 + jA * 16);
    const int nB = tid >> 2;
    const uint32_t bdst = (uint32_t)(10240 + nB * 80 + jA * 16);

    auto issue = [&](int s) {
        const int buf = s % 3;
        const int kb  = s * 32;
        const uint32_t sb = sbase + (uint32_t)(buf * GH_STAGEB);
        const int kh = jA * 8;
        if (K2 == 0 || kb < K1) {
            const __half* src = A1 + (size_t)(r0 + mA) * K1 + kb + kh;
            cpa16(sb + adst0, src);
            cpa16(sb + adst1, src + (size_t)64 * K1);
        } else {
            const __half* src = A2 + (size_t)(r0 + mA) * K2 + (kb - K1) + kh;
            cpa16(sb + adst0, src);
            cpa16(sb + adst1, src + (size_t)64 * K2);
        }
        cpa16(sb + bdst, W + (size_t)(n0 + nB) * KT + kb + kh);
        CPA_COMMIT();
    };

    const int l7 = lane & 7;
    const int aRow = ((lane >> 3) & 1) * 8 + l7;
    const int aKb  = (lane >> 4) * 16;
    const uint32_t aAddr = sbase + (uint32_t)((wm + aRow) * 80 + aKb);
    const int bRow = ((lane >> 4) & 1) * 8 + l7;
    const int bKb  = ((lane >> 3) & 1) * 16;
    const uint32_t bAddr = sbase + (uint32_t)(10240 + (wn + bRow) * 80 + bKb);

    float acc[2][4][4];
    #pragma unroll
    for (int mt = 0; mt < 2; ++mt)
        #pragma unroll
        for (int nt = 0; nt < 4; ++nt)
            #pragma unroll
            for (int e = 0; e < 4; ++e) acc[mt][nt][e] = 0.f;

    auto compute = [&](int buf) {
        const uint32_t bufoff = (uint32_t)(buf * GH_STAGEB);
        #pragma unroll
        for (int ks = 0; ks < 2; ++ks) {
            const uint32_t ko = bufoff + ks * 32;
            uint32_t a[2][4];
            LDSM_X4(a[0], aAddr + ko);
            LDSM_X4(a[1], aAddr + ko + 16 * 80);
            uint32_t bf[4][2];
            #pragma unroll
            for (int p = 0; p < 2; ++p) {
                uint32_t t[4];
                LDSM_X4(t, bAddr + ko + p * 16 * 80);
                bf[2 * p][0]     = t[0];
                bf[2 * p][1]     = t[1];
                bf[2 * p + 1][0] = t[2];
                bf[2 * p + 1][1] = t[3];
            }
            #pragma unroll
            for (int mt = 0; mt < 2; ++mt)
                #pragma unroll
                for (int nt = 0; nt < 4; ++nt)
                    MMA_F16(acc[mt][nt], a[mt], bf[nt]);
        }
    };

    issue(0);
    if (NS > 1) issue(1);
    CPA_WAIT(1);
    __syncthreads();

    #pragma unroll 1
    for (int s = 0; s < NS; ++s) {
        compute(s % 3);
        if (s + 2 < NS) { issue(s + 2); CPA_WAIT(1); }
        else            { CPA_WAIT(0); }
        __syncthreads();
    }

    #pragma unroll
    for (int mt = 0; mt < 2; ++mt) {
        #pragma unroll
        for (int nt = 0; nt < 4; ++nt) {
            size_t r = r0 + wm + mt * 16 + g;
            int    c = n0 + wn + nt * 8 + tg * 2;
            float v0 = acc[mt][nt][0], v1 = acc[mt][nt][1];
            float v2 = acc[mt][nt][2], v3 = acc[mt][nt][3];
            if (EPI >= 1) {
                float b0 = bias[c], b1 = bias[c + 1];
                v0 += b0; v1 += b1; v2 += b0; v3 += b1;
            }
            if (EPI == 2) {
                v0 = fmaxf(v0, 0.f); v1 = fmaxf(v1, 0.f);
                v2 = fmaxf(v2, 0.f); v3 = fmaxf(v3, 0.f);
            }
            if (OUTH) {
                __half* Ch = (__half*)Cout;
                *(__half2*)(Ch + r * ldc + c)       = __floats2half2_rn(v0, v1);
                *(__half2*)(Ch + (r + 8) * ldc + c) = __floats2half2_rn(v2, v3);
            } else {
                float* C = (float*)Cout;
                *(float2*)(C + r * ldc + c)       = make_float2(v0, v1);
                *(float2*)(C + (r + 8) * ldc + c) = make_float2(v2, v3);
            }
        }
    }
}

// ---------------------------------------------------------------------------
// kB: per-batch masked attention — unchanged from proven R13
// ---------------------------------------------------------------------------
#define KB_HS    0
#define KB_ALPHA 8224
#define KB_SSRC  (KB_ALPHA + 4*32*33)
#define KB_SDST  (KB_SSRC + 128)
#define KB_SAS   (KB_SDST + 128)
#define KB_SAD   (KB_SAS + 256)
#define KB_MSK   (KB_SAD + 256)
#define KB_SMEM  ((KB_MSK + 32*33) * 4)  // 57088 B

__global__ void __launch_bounds__(256) kB_attn(
    const __half* __restrict__ H, const int* __restrict__ mask,
    const float* __restrict__ asrc, const float* __restrict__ adst,
    __half* __restrict__ agg)
{
    extern __shared__ float smf[];
    float* Hs    = smf + KB_HS;
    float* alpha = smf + KB_ALPHA;
    float* ssrc  = smf + KB_SSRC;
    float* sdst  = smf + KB_SDST;
    float* sas   = smf + KB_SAS;
    float* sad   = smf + KB_SAD;
    int*   msk   = (int*)(smf + KB_MSK);

    const int tid  = threadIdx.x;
    const int lane = tid & 31;
    const int warp = tid >> 5;
    const int b    = blockIdx.x;

    const __half2* Hb2 = (const __half2*)(H + (size_t)b * (32 * 256));
    for (int i = tid; i < 32 * 128; i += 256) {
        int a = i >> 7, c2 = i & 127;
        float2 v = __half22float2(Hb2[i]);
        Hs[a * 257 + 2 * c2]     = v.x;
        Hs[a * 257 + 2 * c2 + 1] = v.y;
    }
    for (int i = tid; i < 256; i += 256) { sas[i] = asrc[i]; sad[i] = adst[i]; }
    for (int i = tid; i < 32 * 32; i += 256) {
        int r = i >> 5, c = i & 31;
        msk[r * 33 + c] = mask[(size_t)b * (32 * 32) + i];
    }
    __syncthreads();

    if (warp < 4) {
        int hd = warp;
        float vs = 0.f, vd = 0.f;
        const float* hr = Hs + lane * 257 + hd * 64;
        #pragma unroll
        for (int d = 0; d < 64; ++d) {
            float h = hr[d];
            vs = fmaf(h, sas[hd * 64 + d], vs);
            vd = fmaf(h, sad[hd * 64 + d], vd);
        }
        ssrc[hd * 32 + lane] = vs;
        sdst[hd * 32 + lane] = vd;
    }
    __syncthreads();

    if (tid < 128) {
        int hd = tid >> 5, i = tid & 31;
        float si = ssrc[hd * 32 + i];
        float v[32];
        float m = -3.4e38f;
        #pragma unroll
        for (int j = 0; j < 32; ++j) {
            float e_ = si + sdst[hd * 32 + j];
            float l  = e_ > 0.f ? e_ : 0.2f * e_;
            if (msk[i * 33 + j] <= 0) l = -1e9f;
            v[j] = l; m = fmaxf(m, l);
        }
        float s = 0.f;
        #pragma unroll
        for (int j = 0; j < 32; ++j) { v[j] = __expf(v[j] - m); s += v[j]; }
        float inv = 1.f / s;
        #pragma unroll
        for (int j = 0; j < 32; ++j) alpha[(hd * 32 + i) * 33 + j] = v[j] * inv;
    }
    __syncthreads();

    {
        float v[32];
        #pragma unroll
        for (int j = 0; j < 32; ++j) v[j] = Hs[j * 257 + tid];
        const int hd = tid >> 6;
        __half* aggb = agg + (size_t)b * (32 * 256);
        #pragma unroll 4
        for (int a = 0; a < 32; ++a) {
            const float* al = alpha + (hd * 32 + a) * 33;
            float s = 0.f;
            #pragma unroll
            for (int j = 0; j < 32; ++j) s = fmaf(al[j], v[j], s);
            aggb[a * 256 + tid] = __float2half(s);
        }
    }
}

// ---------------------------------------------------------------------------
// k2: GRU via fp16 MMA — BK=64 stages (proven R15)
// ---------------------------------------------------------------------------
#define K2H_STAGEB (128*144 + 96*144)
#define K2H_SMEM   (3 * K2H_STAGEB)

__global__ void __launch_bounds__(256, 2) k2_gru_f16(
    const __half* __restrict__ xrh,  const __half* __restrict__ hinh,
    const __half* __restrict__ Wih,  const __half* __restrict__ Whh,
    const float*  __restrict__ bih,  const float*  __restrict__ bhh,
    float* __restrict__ hh_out)
{
    extern __shared__ __half smh[];
    const uint32_t sbase = (uint32_t)__cvta_generic_to_shared(smh);

    const int tid  = threadIdx.x;
    const int lane = tid & 31;
    const int warp = tid >> 5;
    const int wm  = (warp & 3) * 32;
    const int wn  = (warp >> 2) * 48;
    const int g   = lane >> 2;
    const int tg  = lane & 3;
    const size_t r0 = (size_t)blockIdx.y * 128;
    const int c0 = blockIdx.x * 32;

    auto wrow_of = [&](int n) {
        int grp = n >> 4, cl = n & 15;
        return (grp % 3) * 256 + c0 + (grp / 3) * 16 + cl;
    };

    const int mS = tid >> 3;
    const int jS = tid & 7;

    auto issue = [&](int s) {
        const int buf = s % 3;
        const int kb  = (s & 3) * 64;
        const __half* Asrc = (s < 4) ? xrh : hinh;
        const __half* Wsrc = (s < 4) ? Wih : Whh;
        const uint32_t sb = sbase + (uint32_t)(buf * K2H_STAGEB);
        #pragma unroll
        for (int i = 0; i < 4; ++i) {
            int m = mS + i * 32;
            cpa16(sb + (uint32_t)(m * 144 + jS * 16),
                  Asrc + (r0 + m) * 256 + kb + jS * 8);
        }
        #pragma unroll
        for (int i = 0; i < 3; ++i) {
            int n = mS + i * 32;
            cpa16(sb + (uint32_t)(18432 + n * 144 + jS * 16),
                  Wsrc + (size_t)wrow_of(n) * 256 + kb + jS * 8);
        }
        CPA_COMMIT();
    };

    const int l7 = lane & 7;
    const int aRow = ((lane >> 3) & 1) * 8 + l7;
    const int aKb  = (lane >> 4) * 16;
    const uint32_t aAddr = sbase + (uint32_t)((wm + aRow) * 144 + aKb);
    const int bRow = ((lane >> 4) & 1) * 8 + l7;
    const int bKb  = ((lane >> 3) & 1) * 16;
    const uint32_t bAddr = sbase + (uint32_t)(18432 + (wn + bRow) * 144 + bKb);

    float acc [2][4][4];
    float accd[2][2][2][4];
    #pragma unroll
    for (int mt = 0; mt < 2; ++mt) {
        #pragma unroll
        for (int nt = 0; nt < 4; ++nt)
            #pragma unroll
            for (int e = 0; e < 4; ++e) acc[mt][nt][e] = 0.f;
        #pragma unroll
        for (int p = 0; p < 2; ++p)
            #pragma unroll
            for (int j = 0; j < 2; ++j)
                #pragma unroll
                for (int e = 0; e < 4; ++e) accd[p][mt][j][e] = 0.f;
    }

    auto compute = [&](int buf, int ph) {
        const uint32_t bufoff = (uint32_t)(buf * K2H_STAGEB);
        #pragma unroll
        for (int ks = 0; ks < 4; ++ks) {
            const uint32_t ko = bufoff + ks * 32;
            uint32_t a[2][4];
            LDSM_X4(a[0], aAddr + ko);
            LDSM_X4(a[1], aAddr + ko + 16 * 144);
            uint32_t bf[6][2];
            #pragma unroll
            for (int p = 0; p < 3; ++p) {
                uint32_t t[4];
                LDSM_X4(t, bAddr + ko + p * 16 * 144);
                bf[2 * p][0]     = t[0];
                bf[2 * p][1]     = t[1];
                bf[2 * p + 1][0] = t[2];
                bf[2 * p + 1][1] = t[3];
            }
            #pragma unroll
            for (int mt = 0; mt < 2; ++mt) {
                #pragma unroll
                for (int nt = 0; nt < 4; ++nt)
                    MMA_F16(acc[mt][nt], a[mt], bf[nt]);
                #pragma unroll
                for (int j = 0; j < 2; ++j) {
                    if (ph == 0) { MMA_F16(accd[0][mt][j], a[mt], bf[4 + j]); }
                    else         { MMA_F16(accd[1][mt][j], a[mt], bf[4 + j]); }
                }
            }
        }
    };

    issue(0);
    issue(1);
    CPA_WAIT(1);
    __syncthreads();

    #pragma unroll 1
    for (int s = 0; s < 8; ++s) {
        compute(s % 3, (s < 4) ? 0 : 1);
        if (s + 2 < 8) { issue(s + 2); CPA_WAIT(1); }
        else           { CPA_WAIT(0); }
        __syncthreads();
    }

    const int colbase = c0 + (wn ? 16 : 0);
    #pragma unroll
    for (int mt = 0; mt < 2; ++mt) {
        const size_t rA = r0 + wm + mt * 16 + g;
        const size_t rB = rA + 8;
        #pragma unroll
        for (int j = 0; j < 2; ++j) {
            const int c = colbase + j * 8 + tg * 2;
            const float br0  = bih[c]       + bhh[c];
            const float br1  = bih[c + 1]   + bhh[c + 1];
            const float bz0  = bih[256 + c] + bhh[256 + c];
            const float bz1  = bih[257 + c] + bhh[257 + c];
            const float bni0 = bih[512 + c],  bni1 = bih[513 + c];
            const float bnh0 = bhh[512 + c],  bnh1 = bhh[513 + c];
            const float2 hpA = __half22float2(*(const __half2*)(hinh + rA * 256 + c));
            const float2 hpB = __half22float2(*(const __half2*)(hinh + rB * 256 + c));

            float rg, zg, ng;
            rg = sigf(acc[mt][j][0] + br0);
            zg = sigf(acc[mt][2 + j][0] + bz0);
            ng = tanhf(accd[0][mt][j][0] + bni0 + rg * (accd[1][mt][j][0] + bnh0));
            float o0 = (1.f - zg) * ng + zg * hpA.x;

            rg = sigf(acc[mt][j][1] + br1);
            zg = sigf(acc[mt][2 + j][1] + bz1);
            ng = tanhf(accd[0][mt][j][1] + bni1 + rg * (accd[1][mt][j][1] + bnh1));
            float o1 = (1.f - zg) * ng + zg * hpA.y;

            rg = sigf(acc[mt][j][2] + br0);
            zg = sigf(acc[mt][2 + j][2] + bz0);
            ng = tanhf(accd[0][mt][j][2] + bni0 + rg * (accd[1][mt][j][2] + bnh0));
            float o2 = (1.f - zg) * ng + zg * hpB.x;

            rg = sigf(acc[mt][j][3] + br1);
            zg = sigf(acc[mt][2 + j][3] + bz1);
            ng = tanhf(accd[0][mt][j][3] + bni1 + rg * (accd[1][mt][j][3] + bnh1));
            float o3 = (1.f - zg) * ng + zg * hpB.y;

            *(float2*)(hh_out + rA * 256 + c) = make_float2(o0, o1);
            *(float2*)(hh_out + rB * 256 + c) = make_float2(o2, o3);
        }
    }
}

// ---------------------------------------------------------------------------
// k3: LayerNorm + fc2 — dual-row warps (proven R13)
// ---------------------------------------------------------------------------
__global__ void __launch_bounds__(256) k3_ln_fc2(
    const float* __restrict__ hh, const float* __restrict__ lng,
    const float* __restrict__ lnb, const float* __restrict__ W2,
    const float* __restrict__ b2, float* __restrict__ q, int nrows)
{
    int warp = (blockIdx.x * blockDim.x + threadIdx.x) >> 5;
    int lane = threadIdx.x & 31;
    size_t rA = (size_t)warp * 2;
    if (rA >= (size_t)nrows) return;
    size_t rB = rA + 1;
    const float* hA = hh + rA * RDIM;
    const float* hB = hh + rB * RDIM;

    float vA[8], vB[8];
    float sA = 0.f, sB = 0.f;
    #pragma unroll
    for (int i = 0; i < 8; ++i) {
        vA[i] = hA[lane + 32 * i]; sA += vA[i];
        vB[i] = hB[lane + 32 * i]; sB += vB[i];
    }
    #pragma unroll
    for (int o = 16; o; o >>= 1) {
        sA += __shfl_xor_sync(0xffffffffu, sA, o);
        sB += __shfl_xor_sync(0xffffffffu, sB, o);
    }
    float muA = sA * (1.f / 256.f), muB = sB * (1.f / 256.f);
    float qA = 0.f, qB = 0.f;
    #pragma unroll
    for (int i = 0; i < 8; ++i) {
        float dA = vA[i] - muA; qA += dA * dA;
        float dB = vB[i] - muB; qB += dB * dB;
    }
    #pragma unroll
    for (int o = 16; o; o >>= 1) {
        qA += __shfl_xor_sync(0xffffffffu, qA, o);
        qB += __shfl_xor_sync(0xffffffffu, qB, o);
    }
    float invA = rsqrtf(qA * (1.f / 256.f) + 1e-5f);
    float invB = rsqrtf(qB * (1.f / 256.f) + 1e-5f);

    float nA[8], nB[8];
    #pragma unroll
    for (int i = 0; i < 8; ++i) {
        float gg = lng[lane + 32 * i], bb = lnb[lane + 32 * i];
        nA[i] = (vA[i] - muA) * invA * gg + bb;
        nB[i] = (vB[i] - muB) * invB * gg + bb;
    }

    #pragma unroll
    for (int j = 0; j < NACT; ++j) {
        float pA = 0.f, pB = 0.f;
        #pragma unroll
        for (int i = 0; i < 8; ++i) {
            float w = W2[j * RDIM + lane + 32 * i];
            pA = fmaf(nA[i], w, pA);
            pB = fmaf(nB[i], w, pB);
        }
        #pragma unroll
        for (int o = 16; o; o >>= 1) {
            pA += __shfl_xor_sync(0xffffffffu, pA, o);
            pB += __shfl_xor_sync(0xffffffffu, pB, o);
        }
        if (lane == j) {
            q[rA * NACT + j] = pA + b2[j];
            q[rB * NACT + j] = pB + b2[j];
        }
    }
}

// ---------------------------------------------------------------------------
extern "C" void kernel_launch(void* const* d_in, const int* in_sizes, int n_in,
                              void* d_out, int out_size)
{
    const float* inputs = (const float*)d_in[0];
    const float* hidden = (const float*)d_in[1];
    const int*   mask   = (const int*)  d_in[2];
    const float* Wfc    = (const float*)d_in[3];
    const float* bfc    = (const float*)d_in[4];
    const float* Wh     = (const float*)d_in[5];
    const float* asrc   = (const float*)d_in[6];
    const float* adst   = (const float*)d_in[7];
    const float* Wo     = (const float*)d_in[8];
    const float* bo     = (const float*)d_in[9];
    const float* W1     = (const float*)d_in[10];
    const float* b1     = (const float*)d_in[11];
    const float* Wih    = (const float*)d_in[12];
    const float* Whh    = (const float*)d_in[13];
    const float* bih    = (const float*)d_in[14];
    const float* bhh    = (const float*)d_in[15];
    const float* lng    = (const float*)d_in[16];
    const float* lnb    = (const float*)d_in[17];
    const float* W2     = (const float*)d_in[18];
    const float* b2     = (const float*)d_in[19];

    const int B = in_sizes[0] / (AN * OBS);       // 4096
    const int nrows = B * AN;                     // 131072
    const int mblk = nrows / 128;                 // 1024

    float* q_out  = (float*)d_out;
    float* hh_out = (float*)d_out + (size_t)nrows * NACT;

    __half *bhh16buf, *inh, *xeh, *aggh, *atth, *xrh, *hinh;
    __half *wfch, *whth, *woth, *w1h, *wih16, *whh16;
    cudaGetSymbolAddress((void**)&bhh16buf, g_bufHh);
    cudaGetSymbolAddress((void**)&inh,   g_inh);
    cudaGetSymbolAddress((void**)&xeh,   g_xeh);
    cudaGetSymbolAddress((void**)&aggh,  g_aggh);
    cudaGetSymbolAddress((void**)&atth,  g_atth);
    cudaGetSymbolAddress((void**)&xrh,   g_xrh);
    cudaGetSymbolAddress((void**)&hinh,  g_hinh);
    cudaGetSymbolAddress((void**)&wfch,  g_Wfch);
    cudaGetSymbolAddress((void**)&whth,  g_WhTh);
    cudaGetSymbolAddress((void**)&woth,  g_WoTh);
    cudaGetSymbolAddress((void**)&w1h,   g_W1h);
    cudaGetSymbolAddress((void**)&wih16, g_Wih16);
    cudaGetSymbolAddress((void**)&whh16, g_Whh16);

    // smem sizes for single-shot GEMMs
    const int G1_SMEM = (128 + 64)  * (128 + 8) * 2;  // 52224 B
    const int G2_SMEM = (128 + 256) * (64 + 8)  * 2;  // 55296 B

    cudaFuncSetAttribute(kB_attn,    cudaFuncAttributeMaxDynamicSharedMemorySize, KB_SMEM);
    cudaFuncSetAttribute(k2_gru_f16, cudaFuncAttributeMaxDynamicSharedMemorySize, K2H_SMEM);
    cudaFuncSetAttribute(gemm_ss<128, 1, 1>, cudaFuncAttributeMaxDynamicSharedMemorySize, G1_SMEM);
    cudaFuncSetAttribute(gemm_ss<64, 4, 0>,  cudaFuncAttributeMaxDynamicSharedMemorySize, G2_SMEM);
    cudaFuncSetAttribute(gemm_hn<256, 0, 1, 1>, cudaFuncAttributeMaxDynamicSharedMemorySize, GH_SMEM);
    cudaFuncSetAttribute(gemm_hn<128, 64, 2, 1>,cudaFuncAttributeMaxDynamicSharedMemorySize, GH_SMEM);

    // merged prologue: all weight conversions + hidden/inputs fp16
    k0_prep<<<2048, 256>>>(Wfc, Wh, Wo, W1, Wih, Whh, hidden, inputs,
                           wfch, whth, woth, w1h, wih16, whh16,
                           (__half2*)hinh, (__half2*)inh,
                           nrows * RDIM / 4, nrows * OBS / 4);

    // G1: XE = inputs @ Wfc^T + bfc          [M,64] fp16 (single-shot)
    gemm_ss<128, 1, 1><<<dim3(1, mblk), 256, G1_SMEM>>>(inh, wfch, bfc, xeh);
    // G2: H = XE @ WhT^T                     [M,256] fp16 (single-shot)
    gemm_ss<64, 4, 0><<<dim3(1, mblk), 256, G2_SMEM>>>(xeh, whth, nullptr, bhh16buf);
    // attention (fp16 H in, fp16 agg out)
    kB_attn<<<B, 256, KB_SMEM>>>(bhh16buf, mask, asrc, adst, aggh);
    // G3: ATT = agg @ WoT^T + bo             [M,64] fp16
    gemm_hn<256, 0, 1, 1><<<dim3(1, mblk), 256, GH_SMEM>>>(aggh, nullptr, woth, bo, atth);
    // G4: XR = relu([inputs|ATT] @ W1^T+b1)  [M,256] fp16
    gemm_hn<128, 64, 2, 1><<<dim3(4, mblk), 256, GH_SMEM>>>(inh, atth, w1h, b1, xrh);
    // GRU (fp16 MMA, BK=64 stages, fp16 hprev)
    k2_gru_f16<<<dim3(8, mblk), 256, K2H_SMEM>>>(xrh, hinh, wih16, whh16,
                                                 bih, bhh, hh_out);
    // LN + fc2 (dual-row warps)
    k3_ln_fc2<<<(nrows / 2 + 7) / 8, 256>>>(hh_out, lng, lnb, W2, b2, q_out, nrows);
}